// round 2
// baseline (speedup 1.0000x reference)
#include <cuda_runtime.h>
#include <math.h>

#define SEQN  4096
#define BATCH 4
#define DIM   1024
#define NH    16
#define DHD   64
#define NL    32
#define WW    8
#define EE    4
#define BAND  16
#define NG    (SEQN / WW)       // 512
#define MROWS (BATCH * SEQN)    // 16384
#define NSPLIT 8
#define CSIZE (BATCH * NH * NL * DHD)  // 131072

// ---------------- device scratch (static globals; no cudaMalloc allowed) ---
__device__ float g_Q  [BATCH * NH * SEQN * DHD];   // (b,h,s,d)
__device__ float g_K  [BATCH * NH * SEQN * DHD];
__device__ float g_V  [BATCH * NH * SEQN * DHD];
__device__ float g_tmp[BATCH * SEQN * DIM];        // raw K/V GEMM output
__device__ float g_D  [BATCH * SEQN * NH * NL];    // raw head scores (b,s,512)
__device__ float g_P  [BATCH * NH * NL * SEQN];    // transposed+softmaxed (b,col,s)
__device__ float g_KcP[NSPLIT * CSIZE];            // split-K partials
__device__ float g_VcP[NSPLIT * CSIZE];
__device__ float g_Kc [CSIZE];                     // (b,h,l,d) LN'd
__device__ float g_Vc [CSIZE];
__device__ float g_C  [BATCH * SEQN * DIM];        // attention output (b,s,DIM)

// ---------------- SGEMM: C = A(16384xK=1024) @ W(1024xN) + bias -----------
// IN_MODE:  0 -> A row r contiguous at r*DIM
//           1 -> A is query (SEQ,B,DIM); row r=(b,s) at (s*B+b)*DIM
// OUT_MODE: 0 -> out[r*N+c]
//           1 -> Q head-split: out[((b*NH+h)*SEQN+s)*DHD+dh], scaled
//           2 -> final out[(s*B+b)*DIM+c]
template <int IN_MODE, int OUT_MODE>
__global__ __launch_bounds__(256) void sgemm_kernel(
    const float* __restrict__ A, const float* __restrict__ Wt,
    const float* __restrict__ bias, float* __restrict__ out,
    int N, float scale)
{
    constexpr int BM = 128, BN = 128, BK = 8;
    __shared__ float As[2][BK][BM];
    __shared__ float Bs[2][BK][BN];

    const int tid = threadIdx.x;
    const int bm = blockIdx.y * BM;
    const int bn = blockIdx.x * BN;

    const int a_row = tid >> 1;
    const int a_col = (tid & 1) << 2;
    size_t a_base;
    {
        int r = bm + a_row;
        if (IN_MODE == 0) {
            a_base = (size_t)r * DIM;
        } else {
            int bb = r >> 12, ss = r & (SEQN - 1);
            a_base = ((size_t)ss * BATCH + bb) * DIM;
        }
    }
    const int b_row = tid >> 5;
    const int b_col = (tid & 31) << 2;
    const size_t b_base = (size_t)b_row * N + bn + b_col;

    float4 aR = *(const float4*)(A + a_base + a_col);
    float4 bR = *(const float4*)(Wt + b_base);
    As[0][a_col + 0][a_row] = aR.x;
    As[0][a_col + 1][a_row] = aR.y;
    As[0][a_col + 2][a_row] = aR.z;
    As[0][a_col + 3][a_row] = aR.w;
    *(float4*)&Bs[0][b_row][b_col] = bR;
    __syncthreads();

    const int tx = tid & 15, ty = tid >> 4;
    float acc[8][8];
#pragma unroll
    for (int i = 0; i < 8; i++)
#pragma unroll
        for (int j = 0; j < 8; j++) acc[i][j] = 0.f;

    int stage = 0;
    constexpr int NIT = DIM / BK;  // 128
#pragma unroll 1
    for (int it = 0; it < NIT; it++) {
        if (it + 1 < NIT) {
            int k0 = (it + 1) * BK;
            aR = *(const float4*)(A + a_base + k0 + a_col);
            bR = *(const float4*)(Wt + (size_t)k0 * N + b_base);
        }
#pragma unroll
        for (int kk = 0; kk < BK; kk++) {
            float af[8], bf[8];
            *(float4*)(af)     = *(float4*)&As[stage][kk][ty * 8];
            *(float4*)(af + 4) = *(float4*)&As[stage][kk][ty * 8 + 4];
            *(float4*)(bf)     = *(float4*)&Bs[stage][kk][tx * 8];
            *(float4*)(bf + 4) = *(float4*)&Bs[stage][kk][tx * 8 + 4];
#pragma unroll
            for (int i = 0; i < 8; i++)
#pragma unroll
                for (int j = 0; j < 8; j++) acc[i][j] += af[i] * bf[j];
        }
        if (it + 1 < NIT) {
            stage ^= 1;
            As[stage][a_col + 0][a_row] = aR.x;
            As[stage][a_col + 1][a_row] = aR.y;
            As[stage][a_col + 2][a_row] = aR.z;
            As[stage][a_col + 3][a_row] = aR.w;
            *(float4*)&Bs[stage][b_row][b_col] = bR;
            __syncthreads();
        }
    }

#pragma unroll
    for (int i = 0; i < 8; i++) {
        int r = bm + ty * 8 + i;
        int bb = r >> 12, ss = r & (SEQN - 1);
#pragma unroll
        for (int j = 0; j < 8; j++) {
            int c = bn + tx * 8 + j;
            float v = (acc[i][j] + bias[c]) * scale;
            if (OUT_MODE == 0) {
                out[(size_t)r * N + c] = v;
            } else if (OUT_MODE == 1) {
                int hh = c >> 6, dd = c & 63;
                out[((size_t)(bb * NH + hh) * SEQN + ss) * DHD + dd] = v;
            } else {
                out[((size_t)ss * BATCH + bb) * DIM + c] = v;
            }
        }
    }
}

// ---------------- LayerNorm over DIM, scatter to head-split layout --------
__global__ __launch_bounds__(256) void ln_split_kernel(
    const float* __restrict__ X, const float* __restrict__ gamma,
    const float* __restrict__ beta, float* __restrict__ out)
{
    __shared__ float shs[8], shq[8];
    int r = blockIdx.x;
    int tid = threadIdx.x;
    const float4 v = ((const float4*)(X + (size_t)r * DIM))[tid];
    float s = v.x + v.y + v.z + v.w;
    float q = v.x * v.x + v.y * v.y + v.z * v.z + v.w * v.w;
    int lane = tid & 31, wid = tid >> 5;
#pragma unroll
    for (int o = 16; o; o >>= 1) {
        s += __shfl_xor_sync(~0u, s, o);
        q += __shfl_xor_sync(~0u, q, o);
    }
    if (lane == 0) { shs[wid] = s; shq[wid] = q; }
    __syncthreads();
    if (tid == 0) {
        float ts = 0, tq = 0;
        for (int i = 0; i < 8; i++) { ts += shs[i]; tq += shq[i]; }
        shs[0] = ts; shq[0] = tq;
    }
    __syncthreads();
    float mean = shs[0] * (1.f / DIM);
    float var  = shq[0] * (1.f / DIM) - mean * mean;
    float rstd = rsqrtf(var + 1e-5f);
    int c = tid * 4;
    float4 g4 = ((const float4*)gamma)[tid];
    float4 b4 = ((const float4*)beta)[tid];
    float4 o;
    o.x = (v.x - mean) * rstd * g4.x + b4.x;
    o.y = (v.y - mean) * rstd * g4.y + b4.y;
    o.z = (v.z - mean) * rstd * g4.z + b4.z;
    o.w = (v.w - mean) * rstd * g4.w + b4.w;
    int b = r >> 12, sq = r & (SEQN - 1);
    int h = c >> 6, dh = c & 63;
    *(float4*)(out + ((size_t)(b * NH + h) * SEQN + sq) * DHD + dh) = o;
}

// ---------------- transpose (b, s, 512) -> (b, 512, s) --------------------
__global__ void transpose_kernel(const float* __restrict__ D, float* __restrict__ P)
{
    __shared__ float t[32][33];
    int b = blockIdx.z;
    int c0 = blockIdx.x * 32, s0 = blockIdx.y * 32;
    int x = threadIdx.x, y = threadIdx.y;  // (32,8)
    const float* Db = D + (size_t)b * SEQN * (NH * NL);
    float* Pb = P + (size_t)b * (NH * NL) * SEQN;
#pragma unroll
    for (int i = 0; i < 32; i += 8)
        t[y + i][x] = Db[(size_t)(s0 + y + i) * (NH * NL) + c0 + x];
    __syncthreads();
#pragma unroll
    for (int i = 0; i < 32; i += 8)
        Pb[(size_t)(c0 + y + i) * SEQN + s0 + x] = t[x][y + i];
}

// ---------------- row softmax over 4096 (sequence axis of head_scores) ----
__global__ __launch_bounds__(256) void softmax_rows_kernel(float* __restrict__ P)
{
    __shared__ float sh[8];
    size_t base = (size_t)blockIdx.x * SEQN;
    int tid = threadIdx.x;
    int lane = tid & 31, wid = tid >> 5;
    float v[16];
    float m = -1e30f;
#pragma unroll
    for (int i = 0; i < 16; i++) {
        v[i] = P[base + tid + i * 256];
        m = fmaxf(m, v[i]);
    }
#pragma unroll
    for (int o = 16; o; o >>= 1) m = fmaxf(m, __shfl_xor_sync(~0u, m, o));
    if (lane == 0) sh[wid] = m;
    __syncthreads();
    if (tid == 0) {
        float t = sh[0];
        for (int i = 1; i < 8; i++) t = fmaxf(t, sh[i]);
        sh[0] = t;
    }
    __syncthreads();
    float M = sh[0];
    __syncthreads();
    float s = 0.f;
#pragma unroll
    for (int i = 0; i < 16; i++) { v[i] = __expf(v[i] - M); s += v[i]; }
#pragma unroll
    for (int o = 16; o; o >>= 1) s += __shfl_xor_sync(~0u, s, o);
    if (lane == 0) sh[wid] = s;
    __syncthreads();
    if (tid == 0) {
        float t = 0;
        for (int i = 0; i < 8; i++) t += sh[i];
        sh[0] = t;
    }
    __syncthreads();
    float inv = 1.f / sh[0];
#pragma unroll
    for (int i = 0; i < 16; i++) P[base + tid + i * 256] = v[i] * inv;
}

// ---------------- Kc/Vc = hs @ K / hs @ V  (split-K over s, partials) -----
__global__ __launch_bounds__(256) void compress_partial_kernel(
    const float* __restrict__ P, const float* __restrict__ K,
    const float* __restrict__ V, float* __restrict__ partK,
    float* __restrict__ partV)
{
    __shared__ float Ps[NL][33];
    __shared__ float Ks[32][DHD];
    __shared__ float Vs[32][DHD];
    int bh = blockIdx.x, sp = blockIdx.y;
    int b = bh >> 4, h = bh & 15;
    int tid = threadIdx.x;
    int l = tid >> 3, qd = (tid & 7) * 8;
    float accK[8] = {0, 0, 0, 0, 0, 0, 0, 0};
    float accV[8] = {0, 0, 0, 0, 0, 0, 0, 0};
    const float* Pb = P + (size_t)(b * (NH * NL) + h * NL) * SEQN;
    const float* Kb = K + (size_t)bh * SEQN * DHD;
    const float* Vb = V + (size_t)bh * SEQN * DHD;
    const int schunk = SEQN / NSPLIT;  // 512
    for (int sc = 0; sc < schunk; sc += 32) {
        int s0 = sp * schunk + sc;
        {
            int pl = tid >> 3, ps = (tid & 7) * 4;
            float4 p4 = *(const float4*)(Pb + (size_t)pl * SEQN + s0 + ps);
            Ps[pl][ps] = p4.x; Ps[pl][ps + 1] = p4.y;
            Ps[pl][ps + 2] = p4.z; Ps[pl][ps + 3] = p4.w;
        }
        {
            int ks = tid >> 3, kd = (tid & 7) * 8;
            const float* kp = Kb + (size_t)(s0 + ks) * DHD + kd;
            *(float4*)&Ks[ks][kd]     = *(const float4*)kp;
            *(float4*)&Ks[ks][kd + 4] = *(const float4*)(kp + 4);
            const float* vp = Vb + (size_t)(s0 + ks) * DHD + kd;
            *(float4*)&Vs[ks][kd]     = *(const float4*)vp;
            *(float4*)&Vs[ks][kd + 4] = *(const float4*)(vp + 4);
        }
        __syncthreads();
#pragma unroll 8
        for (int si = 0; si < 32; si++) {
            float p = Ps[l][si];
            float kf[8], vf[8];
            *(float4*)kf       = *(float4*)&Ks[si][qd];
            *(float4*)(kf + 4) = *(float4*)&Ks[si][qd + 4];
            *(float4*)vf       = *(float4*)&Vs[si][qd];
            *(float4*)(vf + 4) = *(float4*)&Vs[si][qd + 4];
#pragma unroll
            for (int j = 0; j < 8; j++) {
                accK[j] += p * kf[j];
                accV[j] += p * vf[j];
            }
        }
        __syncthreads();
    }
    size_t ob = (size_t)sp * CSIZE + ((size_t)bh * NL + l) * DHD + qd;
    *(float4*)(partK + ob)     = make_float4(accK[0], accK[1], accK[2], accK[3]);
    *(float4*)(partK + ob + 4) = make_float4(accK[4], accK[5], accK[6], accK[7]);
    *(float4*)(partV + ob)     = make_float4(accV[0], accV[1], accV[2], accV[3]);
    *(float4*)(partV + ob + 4) = make_float4(accV[4], accV[5], accV[6], accV[7]);
}

// ---------------- reduce partials + LayerNorm over DIM for Kc/Vc ----------
__global__ __launch_bounds__(256) void compress_ln_kernel(
    const float* __restrict__ partK, const float* __restrict__ partV,
    const float* __restrict__ gamma, const float* __restrict__ beta,
    float* __restrict__ outK, float* __restrict__ outV)
{
    __shared__ float shs[8], shq[8];
    int bl = blockIdx.x;
    int b = bl >> 5, l = bl & 31;
    const float* part = blockIdx.y ? partV : partK;
    float* out = blockIdx.y ? outV : outK;
    int tid = threadIdx.x;
    int c = tid * 4;
    int h = c >> 6, dh = c & 63;
    size_t base = ((size_t)(b * NH + h) * NL + l) * DHD + dh;
    float4 acc = make_float4(0, 0, 0, 0);
#pragma unroll
    for (int sp = 0; sp < NSPLIT; sp++) {
        float4 p = *(const float4*)(part + (size_t)sp * CSIZE + base);
        acc.x += p.x; acc.y += p.y; acc.z += p.z; acc.w += p.w;
    }
    float s = acc.x + acc.y + acc.z + acc.w;
    float q = acc.x * acc.x + acc.y * acc.y + acc.z * acc.z + acc.w * acc.w;
    int lane = tid & 31, wid = tid >> 5;
#pragma unroll
    for (int o = 16; o; o >>= 1) {
        s += __shfl_xor_sync(~0u, s, o);
        q += __shfl_xor_sync(~0u, q, o);
    }
    if (lane == 0) { shs[wid] = s; shq[wid] = q; }
    __syncthreads();
    if (tid == 0) {
        float ts = 0, tq = 0;
        for (int i = 0; i < 8; i++) { ts += shs[i]; tq += shq[i]; }
        shs[0] = ts; shq[0] = tq;
    }
    __syncthreads();
    float mean = shs[0] * (1.f / DIM);
    float var  = shq[0] * (1.f / DIM) - mean * mean;
    float rstd = rsqrtf(var + 1e-5f);
    float4 g4 = ((const float4*)gamma)[tid];
    float4 b4 = ((const float4*)beta)[tid];
    float4 o;
    o.x = (acc.x - mean) * rstd * g4.x + b4.x;
    o.y = (acc.y - mean) * rstd * g4.y + b4.y;
    o.z = (acc.z - mean) * rstd * g4.z + b4.z;
    o.w = (acc.w - mean) * rstd * g4.w + b4.w;
    *(float4*)(out + base) = o;
}

// ---------------- fused attention: compressed(32) + window(16) ------------
__global__ __launch_bounds__(256) void attn_kernel(
    const float* __restrict__ Q, const float* __restrict__ K,
    const float* __restrict__ V, const float* __restrict__ Kc,
    const float* __restrict__ Vc, float* __restrict__ C)
{
    __shared__ float Kcs[NL][DHD + 1];
    __shared__ float Vcs[NL][DHD + 1];
    __shared__ float Kws[BAND][DHD + 1];
    __shared__ float Vws[BAND][DHD + 1];
    __shared__ float Qs[WW][DHD + 1];
    __shared__ float probs[WW][NL + BAND];

    int g = blockIdx.x, h = blockIdx.y, b = blockIdx.z;
    int bh = b * NH + h;
    int tid = threadIdx.x;

    {   // Kc/Vc tiles: 32x64 each
        int l = tid >> 3, d0 = (tid & 7) * 8;
        size_t src = ((size_t)bh * NL + l) * DHD + d0;
        float tk[8], tv[8];
        *(float4*)tk       = *(const float4*)(Kc + src);
        *(float4*)(tk + 4) = *(const float4*)(Kc + src + 4);
        *(float4*)tv       = *(const float4*)(Vc + src);
        *(float4*)(tv + 4) = *(const float4*)(Vc + src + 4);
#pragma unroll
        for (int i = 0; i < 8; i++) { Kcs[l][d0 + i] = tk[i]; Vcs[l][d0 + i] = tv[i]; }
    }
    {   // window K/V tiles: 16x64, zero-filled when out of range
        int k = tid >> 4, d = (tid & 15) * 4;
        int sk = g * WW - EE + k;
        float4 kv = make_float4(0, 0, 0, 0), vv = make_float4(0, 0, 0, 0);
        if (sk >= 0 && sk < SEQN) {
            size_t src = ((size_t)bh * SEQN + sk) * DHD + d;
            kv = *(const float4*)(K + src);
            vv = *(const float4*)(V + src);
        }
        Kws[k][d] = kv.x; Kws[k][d + 1] = kv.y; Kws[k][d + 2] = kv.z; Kws[k][d + 3] = kv.w;
        Vws[k][d] = vv.x; Vws[k][d + 1] = vv.y; Vws[k][d + 2] = vv.z; Vws[k][d + 3] = vv.w;
    }
    if (tid < 128) {  // Q tile: 8x64
        int w = tid >> 4, d = (tid & 15) * 4;
        float4 qv = *(const float4*)(Q + ((size_t)bh * SEQN + g * WW + w) * DHD + d);
        Qs[w][d] = qv.x; Qs[w][d + 1] = qv.y; Qs[w][d + 2] = qv.z; Qs[w][d + 3] = qv.w;
    }
    __syncthreads();

    int warp = tid >> 5, lane = tid & 31;
    float sc = 0.f, sw = 0.f;
    int k = lane & 15;
#pragma unroll
    for (int d = 0; d < DHD; d++) {
        float qd = Qs[warp][d];
        sc += qd * Kcs[lane][d];
        sw += qd * Kws[k][d];
    }
    int sk = g * WW - EE + k;
    bool kvalid = (lane < BAND) && (sk >= 0) && (sk < SEQN);
    float m = fmaxf(sc, kvalid ? sw : -1e30f);
#pragma unroll
    for (int o = 16; o; o >>= 1) m = fmaxf(m, __shfl_xor_sync(~0u, m, o));
    float e0 = __expf(sc - m);
    float e1 = kvalid ? __expf(sw - m) : 0.f;
    float t = e0 + e1;
#pragma unroll
    for (int o = 16; o; o >>= 1) t += __shfl_xor_sync(~0u, t, o);
    float inv = 1.f / t;
    probs[warp][lane] = e0 * inv;
    if (lane < BAND) probs[warp][NL + lane] = e1 * inv;
    __syncwarp();

    float a0 = 0.f, a1 = 0.f;
#pragma unroll
    for (int j = 0; j < NL; j++) {
        float p = probs[warp][j];
        a0 += p * Vcs[j][lane];
        a1 += p * Vcs[j][lane + 32];
    }
#pragma unroll
    for (int kk = 0; kk < BAND; kk++) {
        float p = probs[warp][NL + kk];
        a0 += p * Vws[kk][lane];
        a1 += p * Vws[kk][lane + 32];
    }
    int s = g * WW + warp;
    size_t off = ((size_t)(b * SEQN) + s) * DIM + h * DHD;
    C[off + lane] = a0;
    C[off + 32 + lane] = a1;
}

// ---------------------------------------------------------------------------
extern "C" void kernel_launch(void* const* d_in, const int* in_sizes, int n_in,
                              void* d_out, int out_size)
{
    (void)in_sizes; (void)n_in; (void)out_size;
    const float* query = (const float*)d_in[0];
    const float* Wq = (const float*)d_in[1];
    const float* bq = (const float*)d_in[2];
    const float* Wk = (const float*)d_in[3];
    const float* bk = (const float*)d_in[4];
    const float* Wv = (const float*)d_in[5];
    const float* bv = (const float*)d_in[6];
    const float* Wo = (const float*)d_in[7];
    const float* bo = (const float*)d_in[8];
    const float* gl = (const float*)d_in[9];
    const float* bl = (const float*)d_in[10];
    const float* gs = (const float*)d_in[11];
    const float* bs = (const float*)d_in[12];
    const float* Wd = (const float*)d_in[13];
    const float* bd = (const float*)d_in[14];
    float* out = (float*)d_out;

    float *pQ, *pK, *pV, *pTmp, *pD, *pP, *pKcP, *pVcP, *pKc, *pVc, *pC;
    cudaGetSymbolAddress((void**)&pQ, g_Q);
    cudaGetSymbolAddress((void**)&pK, g_K);
    cudaGetSymbolAddress((void**)&pV, g_V);
    cudaGetSymbolAddress((void**)&pTmp, g_tmp);
    cudaGetSymbolAddress((void**)&pD, g_D);
    cudaGetSymbolAddress((void**)&pP, g_P);
    cudaGetSymbolAddress((void**)&pKcP, g_KcP);
    cudaGetSymbolAddress((void**)&pVcP, g_VcP);
    cudaGetSymbolAddress((void**)&pKc, g_Kc);
    cudaGetSymbolAddress((void**)&pVc, g_Vc);
    cudaGetSymbolAddress((void**)&pC, g_C);

    dim3 gQKV(DIM / 128, MROWS / 128);       // 8 x 128
    dim3 gD((NH * NL) / 128, MROWS / 128);   // 4 x 128

    // Q = split(X@Wq + bq) / 8
    sgemm_kernel<1, 1><<<gQKV, 256>>>(query, Wq, bq, pQ, DIM, 0.125f);
    // K = split(LN(X@Wk + bk))
    sgemm_kernel<1, 0><<<gQKV, 256>>>(query, Wk, bk, pTmp, DIM, 1.f);
    ln_split_kernel<<<MROWS, 256>>>(pTmp, gl, bl, pK);
    // V = split(LN(X@Wv + bv))
    sgemm_kernel<1, 0><<<gQKV, 256>>>(query, Wv, bv, pTmp, DIM, 1.f);
    ln_split_kernel<<<MROWS, 256>>>(pTmp, gl, bl, pV);
    // head scores D = X@Wd + bd, then softmax over sequence axis
    sgemm_kernel<1, 0><<<gD, 256>>>(query, Wd, bd, pD, NH * NL, 1.f);
    transpose_kernel<<<dim3((NH * NL) / 32, SEQN / 32, BATCH), dim3(32, 8)>>>(pD, pP);
    softmax_rows_kernel<<<BATCH * NH * NL, 256>>>(pP);
    // Kc/Vc = hs @ K / hs @ V (split-K), then LN over DIM
    compress_partial_kernel<<<dim3(BATCH * NH, NSPLIT), 256>>>(pP, pK, pV, pKcP, pVcP);
    compress_ln_kernel<<<dim3(BATCH * NL, 2), 256>>>(pKcP, pVcP, gs, bs, pKc, pVc);
    // fused compressed+window attention -> C (b,s,DIM)
    attn_kernel<<<dim3(NG, NH, BATCH), 256>>>(pQ, pK, pV, pKc, pVc, pC);
    // out = C @ Wo + bo, permuted to (s,b,DIM)
    sgemm_kernel<0, 2><<<gQKV, 256>>>(pC, Wo, bo, out, DIM, 1.f);
}

// round 5
// speedup vs baseline: 2.2029x; 2.2029x over previous
#include <cuda_runtime.h>
#include <cuda_fp16.h>
#include <math.h>
#include <stdint.h>

#define SEQN  4096
#define BATCH 4
#define DIM   1024
#define NH    16
#define DHD   64
#define NL    32
#define WW    8
#define EE    4
#define BAND  16
#define NG    (SEQN / WW)
#define MROWS (BATCH * SEQN)
#define NSPLIT 8
#define CSIZE (BATCH * NH * NL * DHD)

__device__ float g_Q  [BATCH * NH * SEQN * DHD];
__device__ float g_K  [BATCH * NH * SEQN * DHD];
__device__ float g_V  [BATCH * NH * SEQN * DHD];
__device__ float g_tmp[BATCH * SEQN * DIM];
__device__ float g_D  [BATCH * SEQN * NH * NL];
__device__ float g_P  [BATCH * NH * NL * SEQN];
__device__ float g_KcP[NSPLIT * CSIZE];
__device__ float g_VcP[NSPLIT * CSIZE];
__device__ float g_Kc [CSIZE];
__device__ float g_Vc [CSIZE];
__device__ float g_C  [BATCH * SEQN * DIM];

__device__ __align__(16) __half g_Xh[MROWS * DIM];
__device__ __align__(16) __half g_Xl[MROWS * DIM];
__device__ __align__(16) __half g_Ch[MROWS * DIM];
__device__ __align__(16) __half g_Cl[MROWS * DIM];
#define WOFF_Q 0
#define WOFF_K (1 * DIM * DIM)
#define WOFF_V (2 * DIM * DIM)
#define WOFF_O (3 * DIM * DIM)
#define WOFF_D (4 * DIM * DIM)
#define WT_TOTAL (4 * DIM * DIM + (NH * NL) * DIM)
__device__ __align__(16) __half g_Wth[WT_TOTAL];
__device__ __align__(16) __half g_Wtl[WT_TOTAL];

// =========================== HMMA GEMM =====================================
// out[M=16384, N] = A @ Bt^T, A hi/lo [m][k] stride DIM, Bt hi/lo [n][k].
// fp16 error split: acc = Ah*Bh + Ah*Bl + Al*Bh (fp32 accum).
#define SROWB 80                 // 64B data + 16B pad per 32-half row
#define TILEB (128 * SROWB)      // 10240 B
#define STAGEB (4 * TILEB)       // AH, AL, BH, BL
#define SM_AH(s) ((s) * STAGEB + 0)
#define SM_AL(s) ((s) * STAGEB + TILEB)
#define SM_BH(s) ((s) * STAGEB + 2 * TILEB)
#define SM_BL(s) ((s) * STAGEB + 3 * TILEB)
#define GEMM_SMEM (2 * STAGEB)   // 81920 B
#define NIT (DIM / 32)           // 32 k-chunks of 32 halves

__device__ __forceinline__ uint32_t smem_u32(const void* p) {
    uint32_t a;
    asm("{ .reg .u64 t; cvta.to.shared.u64 t, %1; cvt.u32.u64 %0, t; }" : "=r"(a) : "l"(p));
    return a;
}
#define CPA(dst, src) \
    asm volatile("cp.async.cg.shared.global [%0], [%1], 16;" :: "r"(dst), "l"(src))
#define CP_COMMIT() asm volatile("cp.async.commit_group;")
#define CP_WAIT(n)  asm volatile("cp.async.wait_group %0;" :: "n"(n))
#define LDSM4(R, addr) \
    asm volatile("ldmatrix.sync.aligned.m8n8.x4.shared.b16 {%0,%1,%2,%3}, [%4];" \
        : "=r"((R)[0]), "=r"((R)[1]), "=r"((R)[2]), "=r"((R)[3]) : "r"(addr))
#define MMA16816(d, a, b0, b1) \
    asm volatile("mma.sync.aligned.m16n8k16.row.col.f32.f16.f16.f32 " \
        "{%0,%1,%2,%3}, {%4,%5,%6,%7}, {%8,%9}, {%0,%1,%2,%3};" \
        : "+f"((d)[0]), "+f"((d)[1]), "+f"((d)[2]), "+f"((d)[3]) \
        : "r"((a)[0]), "r"((a)[1]), "r"((a)[2]), "r"((a)[3]), "r"(b0), "r"(b1))

// OUT_MODE: 0 row-major[r*N+c]; 1 Q head-split scaled; 2 (s,b,DIM)
template <int OUT_MODE>
__global__ __launch_bounds__(256, 2) void hgemm(
    const __half* __restrict__ Ah, const __half* __restrict__ Al,
    const __half* __restrict__ Bh, const __half* __restrict__ Bl,
    const float* __restrict__ bias, float* __restrict__ out, int N, float scale)
{
    extern __shared__ __align__(16) char smem[];
    const uint32_t sb = smem_u32(smem);
    const int tid = threadIdx.x, wid = tid >> 5, lane = tid & 31;
    const int bn = blockIdx.x * 128, bm = blockIdx.y * 128;
    const int wm = wid & 3, wn = wid >> 2;

    // --- async loader mapping: 2 rows x 16B per tile per thread ---
    const int lr0 = tid >> 2;
    const size_t aoff0 = ((size_t)(bm + lr0) << 10) + (size_t)(tid & 3) * 8;
    const size_t aoff1 = aoff0 + ((size_t)64 << 10);
    const size_t boff0 = ((size_t)(bn + lr0) << 10) + (size_t)(tid & 3) * 8;
    const size_t boff1 = boff0 + ((size_t)64 << 10);
    const uint32_t d0 = (uint32_t)lr0 * SROWB + (tid & 3) * 16;
    const uint32_t d1 = d0 + 64 * SROWB;

    // prologue: stage 0 (k chunk 0)
    CPA(sb + SM_AH(0) + d0, Ah + aoff0); CPA(sb + SM_AH(0) + d1, Ah + aoff1);
    CPA(sb + SM_AL(0) + d0, Al + aoff0); CPA(sb + SM_AL(0) + d1, Al + aoff1);
    CPA(sb + SM_BH(0) + d0, Bh + boff0); CPA(sb + SM_BH(0) + d1, Bh + boff1);
    CPA(sb + SM_BL(0) + d0, Bl + boff0); CPA(sb + SM_BL(0) + d1, Bl + boff1);
    CP_COMMIT();

    float acc[2][8][4];
#pragma unroll
    for (int i = 0; i < 2; i++)
#pragma unroll
        for (int j = 0; j < 8; j++)
#pragma unroll
            for (int k = 0; k < 4; k++) acc[i][j][k] = 0.f;

    // per-warp ldmatrix base offsets (within a tile)
    const uint32_t aBase = (uint32_t)(wm * 32 + (lane & 15)) * SROWB + (lane >> 4) * 16;
    const uint32_t bBase = (uint32_t)(wn * 64 + ((lane >> 4) & 1) * 8 + (lane & 7)) * SROWB
                           + ((lane >> 3) & 1) * 16;

    for (int it = 0; it < NIT; it++) {
        const int p = it & 1;
        if (it + 1 < NIT) {
            const int np = p ^ 1;
            const int kb = (it + 1) * 32;
            CPA(sb + SM_AH(np) + d0, Ah + aoff0 + kb); CPA(sb + SM_AH(np) + d1, Ah + aoff1 + kb);
            CPA(sb + SM_AL(np) + d0, Al + aoff0 + kb); CPA(sb + SM_AL(np) + d1, Al + aoff1 + kb);
            CPA(sb + SM_BH(np) + d0, Bh + boff0 + kb); CPA(sb + SM_BH(np) + d1, Bh + boff1 + kb);
            CPA(sb + SM_BL(np) + d0, Bl + boff0 + kb); CPA(sb + SM_BL(np) + d1, Bl + boff1 + kb);
            CP_COMMIT();
            CP_WAIT(1);
        } else {
            CP_WAIT(0);
        }
        __syncthreads();

        const uint32_t sAH = sb + SM_AH(p) + aBase, sAL = sb + SM_AL(p) + aBase;
        const uint32_t sBH = sb + SM_BH(p) + bBase, sBL = sb + SM_BL(p) + bBase;
#pragma unroll
        for (int ks = 0; ks < 2; ks++) {
            const uint32_t ko = ks * 32;
            uint32_t ah[2][4], al[2][4];
            LDSM4(ah[0], sAH + ko);
            LDSM4(ah[1], sAH + ko + 16 * SROWB);
            LDSM4(al[0], sAL + ko);
            LDSM4(al[1], sAL + ko + 16 * SROWB);
#pragma unroll
            for (int q = 0; q < 4; q++) {
                uint32_t bh[4], bl[4];
                LDSM4(bh, sBH + ko + q * 16 * SROWB);
                LDSM4(bl, sBL + ko + q * 16 * SROWB);
#pragma unroll
                for (int mt = 0; mt < 2; mt++) {
                    MMA16816(acc[mt][2 * q + 0], ah[mt], bh[0], bh[1]);
                    MMA16816(acc[mt][2 * q + 0], ah[mt], bl[0], bl[1]);
                    MMA16816(acc[mt][2 * q + 0], al[mt], bh[0], bh[1]);
                    MMA16816(acc[mt][2 * q + 1], ah[mt], bh[2], bh[3]);
                    MMA16816(acc[mt][2 * q + 1], ah[mt], bl[2], bl[3]);
                    MMA16816(acc[mt][2 * q + 1], al[mt], bh[2], bh[3]);
                }
            }
        }
        __syncthreads();
    }

    // --- epilogue: bias + scale + layout fuse ---
    const int r0 = bm + wm * 32 + (lane >> 2);
    const int c0 = bn + wn * 64 + (lane & 3) * 2;
#pragma unroll
    for (int mt = 0; mt < 2; mt++) {
#pragma unroll
        for (int hf = 0; hf < 2; hf++) {
            const int r = r0 + mt * 16 + hf * 8;
            const int bb = r >> 12, ss = r & (SEQN - 1);
#pragma unroll
            for (int nt = 0; nt < 8; nt++) {
                const int col = c0 + nt * 8;
                const float2 bv = *(const float2*)(bias + col);
                float vx = (acc[mt][nt][hf * 2 + 0] + bv.x) * scale;
                float vy = (acc[mt][nt][hf * 2 + 1] + bv.y) * scale;
                size_t o;
                if (OUT_MODE == 0) o = (size_t)r * N + col;
                else if (OUT_MODE == 1)
                    o = ((size_t)(bb * NH + (col >> 6)) * SEQN + ss) * DHD + (col & 63);
                else o = ((size_t)ss * BATCH + bb) * DIM + col;
                *(float2*)(out + o) = make_float2(vx, vy);
            }
        }
    }
}

// ---- fp32 -> fp16 hi/lo split (PERM=1: (s,b)->(b,s)) ----
template <int PERM>
__global__ __launch_bounds__(256) void split_kernel(
    const float* __restrict__ X, __half* __restrict__ H, __half* __restrict__ L)
{
    int i = blockIdx.x * 256 + threadIdx.x;
    float4 v;
    if (PERM) {
        int r = i >> 8, k4 = i & 255;
        int b = r >> 12, s = r & (SEQN - 1);
        v = *((const float4*)X + ((size_t)s * BATCH + b) * 256 + k4);
    } else v = ((const float4*)X)[i];
    __half h0 = __float2half_rn(v.x), h1 = __float2half_rn(v.y);
    __half h2 = __float2half_rn(v.z), h3 = __float2half_rn(v.w);
    __half2* Hp = (__half2*)(H + (size_t)i * 4);
    __half2* Lp = (__half2*)(L + (size_t)i * 4);
    Hp[0] = __halves2half2(h0, h1); Hp[1] = __halves2half2(h2, h3);
    Lp[0] = __halves2half2(__float2half_rn(v.x - __half2float(h0)),
                           __float2half_rn(v.y - __half2float(h1)));
    Lp[1] = __halves2half2(__float2half_rn(v.z - __half2float(h2)),
                           __float2half_rn(v.w - __half2float(h3)));
}

// ---- weight transpose + split: Th[n][k] = fp16(W[k][n]) ----
__global__ void wsplit_kernel(const float* __restrict__ W,
                              __half* __restrict__ Th, __half* __restrict__ Tl, int N)
{
    __shared__ float t[32][33];
    int n0 = blockIdx.x * 32, k0 = blockIdx.y * 32;
    int x = threadIdx.x, y = threadIdx.y;
#pragma unroll
    for (int i = 0; i < 32; i += 8)
        t[y + i][x] = W[(size_t)(k0 + y + i) * N + n0 + x];
    __syncthreads();
#pragma unroll
    for (int i = 0; i < 32; i += 8) {
        float v = t[x][y + i];
        __half h = __float2half_rn(v);
        size_t o = (size_t)(n0 + y + i) * DIM + k0 + x;
        Th[o] = h;
        Tl[o] = __float2half_rn(v - __half2float(h));
    }
}

// ---- LayerNorm over DIM, scatter head-split ----
__global__ __launch_bounds__(256) void ln_split_kernel(
    const float* __restrict__ X, const float* __restrict__ gamma,
    const float* __restrict__ beta, float* __restrict__ out)
{
    __shared__ float shs[8], shq[8];
    int r = blockIdx.x, tid = threadIdx.x;
    const float4 v = ((const float4*)(X + (size_t)r * DIM))[tid];
    float s = v.x + v.y + v.z + v.w;
    float q = v.x*v.x + v.y*v.y + v.z*v.z + v.w*v.w;
    int lane = tid & 31, wid = tid >> 5;
#pragma unroll
    for (int o = 16; o; o >>= 1) {
        s += __shfl_xor_sync(~0u, s, o); q += __shfl_xor_sync(~0u, q, o);
    }
    if (lane == 0) { shs[wid] = s; shq[wid] = q; }
    __syncthreads();
    if (tid == 0) {
        float ts = 0, tq = 0;
        for (int i = 0; i < 8; i++) { ts += shs[i]; tq += shq[i]; }
        shs[0] = ts; shq[0] = tq;
    }
    __syncthreads();
    float mean = shs[0] * (1.f / DIM);
    float rstd = rsqrtf(shq[0] * (1.f / DIM) - mean * mean + 1e-5f);
    int c = tid * 4;
    float4 g4 = ((const float4*)gamma)[tid], b4 = ((const float4*)beta)[tid];
    float4 o;
    o.x = (v.x - mean) * rstd * g4.x + b4.x;
    o.y = (v.y - mean) * rstd * g4.y + b4.y;
    o.z = (v.z - mean) * rstd * g4.z + b4.z;
    o.w = (v.w - mean) * rstd * g4.w + b4.w;
    int b = r >> 12, sq = r & (SEQN - 1);
    *(float4*)(out + ((size_t)(b * NH + (c >> 6)) * SEQN + sq) * DHD + (c & 63)) = o;
}

// ---- transpose (b,s,512) -> (b,512,s) ----
__global__ void transpose_kernel(const float* __restrict__ D, float* __restrict__ P)
{
    __shared__ float t[32][33];
    int b = blockIdx.z, c0 = blockIdx.x * 32, s0 = blockIdx.y * 32;
    int x = threadIdx.x, y = threadIdx.y;
    const float* Db = D + (size_t)b * SEQN * (NH * NL);
    float* Pb = P + (size_t)b * (NH * NL) * SEQN;
#pragma unroll
    for (int i = 0; i < 32; i += 8)
        t[y + i][x] = Db[(size_t)(s0 + y + i) * (NH * NL) + c0 + x];
    __syncthreads();
#pragma unroll
    for (int i = 0; i < 32; i += 8)
        Pb[(size_t)(c0 + y + i) * SEQN + s0 + x] = t[x][y + i];
}

// ---- row softmax over 4096 ----
__global__ __launch_bounds__(256) void softmax_rows_kernel(float* __restrict__ P)
{
    __shared__ float sh[8];
    size_t base = (size_t)blockIdx.x * SEQN;
    int tid = threadIdx.x, lane = tid & 31, wid = tid >> 5;
    float v[16], m = -1e30f;
#pragma unroll
    for (int i = 0; i < 16; i++) { v[i] = P[base + tid + i * 256]; m = fmaxf(m, v[i]); }
#pragma unroll
    for (int o = 16; o; o >>= 1) m = fmaxf(m, __shfl_xor_sync(~0u, m, o));
    if (lane == 0) sh[wid] = m;
    __syncthreads();
    if (tid == 0) { float t = sh[0]; for (int i = 1; i < 8; i++) t = fmaxf(t, sh[i]); sh[0] = t; }
    __syncthreads();
    float M = sh[0];
    __syncthreads();
    float s = 0.f;
#pragma unroll
    for (int i = 0; i < 16; i++) { v[i] = __expf(v[i] - M); s += v[i]; }
#pragma unroll
    for (int o = 16; o; o >>= 1) s += __shfl_xor_sync(~0u, s, o);
    if (lane == 0) sh[wid] = s;
    __syncthreads();
    if (tid == 0) { float t = 0; for (int i = 0; i < 8; i++) t += sh[i]; sh[0] = t; }
    __syncthreads();
    float inv = 1.f / sh[0];
#pragma unroll
    for (int i = 0; i < 16; i++) P[base + tid + i * 256] = v[i] * inv;
}

// ---- Kc/Vc partials (split-K over s) ----
__global__ __launch_bounds__(256) void compress_partial_kernel(
    const float* __restrict__ P, const float* __restrict__ K,
    const float* __restrict__ V, float* __restrict__ partK, float* __restrict__ partV)
{
    __shared__ float Ps[NL][33];
    __shared__ float Ks[32][DHD];
    __shared__ float Vs[32][DHD];
    int bh = blockIdx.x, sp = blockIdx.y;
    int b = bh >> 4, h = bh & 15;
    int tid = threadIdx.x;
    int l = tid >> 3, qd = (tid & 7) * 8;
    float accK[8] = {}, accV[8] = {};
    const float* Pb = P + (size_t)(b * (NH * NL) + h * NL) * SEQN;
    const float* Kb = K + (size_t)bh * SEQN * DHD;
    const float* Vb = V + (size_t)bh * SEQN * DHD;
    for (int sc = 0; sc < SEQN / NSPLIT; sc += 32) {
        int s0 = sp * (SEQN / NSPLIT) + sc;
        {
            int pl = tid >> 3, ps = (tid & 7) * 4;
            float4 p4 = *(const float4*)(Pb + (size_t)pl * SEQN + s0 + ps);
            Ps[pl][ps] = p4.x; Ps[pl][ps+1] = p4.y; Ps[pl][ps+2] = p4.z; Ps[pl][ps+3] = p4.w;
        }
        {
            int ks = tid >> 3, kd = (tid & 7) * 8;
            const float* kp = Kb + (size_t)(s0 + ks) * DHD + kd;
            *(float4*)&Ks[ks][kd] = *(const float4*)kp;
            *(float4*)&Ks[ks][kd+4] = *(const float4*)(kp + 4);
            const float* vp = Vb + (size_t)(s0 + ks) * DHD + kd;
            *(float4*)&Vs[ks][kd] = *(const float4*)vp;
            *(float4*)&Vs[ks][kd+4] = *(const float4*)(vp + 4);
        }
        __syncthreads();
#pragma unroll 8
        for (int si = 0; si < 32; si++) {
            float p = Ps[l][si];
            float kf[8], vf[8];
            *(float4*)kf = *(float4*)&Ks[si][qd]; *(float4*)(kf+4) = *(float4*)&Ks[si][qd+4];
            *(float4*)vf = *(float4*)&Vs[si][qd]; *(float4*)(vf+4) = *(float4*)&Vs[si][qd+4];
#pragma unroll
            for (int j = 0; j < 8; j++) { accK[j] += p * kf[j]; accV[j] += p * vf[j]; }
        }
        __syncthreads();
    }
    size_t ob = (size_t)sp * CSIZE + ((size_t)bh * NL + l) * DHD + qd;
    *(float4*)(partK + ob)   = make_float4(accK[0], accK[1], accK[2], accK[3]);
    *(float4*)(partK + ob+4) = make_float4(accK[4], accK[5], accK[6], accK[7]);
    *(float4*)(partV + ob)   = make_float4(accV[0], accV[1], accV[2], accV[3]);
    *(float4*)(partV + ob+4) = make_float4(accV[4], accV[5], accV[6], accV[7]);
}

// ---- reduce partials + LN for Kc/Vc ----
__global__ __launch_bounds__(256) void compress_ln_kernel(
    const float* __restrict__ partK, const float* __restrict__ partV,
    const float* __restrict__ gamma, const float* __restrict__ beta,
    float* __restrict__ outK, float* __restrict__ outV)
{
    __shared__ float shs[8], shq[8];
    int bl = blockIdx.x, b = bl >> 5, l = bl & 31;
    const float* part = blockIdx.y ? partV : partK;
    float* out = blockIdx.y ? outV : outK;
    int tid = threadIdx.x, c = tid * 4;
    size_t base = ((size_t)(b * NH + (c >> 6)) * NL + l) * DHD + (c & 63);
    float4 acc = make_float4(0, 0, 0, 0);
#pragma unroll
    for (int sp = 0; sp < NSPLIT; sp++) {
        float4 p = *(const float4*)(part + (size_t)sp * CSIZE + base);
        acc.x += p.x; acc.y += p.y; acc.z += p.z; acc.w += p.w;
    }
    float s = acc.x + acc.y + acc.z + acc.w;
    float q = acc.x*acc.x + acc.y*acc.y + acc.z*acc.z + acc.w*acc.w;
    int lane = tid & 31, wid = tid >> 5;
#pragma unroll
    for (int o = 16; o; o >>= 1) {
        s += __shfl_xor_sync(~0u, s, o); q += __shfl_xor_sync(~0u, q, o);
    }
    if (lane == 0) { shs[wid] = s; shq[wid] = q; }
    __syncthreads();
    if (tid == 0) {
        float ts = 0, tq = 0;
        for (int i = 0; i < 8; i++) { ts += shs[i]; tq += shq[i]; }
        shs[0] = ts; shq[0] = tq;
    }
    __syncthreads();
    float mean = shs[0] * (1.f / DIM);
    float rstd = rsqrtf(shq[0] * (1.f / DIM) - mean * mean + 1e-5f);
    float4 g4 = ((const float4*)gamma)[tid], b4 = ((const float4*)beta)[tid];
    float4 o;
    o.x = (acc.x - mean) * rstd * g4.x + b4.x;
    o.y = (acc.y - mean) * rstd * g4.y + b4.y;
    o.z = (acc.z - mean) * rstd * g4.z + b4.z;
    o.w = (acc.w - mean) * rstd * g4.w + b4.w;
    *(float4*)(out + base) = o;
}

// ---- fused attention: compressed(32) + window(16) ----
__global__ __launch_bounds__(256) void attn_kernel(
    const float* __restrict__ Q, const float* __restrict__ K,
    const float* __restrict__ V, const float* __restrict__ Kc,
    const float* __restrict__ Vc, float* __restrict__ C)
{
    __shared__ float Kcs[NL][DHD + 1];
    __shared__ float Vcs[NL][DHD + 1];
    __shared__ float Kws[BAND][DHD + 1];
    __shared__ float Vws[BAND][DHD + 1];
    __shared__ float Qs[WW][DHD + 1];
    __shared__ float probs[WW][NL + BAND];

    int g = blockIdx.x, h = blockIdx.y, b = blockIdx.z;
    int bh = b * NH + h, tid = threadIdx.x;
    {
        int l = tid >> 3, d0 = (tid & 7) * 8;
        size_t src = ((size_t)bh * NL + l) * DHD + d0;
        float tk[8], tv[8];
        *(float4*)tk = *(const float4*)(Kc + src); *(float4*)(tk+4) = *(const float4*)(Kc + src + 4);
        *(float4*)tv = *(const float4*)(Vc + src); *(float4*)(tv+4) = *(const float4*)(Vc + src + 4);
#pragma unroll
        for (int i = 0; i < 8; i++) { Kcs[l][d0+i] = tk[i]; Vcs[l][d0+i] = tv[i]; }
    }
    {
        int k = tid >> 4, d = (tid & 15) * 4;
        int sk = g * WW - EE + k;
        float4 kv = make_float4(0,0,0,0), vv = make_float4(0,0,0,0);
        if (sk >= 0 && sk < SEQN) {
            size_t src = ((size_t)bh * SEQN + sk) * DHD + d;
            kv = *(const float4*)(K + src); vv = *(const float4*)(V + src);
        }
        Kws[k][d] = kv.x; Kws[k][d+1] = kv.y; Kws[k][d+2] = kv.z; Kws[k][d+3] = kv.w;
        Vws[k][d] = vv.x; Vws[k][d+1] = vv.y; Vws[k][d+2] = vv.z; Vws[k][d+3] = vv.w;
    }
    if (tid < 128) {
        int w = tid >> 4, d = (tid & 15) * 4;
        float4 qv = *(const float4*)(Q + ((size_t)bh * SEQN + g * WW + w) * DHD + d);
        Qs[w][d] = qv.x; Qs[w][d+1] = qv.y; Qs[w][d+2] = qv.z; Qs[w][d+3] = qv.w;
    }
    __syncthreads();

    int warp = tid >> 5, lane = tid & 31;
    float sc = 0.f, sw = 0.f;
    int k = lane & 15;
#pragma unroll
    for (int d = 0; d < DHD; d++) {
        float qd = Qs[warp][d];
        sc += qd * Kcs[lane][d];
        sw += qd * Kws[k][d];
    }
    int sk = g * WW - EE + k;
    bool kvalid = (lane < BAND) && (sk >= 0) && (sk < SEQN);
    float m = fmaxf(sc, kvalid ? sw : -1e30f);
#pragma unroll
    for (int o = 16; o; o >>= 1) m = fmaxf(m, __shfl_xor_sync(~0u, m, o));
    float e0 = __expf(sc - m);
    float e1 = kvalid ? __expf(sw - m) : 0.f;
    float t = e0 + e1;
#pragma unroll
    for (int o = 16; o; o >>= 1) t += __shfl_xor_sync(~0u, t, o);
    float inv = 1.f / t;
    probs[warp][lane] = e0 * inv;
    if (lane < BAND) probs[warp][NL + lane] = e1 * inv;
    __syncwarp();

    float a0 = 0.f, a1 = 0.f;
#pragma unroll
    for (int j = 0; j < NL; j++) {
        float p = probs[warp][j];
        a0 += p * Vcs[j][lane]; a1 += p * Vcs[j][lane + 32];
    }
#pragma unroll
    for (int kk = 0; kk < BAND; kk++) {
        float p = probs[warp][NL + kk];
        a0 += p * Vws[kk][lane]; a1 += p * Vws[kk][lane + 32];
    }
    size_t off = ((size_t)(b * SEQN) + g * WW + warp) * DIM + h * DHD;
    C[off + lane] = a0;
    C[off + 32 + lane] = a1;
}

// ===========================================================================
extern "C" void kernel_launch(void* const* d_in, const int* in_sizes, int n_in,
                              void* d_out, int out_size)
{
    (void)in_sizes; (void)n_in; (void)out_size;
    const float* query = (const float*)d_in[0];
    const float* Wq = (const float*)d_in[1];  const float* bq = (const float*)d_in[2];
    const float* Wk = (const float*)d_in[3];  const float* bk = (const float*)d_in[4];
    const float* Wv = (const float*)d_in[5];  const float* bv = (const float*)d_in[6];
    const float* Wo = (const float*)d_in[7];  const float* bo = (const float*)d_in[8];
    const float* gl = (const float*)d_in[9];  const float* bl = (const float*)d_in[10];
    const float* gs = (const float*)d_in[11]; const float* bs = (const float*)d_in[12];
    const float* Wd = (const float*)d_in[13]; const float* bd = (const float*)d_in[14];
    float* out = (float*)d_out;

    float *pQ,*pK,*pV,*pTmp,*pD,*pP,*pKcP,*pVcP,*pKc,*pVc,*pC;
    __half *pXh,*pXl,*pCh,*pCl,*pWth,*pWtl;
    cudaGetSymbolAddress((void**)&pQ, g_Q);
    cudaGetSymbolAddress((void**)&pK, g_K);
    cudaGetSymbolAddress((void**)&pV, g_V);
    cudaGetSymbolAddress((void**)&pTmp, g_tmp);
    cudaGetSymbolAddress((void**)&pD, g_D);
    cudaGetSymbolAddress((void**)&pP, g_P);
    cudaGetSymbolAddress((void**)&pKcP, g_KcP);
    cudaGetSymbolAddress((void**)&pVcP, g_VcP);
    cudaGetSymbolAddress((void**)&pKc, g_Kc);
    cudaGetSymbolAddress((void**)&pVc, g_Vc);
    cudaGetSymbolAddress((void**)&pC, g_C);
    cudaGetSymbolAddress((void**)&pXh, g_Xh);
    cudaGetSymbolAddress((void**)&pXl, g_Xl);
    cudaGetSymbolAddress((void**)&pCh, g_Ch);
    cudaGetSymbolAddress((void**)&pCl, g_Cl);
    cudaGetSymbolAddress((void**)&pWth, g_Wth);
    cudaGetSymbolAddress((void**)&pWtl, g_Wtl);

    cudaFuncSetAttribute(hgemm<0>, cudaFuncAttributeMaxDynamicSharedMemorySize, GEMM_SMEM);
    cudaFuncSetAttribute(hgemm<1>, cudaFuncAttributeMaxDynamicSharedMemorySize, GEMM_SMEM);
    cudaFuncSetAttribute(hgemm<2>, cudaFuncAttributeMaxDynamicSharedMemorySize, GEMM_SMEM);

    // operand prep
    split_kernel<1><<<MROWS * DIM / 4 / 256, 256>>>(query, pXh, pXl);
    dim3 wt(DIM / 32, DIM / 32), wb(32, 8);
    wsplit_kernel<<<wt, wb>>>(Wq, pWth + WOFF_Q, pWtl + WOFF_Q, DIM);
    wsplit_kernel<<<wt, wb>>>(Wk, pWth + WOFF_K, pWtl + WOFF_K, DIM);
    wsplit_kernel<<<wt, wb>>>(Wv, pWth + WOFF_V, pWtl + WOFF_V, DIM);
    wsplit_kernel<<<wt, wb>>>(Wo, pWth + WOFF_O, pWtl + WOFF_O, DIM);
    wsplit_kernel<<<dim3((NH * NL) / 32, DIM / 32), wb>>>(Wd, pWth + WOFF_D, pWtl + WOFF_D, NH * NL);

    dim3 gQKV(DIM / 128, MROWS / 128);
    dim3 gD((NH * NL) / 128, MROWS / 128);
    hgemm<1><<<gQKV, 256, GEMM_SMEM>>>(pXh, pXl, pWth + WOFF_Q, pWtl + WOFF_Q, bq, pQ, DIM, 0.125f);
    hgemm<0><<<gQKV, 256, GEMM_SMEM>>>(pXh, pXl, pWth + WOFF_K, pWtl + WOFF_K, bk, pTmp, DIM, 1.f);
    ln_split_kernel<<<MROWS, 256>>>(pTmp, gl, bl, pK);
    hgemm<0><<<gQKV, 256, GEMM_SMEM>>>(pXh, pXl, pWth + WOFF_V, pWtl + WOFF_V, bv, pTmp, DIM, 1.f);
    ln_split_kernel<<<MROWS, 256>>>(pTmp, gl, bl, pV);
    hgemm<0><<<gD, 256, GEMM_SMEM>>>(pXh, pXl, pWth + WOFF_D, pWtl + WOFF_D, bd, pD, NH * NL, 1.f);

    transpose_kernel<<<dim3((NH * NL) / 32, SEQN / 32, BATCH), dim3(32, 8)>>>(pD, pP);
    softmax_rows_kernel<<<BATCH * NH * NL, 256>>>(pP);
    compress_partial_kernel<<<dim3(BATCH * NH, NSPLIT), 256>>>(pP, pK, pV, pKcP, pVcP);
    compress_ln_kernel<<<dim3(BATCH * NL, 2), 256>>>(pKcP, pVcP, gs, bs, pKc, pVc);
    attn_kernel<<<dim3(NG, NH, BATCH), 256>>>(pQ, pK, pV, pKc, pVc, pC);

    split_kernel<0><<<MROWS * DIM / 4 / 256, 256>>>(pC, pCh, pCl);
    hgemm<2><<<gQKV, 256, GEMM_SMEM>>>(pCh, pCl, pWth + WOFF_O, pWtl + WOFF_O, bo, out, DIM, 1.f);
}

// round 6
// speedup vs baseline: 2.2030x; 1.0001x over previous
#include <cuda_runtime.h>
#include <cuda_fp16.h>
#include <math.h>
#include <stdint.h>

#define SEQN  4096
#define BATCH 4
#define DIM   1024
#define NH    16
#define DHD   64
#define NL    32
#define WW    8
#define EE    4
#define BAND  16
#define NG    (SEQN / WW)
#define MROWS (BATCH * SEQN)
#define NSPLIT 8
#define CSIZE (BATCH * NH * NL * DHD)

__device__ float g_Q  [BATCH * NH * SEQN * DHD];
__device__ float g_K  [BATCH * NH * SEQN * DHD];
__device__ float g_V  [BATCH * NH * SEQN * DHD];
__device__ float g_tmp[BATCH * SEQN * DIM];
__device__ float g_D  [BATCH * SEQN * NH * NL];
__device__ float g_P  [BATCH * NH * NL * SEQN];
__device__ float g_KcP[NSPLIT * CSIZE];
__device__ float g_VcP[NSPLIT * CSIZE];
__device__ float g_Kc [CSIZE];
__device__ float g_Vc [CSIZE];
__device__ float g_C  [BATCH * SEQN * DIM];

__device__ __align__(16) __half g_Xh[MROWS * DIM];
__device__ __align__(16) __half g_Xl[MROWS * DIM];
__device__ __align__(16) __half g_Ch[MROWS * DIM];
__device__ __align__(16) __half g_Cl[MROWS * DIM];
#define WOFF_Q 0
#define WOFF_K (1 * DIM * DIM)
#define WOFF_V (2 * DIM * DIM)
#define WOFF_O (3 * DIM * DIM)
#define WOFF_D (4 * DIM * DIM)
#define WT_TOTAL (4 * DIM * DIM + (NH * NL) * DIM)
__device__ __align__(16) __half g_Wth[WT_TOTAL];
__device__ __align__(16) __half g_Wtl[WT_TOTAL];

// =========================== HMMA GEMM =====================================
// out[M=16384, N] = A @ Bt^T, A hi/lo [m][k] stride DIM, Bt hi/lo [n][k].
// fp16 error split: acc = Ah*Bh + Ah*Bl + Al*Bh (fp32 accum).
#define SROWB 80                 // 64B data + 16B pad per 32-half row
#define TILEB (128 * SROWB)      // 10240 B
#define STAGEB (4 * TILEB)       // AH, AL, BH, BL
#define SM_AH(s) ((s) * STAGEB + 0)
#define SM_AL(s) ((s) * STAGEB + TILEB)
#define SM_BH(s) ((s) * STAGEB + 2 * TILEB)
#define SM_BL(s) ((s) * STAGEB + 3 * TILEB)
#define GEMM_SMEM (2 * STAGEB)   // 81920 B
#define NIT (DIM / 32)           // 32 k-chunks of 32 halves

__device__ __forceinline__ uint32_t smem_u32(const void* p) {
    uint32_t a;
    asm("{ .reg .u64 t; cvta.to.shared.u64 t, %1; cvt.u32.u64 %0, t; }" : "=r"(a) : "l"(p));
    return a;
}
#define CPA(dst, src) \
    asm volatile("cp.async.cg.shared.global [%0], [%1], 16;" :: "r"(dst), "l"(src))
#define CP_COMMIT() asm volatile("cp.async.commit_group;")
#define CP_WAIT(n)  asm volatile("cp.async.wait_group %0;" :: "n"(n))
#define LDSM4(R, addr) \
    asm volatile("ldmatrix.sync.aligned.m8n8.x4.shared.b16 {%0,%1,%2,%3}, [%4];" \
        : "=r"((R)[0]), "=r"((R)[1]), "=r"((R)[2]), "=r"((R)[3]) : "r"(addr))
#define MMA16816(d, a, b0, b1) \
    asm volatile("mma.sync.aligned.m16n8k16.row.col.f32.f16.f16.f32 " \
        "{%0,%1,%2,%3}, {%4,%5,%6,%7}, {%8,%9}, {%0,%1,%2,%3};" \
        : "+f"((d)[0]), "+f"((d)[1]), "+f"((d)[2]), "+f"((d)[3]) \
        : "r"((a)[0]), "r"((a)[1]), "r"((a)[2]), "r"((a)[3]), "r"(b0), "r"(b1))

// OUT_MODE: 0 row-major[r*N+c]; 1 Q head-split scaled; 2 (s,b,DIM)
template <int OUT_MODE>
__global__ __launch_bounds__(256, 2) void hgemm(
    const __half* __restrict__ Ah, const __half* __restrict__ Al,
    const __half* __restrict__ Bh, const __half* __restrict__ Bl,
    const float* __restrict__ bias, float* __restrict__ out, int N, float scale)
{
    extern __shared__ __align__(16) char smem[];
    const uint32_t sb = smem_u32(smem);
    const int tid = threadIdx.x, wid = tid >> 5, lane = tid & 31;
    const int bn = blockIdx.x * 128, bm = blockIdx.y * 128;
    const int wm = wid & 3, wn = wid >> 2;

    // --- async loader mapping: 2 rows x 16B per tile per thread ---
    const int lr0 = tid >> 2;
    const size_t aoff0 = ((size_t)(bm + lr0) << 10) + (size_t)(tid & 3) * 8;
    const size_t aoff1 = aoff0 + ((size_t)64 << 10);
    const size_t boff0 = ((size_t)(bn + lr0) << 10) + (size_t)(tid & 3) * 8;
    const size_t boff1 = boff0 + ((size_t)64 << 10);
    const uint32_t d0 = (uint32_t)lr0 * SROWB + (tid & 3) * 16;
    const uint32_t d1 = d0 + 64 * SROWB;

    // prologue: stage 0 (k chunk 0)
    CPA(sb + SM_AH(0) + d0, Ah + aoff0); CPA(sb + SM_AH(0) + d1, Ah + aoff1);
    CPA(sb + SM_AL(0) + d0, Al + aoff0); CPA(sb + SM_AL(0) + d1, Al + aoff1);
    CPA(sb + SM_BH(0) + d0, Bh + boff0); CPA(sb + SM_BH(0) + d1, Bh + boff1);
    CPA(sb + SM_BL(0) + d0, Bl + boff0); CPA(sb + SM_BL(0) + d1, Bl + boff1);
    CP_COMMIT();

    float acc[2][8][4];
#pragma unroll
    for (int i = 0; i < 2; i++)
#pragma unroll
        for (int j = 0; j < 8; j++)
#pragma unroll
            for (int k = 0; k < 4; k++) acc[i][j][k] = 0.f;

    // per-warp ldmatrix base offsets (within a tile)
    const uint32_t aBase = (uint32_t)(wm * 32 + (lane & 15)) * SROWB + (lane >> 4) * 16;
    const uint32_t bBase = (uint32_t)(wn * 64 + ((lane >> 4) & 1) * 8 + (lane & 7)) * SROWB
                           + ((lane >> 3) & 1) * 16;

    for (int it = 0; it < NIT; it++) {
        const int p = it & 1;
        if (it + 1 < NIT) {
            const int np = p ^ 1;
            const int kb = (it + 1) * 32;
            CPA(sb + SM_AH(np) + d0, Ah + aoff0 + kb); CPA(sb + SM_AH(np) + d1, Ah + aoff1 + kb);
            CPA(sb + SM_AL(np) + d0, Al + aoff0 + kb); CPA(sb + SM_AL(np) + d1, Al + aoff1 + kb);
            CPA(sb + SM_BH(np) + d0, Bh + boff0 + kb); CPA(sb + SM_BH(np) + d1, Bh + boff1 + kb);
            CPA(sb + SM_BL(np) + d0, Bl + boff0 + kb); CPA(sb + SM_BL(np) + d1, Bl + boff1 + kb);
            CP_COMMIT();
            CP_WAIT(1);
        } else {
            CP_WAIT(0);
        }
        __syncthreads();

        const uint32_t sAH = sb + SM_AH(p) + aBase, sAL = sb + SM_AL(p) + aBase;
        const uint32_t sBH = sb + SM_BH(p) + bBase, sBL = sb + SM_BL(p) + bBase;
#pragma unroll
        for (int ks = 0; ks < 2; ks++) {
            const uint32_t ko = ks * 32;
            uint32_t ah[2][4], al[2][4];
            LDSM4(ah[0], sAH + ko);
            LDSM4(ah[1], sAH + ko + 16 * SROWB);
            LDSM4(al[0], sAL + ko);
            LDSM4(al[1], sAL + ko + 16 * SROWB);
#pragma unroll
            for (int q = 0; q < 4; q++) {
                uint32_t bh[4], bl[4];
                LDSM4(bh, sBH + ko + q * 16 * SROWB);
                LDSM4(bl, sBL + ko + q * 16 * SROWB);
#pragma unroll
                for (int mt = 0; mt < 2; mt++) {
                    MMA16816(acc[mt][2 * q + 0], ah[mt], bh[0], bh[1]);
                    MMA16816(acc[mt][2 * q + 0], ah[mt], bl[0], bl[1]);
                    MMA16816(acc[mt][2 * q + 0], al[mt], bh[0], bh[1]);
                    MMA16816(acc[mt][2 * q + 1], ah[mt], bh[2], bh[3]);
                    MMA16816(acc[mt][2 * q + 1], ah[mt], bl[2], bl[3]);
                    MMA16816(acc[mt][2 * q + 1], al[mt], bh[2], bh[3]);
                }
            }
        }
        __syncthreads();
    }

    // --- epilogue: bias + scale + layout fuse ---
    const int r0 = bm + wm * 32 + (lane >> 2);
    const int c0 = bn + wn * 64 + (lane & 3) * 2;
#pragma unroll
    for (int mt = 0; mt < 2; mt++) {
#pragma unroll
        for (int hf = 0; hf < 2; hf++) {
            const int r = r0 + mt * 16 + hf * 8;
            const int bb = r >> 12, ss = r & (SEQN - 1);
#pragma unroll
            for (int nt = 0; nt < 8; nt++) {
                const int col = c0 + nt * 8;
                const float2 bv = *(const float2*)(bias + col);
                float vx = (acc[mt][nt][hf * 2 + 0] + bv.x) * scale;
                float vy = (acc[mt][nt][hf * 2 + 1] + bv.y) * scale;
                size_t o;
                if (OUT_MODE == 0) o = (size_t)r * N + col;
                else if (OUT_MODE == 1)
                    o = ((size_t)(bb * NH + (col >> 6)) * SEQN + ss) * DHD + (col & 63);
                else o = ((size_t)ss * BATCH + bb) * DIM + col;
                *(float2*)(out + o) = make_float2(vx, vy);
            }
        }
    }
}

// ---- fp32 -> fp16 hi/lo split (PERM=1: (s,b)->(b,s)) ----
template <int PERM>
__global__ __launch_bounds__(256) void split_kernel(
    const float* __restrict__ X, __half* __restrict__ H, __half* __restrict__ L)
{
    int i = blockIdx.x * 256 + threadIdx.x;
    float4 v;
    if (PERM) {
        int r = i >> 8, k4 = i & 255;
        int b = r >> 12, s = r & (SEQN - 1);
        v = *((const float4*)X + ((size_t)s * BATCH + b) * 256 + k4);
    } else v = ((const float4*)X)[i];
    __half h0 = __float2half_rn(v.x), h1 = __float2half_rn(v.y);
    __half h2 = __float2half_rn(v.z), h3 = __float2half_rn(v.w);
    __half2* Hp = (__half2*)(H + (size_t)i * 4);
    __half2* Lp = (__half2*)(L + (size_t)i * 4);
    Hp[0] = __halves2half2(h0, h1); Hp[1] = __halves2half2(h2, h3);
    Lp[0] = __halves2half2(__float2half_rn(v.x - __half2float(h0)),
                           __float2half_rn(v.y - __half2float(h1)));
    Lp[1] = __halves2half2(__float2half_rn(v.z - __half2float(h2)),
                           __float2half_rn(v.w - __half2float(h3)));
}

// ---- weight transpose + split: Th[n][k] = fp16(W[k][n]) ----
__global__ void wsplit_kernel(const float* __restrict__ W,
                              __half* __restrict__ Th, __half* __restrict__ Tl, int N)
{
    __shared__ float t[32][33];
    int n0 = blockIdx.x * 32, k0 = blockIdx.y * 32;
    int x = threadIdx.x, y = threadIdx.y;
#pragma unroll
    for (int i = 0; i < 32; i += 8)
        t[y + i][x] = W[(size_t)(k0 + y + i) * N + n0 + x];
    __syncthreads();
#pragma unroll
    for (int i = 0; i < 32; i += 8) {
        float v = t[x][y + i];
        __half h = __float2half_rn(v);
        size_t o = (size_t)(n0 + y + i) * DIM + k0 + x;
        Th[o] = h;
        Tl[o] = __float2half_rn(v - __half2float(h));
    }
}

// ---- LayerNorm over DIM, scatter head-split ----
__global__ __launch_bounds__(256) void ln_split_kernel(
    const float* __restrict__ X, const float* __restrict__ gamma,
    const float* __restrict__ beta, float* __restrict__ out)
{
    __shared__ float shs[8], shq[8];
    int r = blockIdx.x, tid = threadIdx.x;
    const float4 v = ((const float4*)(X + (size_t)r * DIM))[tid];
    float s = v.x + v.y + v.z + v.w;
    float q = v.x*v.x + v.y*v.y + v.z*v.z + v.w*v.w;
    int lane = tid & 31, wid = tid >> 5;
#pragma unroll
    for (int o = 16; o; o >>= 1) {
        s += __shfl_xor_sync(~0u, s, o); q += __shfl_xor_sync(~0u, q, o);
    }
    if (lane == 0) { shs[wid] = s; shq[wid] = q; }
    __syncthreads();
    if (tid == 0) {
        float ts = 0, tq = 0;
        for (int i = 0; i < 8; i++) { ts += shs[i]; tq += shq[i]; }
        shs[0] = ts; shq[0] = tq;
    }
    __syncthreads();
    float mean = shs[0] * (1.f / DIM);
    float rstd = rsqrtf(shq[0] * (1.f / DIM) - mean * mean + 1e-5f);
    int c = tid * 4;
    float4 g4 = ((const float4*)gamma)[tid], b4 = ((const float4*)beta)[tid];
    float4 o;
    o.x = (v.x - mean) * rstd * g4.x + b4.x;
    o.y = (v.y - mean) * rstd * g4.y + b4.y;
    o.z = (v.z - mean) * rstd * g4.z + b4.z;
    o.w = (v.w - mean) * rstd * g4.w + b4.w;
    int b = r >> 12, sq = r & (SEQN - 1);
    *(float4*)(out + ((size_t)(b * NH + (c >> 6)) * SEQN + sq) * DHD + (c & 63)) = o;
}

// ---- transpose (b,s,512) -> (b,512,s) ----
__global__ void transpose_kernel(const float* __restrict__ D, float* __restrict__ P)
{
    __shared__ float t[32][33];
    int b = blockIdx.z, c0 = blockIdx.x * 32, s0 = blockIdx.y * 32;
    int x = threadIdx.x, y = threadIdx.y;
    const float* Db = D + (size_t)b * SEQN * (NH * NL);
    float* Pb = P + (size_t)b * (NH * NL) * SEQN;
#pragma unroll
    for (int i = 0; i < 32; i += 8)
        t[y + i][x] = Db[(size_t)(s0 + y + i) * (NH * NL) + c0 + x];
    __syncthreads();
#pragma unroll
    for (int i = 0; i < 32; i += 8)
        Pb[(size_t)(c0 + y + i) * SEQN + s0 + x] = t[x][y + i];
}

// ---- row softmax over 4096 ----
__global__ __launch_bounds__(256) void softmax_rows_kernel(float* __restrict__ P)
{
    __shared__ float sh[8];
    size_t base = (size_t)blockIdx.x * SEQN;
    int tid = threadIdx.x, lane = tid & 31, wid = tid >> 5;
    float v[16], m = -1e30f;
#pragma unroll
    for (int i = 0; i < 16; i++) { v[i] = P[base + tid + i * 256]; m = fmaxf(m, v[i]); }
#pragma unroll
    for (int o = 16; o; o >>= 1) m = fmaxf(m, __shfl_xor_sync(~0u, m, o));
    if (lane == 0) sh[wid] = m;
    __syncthreads();
    if (tid == 0) { float t = sh[0]; for (int i = 1; i < 8; i++) t = fmaxf(t, sh[i]); sh[0] = t; }
    __syncthreads();
    float M = sh[0];
    __syncthreads();
    float s = 0.f;
#pragma unroll
    for (int i = 0; i < 16; i++) { v[i] = __expf(v[i] - M); s += v[i]; }
#pragma unroll
    for (int o = 16; o; o >>= 1) s += __shfl_xor_sync(~0u, s, o);
    if (lane == 0) sh[wid] = s;
    __syncthreads();
    if (tid == 0) { float t = 0; for (int i = 0; i < 8; i++) t += sh[i]; sh[0] = t; }
    __syncthreads();
    float inv = 1.f / sh[0];
#pragma unroll
    for (int i = 0; i < 16; i++) P[base + tid + i * 256] = v[i] * inv;
}

// ---- Kc/Vc partials (split-K over s) ----
__global__ __launch_bounds__(256) void compress_partial_kernel(
    const float* __restrict__ P, const float* __restrict__ K,
    const float* __restrict__ V, float* __restrict__ partK, float* __restrict__ partV)
{
    __shared__ float Ps[NL][33];
    __shared__ float Ks[32][DHD];
    __shared__ float Vs[32][DHD];
    int bh = blockIdx.x, sp = blockIdx.y;
    int b = bh >> 4, h = bh & 15;
    int tid = threadIdx.x;
    int l = tid >> 3, qd = (tid & 7) * 8;
    float accK[8] = {}, accV[8] = {};
    const float* Pb = P + (size_t)(b * (NH * NL) + h * NL) * SEQN;
    const float* Kb = K + (size_t)bh * SEQN * DHD;
    const float* Vb = V + (size_t)bh * SEQN * DHD;
    for (int sc = 0; sc < SEQN / NSPLIT; sc += 32) {
        int s0 = sp * (SEQN / NSPLIT) + sc;
        {
            int pl = tid >> 3, ps = (tid & 7) * 4;
            float4 p4 = *(const float4*)(Pb + (size_t)pl * SEQN + s0 + ps);
            Ps[pl][ps] = p4.x; Ps[pl][ps+1] = p4.y; Ps[pl][ps+2] = p4.z; Ps[pl][ps+3] = p4.w;
        }
        {
            int ks = tid >> 3, kd = (tid & 7) * 8;
            const float* kp = Kb + (size_t)(s0 + ks) * DHD + kd;
            *(float4*)&Ks[ks][kd] = *(const float4*)kp;
            *(float4*)&Ks[ks][kd+4] = *(const float4*)(kp + 4);
            const float* vp = Vb + (size_t)(s0 + ks) * DHD + kd;
            *(float4*)&Vs[ks][kd] = *(const float4*)vp;
            *(float4*)&Vs[ks][kd+4] = *(const float4*)(vp + 4);
        }
        __syncthreads();
#pragma unroll 8
        for (int si = 0; si < 32; si++) {
            float p = Ps[l][si];
            float kf[8], vf[8];
            *(float4*)kf = *(float4*)&Ks[si][qd]; *(float4*)(kf+4) = *(float4*)&Ks[si][qd+4];
            *(float4*)vf = *(float4*)&Vs[si][qd]; *(float4*)(vf+4) = *(float4*)&Vs[si][qd+4];
#pragma unroll
            for (int j = 0; j < 8; j++) { accK[j] += p * kf[j]; accV[j] += p * vf[j]; }
        }
        __syncthreads();
    }
    size_t ob = (size_t)sp * CSIZE + ((size_t)bh * NL + l) * DHD + qd;
    *(float4*)(partK + ob)   = make_float4(accK[0], accK[1], accK[2], accK[3]);
    *(float4*)(partK + ob+4) = make_float4(accK[4], accK[5], accK[6], accK[7]);
    *(float4*)(partV + ob)   = make_float4(accV[0], accV[1], accV[2], accV[3]);
    *(float4*)(partV + ob+4) = make_float4(accV[4], accV[5], accV[6], accV[7]);
}

// ---- reduce partials + LN for Kc/Vc ----
__global__ __launch_bounds__(256) void compress_ln_kernel(
    const float* __restrict__ partK, const float* __restrict__ partV,
    const float* __restrict__ gamma, const float* __restrict__ beta,
    float* __restrict__ outK, float* __restrict__ outV)
{
    __shared__ float shs[8], shq[8];
    int bl = blockIdx.x, b = bl >> 5, l = bl & 31;
    const float* part = blockIdx.y ? partV : partK;
    float* out = blockIdx.y ? outV : outK;
    int tid = threadIdx.x, c = tid * 4;
    size_t base = ((size_t)(b * NH + (c >> 6)) * NL + l) * DHD + (c & 63);
    float4 acc = make_float4(0, 0, 0, 0);
#pragma unroll
    for (int sp = 0; sp < NSPLIT; sp++) {
        float4 p = *(const float4*)(part + (size_t)sp * CSIZE + base);
        acc.x += p.x; acc.y += p.y; acc.z += p.z; acc.w += p.w;
    }
    float s = acc.x + acc.y + acc.z + acc.w;
    float q = acc.x*acc.x + acc.y*acc.y + acc.z*acc.z + acc.w*acc.w;
    int lane = tid & 31, wid = tid >> 5;
#pragma unroll
    for (int o = 16; o; o >>= 1) {
        s += __shfl_xor_sync(~0u, s, o); q += __shfl_xor_sync(~0u, q, o);
    }
    if (lane == 0) { shs[wid] = s; shq[wid] = q; }
    __syncthreads();
    if (tid == 0) {
        float ts = 0, tq = 0;
        for (int i = 0; i < 8; i++) { ts += shs[i]; tq += shq[i]; }
        shs[0] = ts; shq[0] = tq;
    }
    __syncthreads();
    float mean = shs[0] * (1.f / DIM);
    float rstd = rsqrtf(shq[0] * (1.f / DIM) - mean * mean + 1e-5f);
    float4 g4 = ((const float4*)gamma)[tid], b4 = ((const float4*)beta)[tid];
    float4 o;
    o.x = (acc.x - mean) * rstd * g4.x + b4.x;
    o.y = (acc.y - mean) * rstd * g4.y + b4.y;
    o.z = (acc.z - mean) * rstd * g4.z + b4.z;
    o.w = (acc.w - mean) * rstd * g4.w + b4.w;
    *(float4*)(out + base) = o;
}

// ---- fused attention: compressed(32) + window(16) ----
__global__ __launch_bounds__(256) void attn_kernel(
    const float* __restrict__ Q, const float* __restrict__ K,
    const float* __restrict__ V, const float* __restrict__ Kc,
    const float* __restrict__ Vc, float* __restrict__ C)
{
    __shared__ float Kcs[NL][DHD + 1];
    __shared__ float Vcs[NL][DHD + 1];
    __shared__ float Kws[BAND][DHD + 1];
    __shared__ float Vws[BAND][DHD + 1];
    __shared__ float Qs[WW][DHD + 1];
    __shared__ float probs[WW][NL + BAND];

    int g = blockIdx.x, h = blockIdx.y, b = blockIdx.z;
    int bh = b * NH + h, tid = threadIdx.x;
    {
        int l = tid >> 3, d0 = (tid & 7) * 8;
        size_t src = ((size_t)bh * NL + l) * DHD + d0;
        float tk[8], tv[8];
        *(float4*)tk = *(const float4*)(Kc + src); *(float4*)(tk+4) = *(const float4*)(Kc + src + 4);
        *(float4*)tv = *(const float4*)(Vc + src); *(float4*)(tv+4) = *(const float4*)(Vc + src + 4);
#pragma unroll
        for (int i = 0; i < 8; i++) { Kcs[l][d0+i] = tk[i]; Vcs[l][d0+i] = tv[i]; }
    }
    {
        int k = tid >> 4, d = (tid & 15) * 4;
        int sk = g * WW - EE + k;
        float4 kv = make_float4(0,0,0,0), vv = make_float4(0,0,0,0);
        if (sk >= 0 && sk < SEQN) {
            size_t src = ((size_t)bh * SEQN + sk) * DHD + d;
            kv = *(const float4*)(K + src); vv = *(const float4*)(V + src);
        }
        Kws[k][d] = kv.x; Kws[k][d+1] = kv.y; Kws[k][d+2] = kv.z; Kws[k][d+3] = kv.w;
        Vws[k][d] = vv.x; Vws[k][d+1] = vv.y; Vws[k][d+2] = vv.z; Vws[k][d+3] = vv.w;
    }
    if (tid < 128) {
        int w = tid >> 4, d = (tid & 15) * 4;
        float4 qv = *(const float4*)(Q + ((size_t)bh * SEQN + g * WW + w) * DHD + d);
        Qs[w][d] = qv.x; Qs[w][d+1] = qv.y; Qs[w][d+2] = qv.z; Qs[w][d+3] = qv.w;
    }
    __syncthreads();

    int warp = tid >> 5, lane = tid & 31;
    float sc = 0.f, sw = 0.f;
    int k = lane & 15;
#pragma unroll
    for (int d = 0; d < DHD; d++) {
        float qd = Qs[warp][d];
        sc += qd * Kcs[lane][d];
        sw += qd * Kws[k][d];
    }
    int sk = g * WW - EE + k;
    bool kvalid = (lane < BAND) && (sk >= 0) && (sk < SEQN);
    float m = fmaxf(sc, kvalid ? sw : -1e30f);
#pragma unroll
    for (int o = 16; o; o >>= 1) m = fmaxf(m, __shfl_xor_sync(~0u, m, o));
    float e0 = __expf(sc - m);
    float e1 = kvalid ? __expf(sw - m) : 0.f;
    float t = e0 + e1;
#pragma unroll
    for (int o = 16; o; o >>= 1) t += __shfl_xor_sync(~0u, t, o);
    float inv = 1.f / t;
    probs[warp][lane] = e0 * inv;
    if (lane < BAND) probs[warp][NL + lane] = e1 * inv;
    __syncwarp();

    float a0 = 0.f, a1 = 0.f;
#pragma unroll
    for (int j = 0; j < NL; j++) {
        float p = probs[warp][j];
        a0 += p * Vcs[j][lane]; a1 += p * Vcs[j][lane + 32];
    }
#pragma unroll
    for (int kk = 0; kk < BAND; kk++) {
        float p = probs[warp][NL + kk];
        a0 += p * Vws[kk][lane]; a1 += p * Vws[kk][lane + 32];
    }
    size_t off = ((size_t)(b * SEQN) + g * WW + warp) * DIM + h * DHD;
    C[off + lane] = a0;
    C[off + 32 + lane] = a1;
}

// ===========================================================================
extern "C" void kernel_launch(void* const* d_in, const int* in_sizes, int n_in,
                              void* d_out, int out_size)
{
    (void)in_sizes; (void)n_in; (void)out_size;
    const float* query = (const float*)d_in[0];
    const float* Wq = (const float*)d_in[1];  const float* bq = (const float*)d_in[2];
    const float* Wk = (const float*)d_in[3];  const float* bk = (const float*)d_in[4];
    const float* Wv = (const float*)d_in[5];  const float* bv = (const float*)d_in[6];
    const float* Wo = (const float*)d_in[7];  const float* bo = (const float*)d_in[8];
    const float* gl = (const float*)d_in[9];  const float* bl = (const float*)d_in[10];
    const float* gs = (const float*)d_in[11]; const float* bs = (const float*)d_in[12];
    const float* Wd = (const float*)d_in[13]; const float* bd = (const float*)d_in[14];
    float* out = (float*)d_out;

    float *pQ,*pK,*pV,*pTmp,*pD,*pP,*pKcP,*pVcP,*pKc,*pVc,*pC;
    __half *pXh,*pXl,*pCh,*pCl,*pWth,*pWtl;
    cudaGetSymbolAddress((void**)&pQ, g_Q);
    cudaGetSymbolAddress((void**)&pK, g_K);
    cudaGetSymbolAddress((void**)&pV, g_V);
    cudaGetSymbolAddress((void**)&pTmp, g_tmp);
    cudaGetSymbolAddress((void**)&pD, g_D);
    cudaGetSymbolAddress((void**)&pP, g_P);
    cudaGetSymbolAddress((void**)&pKcP, g_KcP);
    cudaGetSymbolAddress((void**)&pVcP, g_VcP);
    cudaGetSymbolAddress((void**)&pKc, g_Kc);
    cudaGetSymbolAddress((void**)&pVc, g_Vc);
    cudaGetSymbolAddress((void**)&pC, g_C);
    cudaGetSymbolAddress((void**)&pXh, g_Xh);
    cudaGetSymbolAddress((void**)&pXl, g_Xl);
    cudaGetSymbolAddress((void**)&pCh, g_Ch);
    cudaGetSymbolAddress((void**)&pCl, g_Cl);
    cudaGetSymbolAddress((void**)&pWth, g_Wth);
    cudaGetSymbolAddress((void**)&pWtl, g_Wtl);

    cudaFuncSetAttribute(hgemm<0>, cudaFuncAttributeMaxDynamicSharedMemorySize, GEMM_SMEM);
    cudaFuncSetAttribute(hgemm<1>, cudaFuncAttributeMaxDynamicSharedMemorySize, GEMM_SMEM);
    cudaFuncSetAttribute(hgemm<2>, cudaFuncAttributeMaxDynamicSharedMemorySize, GEMM_SMEM);

    // operand prep
    split_kernel<1><<<MROWS * DIM / 4 / 256, 256>>>(query, pXh, pXl);
    dim3 wt(DIM / 32, DIM / 32), wb(32, 8);
    wsplit_kernel<<<wt, wb>>>(Wq, pWth + WOFF_Q, pWtl + WOFF_Q, DIM);
    wsplit_kernel<<<wt, wb>>>(Wk, pWth + WOFF_K, pWtl + WOFF_K, DIM);
    wsplit_kernel<<<wt, wb>>>(Wv, pWth + WOFF_V, pWtl + WOFF_V, DIM);
    wsplit_kernel<<<wt, wb>>>(Wo, pWth + WOFF_O, pWtl + WOFF_O, DIM);
    wsplit_kernel<<<dim3((NH * NL) / 32, DIM / 32), wb>>>(Wd, pWth + WOFF_D, pWtl + WOFF_D, NH * NL);

    dim3 gQKV(DIM / 128, MROWS / 128);
    dim3 gD((NH * NL) / 128, MROWS / 128);
    hgemm<1><<<gQKV, 256, GEMM_SMEM>>>(pXh, pXl, pWth + WOFF_Q, pWtl + WOFF_Q, bq, pQ, DIM, 0.125f);
    hgemm<0><<<gQKV, 256, GEMM_SMEM>>>(pXh, pXl, pWth + WOFF_K, pWtl + WOFF_K, bk, pTmp, DIM, 1.f);
    ln_split_kernel<<<MROWS, 256>>>(pTmp, gl, bl, pK);
    hgemm<0><<<gQKV, 256, GEMM_SMEM>>>(pXh, pXl, pWth + WOFF_V, pWtl + WOFF_V, bv, pTmp, DIM, 1.f);
    ln_split_kernel<<<MROWS, 256>>>(pTmp, gl, bl, pV);
    hgemm<0><<<gD, 256, GEMM_SMEM>>>(pXh, pXl, pWth + WOFF_D, pWtl + WOFF_D, bd, pD, NH * NL, 1.f);

    transpose_kernel<<<dim3((NH * NL) / 32, SEQN / 32, BATCH), dim3(32, 8)>>>(pD, pP);
    softmax_rows_kernel<<<BATCH * NH * NL, 256>>>(pP);
    compress_partial_kernel<<<dim3(BATCH * NH, NSPLIT), 256>>>(pP, pK, pV, pKcP, pVcP);
    compress_ln_kernel<<<dim3(BATCH * NL, 2), 256>>>(pKcP, pVcP, gs, bs, pKc, pVc);
    attn_kernel<<<dim3(NG, NH, BATCH), 256>>>(pQ, pK, pV, pKc, pVc, pC);

    split_kernel<0><<<MROWS * DIM / 4 / 256, 256>>>(pC, pCh, pCl);
    hgemm<2><<<gQKV, 256, GEMM_SMEM>>>(pCh, pCl, pWth + WOFF_O, pWtl + WOFF_O, bo, out, DIM, 1.f);
}

// round 7
// speedup vs baseline: 2.3583x; 1.0705x over previous
#include <cuda_runtime.h>
#include <cuda_fp16.h>
#include <math.h>
#include <stdint.h>

#define SEQN  4096
#define BATCH 4
#define DIM   1024
#define NH    16
#define DHD   64
#define NL    32
#define WW    8
#define EE    4
#define BAND  16
#define NG    (SEQN / WW)
#define MROWS (BATCH * SEQN)
#define NSPLIT 8
#define CSIZE (BATCH * NH * NL * DHD)

__device__ float g_Q  [BATCH * NH * SEQN * DHD];
__device__ float g_K  [BATCH * NH * SEQN * DHD];
__device__ float g_V  [BATCH * NH * SEQN * DHD];
__device__ float g_tmp[BATCH * SEQN * DIM];        // K pre-LN
__device__ float g_tv [BATCH * SEQN * DIM];        // V pre-LN
__device__ float g_D  [BATCH * SEQN * NH * NL];
__device__ float g_P  [BATCH * NH * NL * SEQN];
__device__ float g_KcP[NSPLIT * CSIZE];
__device__ float g_VcP[NSPLIT * CSIZE];
__device__ float g_Kc [CSIZE];
__device__ float g_Vc [CSIZE];

__device__ __align__(16) __half g_Xh[MROWS * DIM];
__device__ __align__(16) __half g_Xl[MROWS * DIM];
__device__ __align__(16) __half g_Ch[MROWS * DIM];
__device__ __align__(16) __half g_Cl[MROWS * DIM];
#define WOFF_Q 0
#define WOFF_K (1 * DIM * DIM)
#define WOFF_V (2 * DIM * DIM)
#define WOFF_D (3 * DIM * DIM)
#define WOFF_O (4 * DIM * DIM)          // O kept separate (not in fused launch)
#define WT_TOTAL (4 * DIM * DIM + (NH * NL) * DIM)
__device__ __align__(16) __half g_Wth[WT_TOTAL];
__device__ __align__(16) __half g_Wtl[WT_TOTAL];
// note: fused-launch B rows are [0,3584): Q,K,V then D; O lives at WOFF_O... but
// WOFF_O overlaps D+... => put O FIRST? Simpler: D at rows 3072..3583, O appended.
// Layout above: Q rows 0-1023, K 1024-2047, V 2048-3071, D 3072-3583, O 3584-4607.
#undef WOFF_D
#undef WOFF_O
#undef WT_TOTAL
#define WOFF_D (3 * DIM * DIM)                     // rows 3072..3583
#define WOFF_O (3 * DIM * DIM + (NH * NL) * DIM)   // rows 3584..4607
#define WT_TOTAL (4 * DIM * DIM + (NH * NL) * DIM)

// =========================== HMMA GEMM core ================================
#define SROWB 80
#define TILEB (128 * SROWB)
#define STAGEB (4 * TILEB)
#define SM_AH(s) ((s) * STAGEB + 0)
#define SM_AL(s) ((s) * STAGEB + TILEB)
#define SM_BH(s) ((s) * STAGEB + 2 * TILEB)
#define SM_BL(s) ((s) * STAGEB + 3 * TILEB)
#define GEMM_SMEM (2 * STAGEB)
#define NIT (DIM / 32)

__device__ __forceinline__ uint32_t smem_u32(const void* p) {
    uint32_t a;
    asm("{ .reg .u64 t; cvta.to.shared.u64 t, %1; cvt.u32.u64 %0, t; }" : "=r"(a) : "l"(p));
    return a;
}
#define CPA(dst, src) \
    asm volatile("cp.async.cg.shared.global [%0], [%1], 16;" :: "r"(dst), "l"(src))
#define CP_COMMIT() asm volatile("cp.async.commit_group;")
#define CP_WAIT(n)  asm volatile("cp.async.wait_group %0;" :: "n"(n))
#define LDSM4(R, addr) \
    asm volatile("ldmatrix.sync.aligned.m8n8.x4.shared.b16 {%0,%1,%2,%3}, [%4];" \
        : "=r"((R)[0]), "=r"((R)[1]), "=r"((R)[2]), "=r"((R)[3]) : "r"(addr))
#define MMA16816(d, a, b0, b1) \
    asm volatile("mma.sync.aligned.m16n8k16.row.col.f32.f16.f16.f32 " \
        "{%0,%1,%2,%3}, {%4,%5,%6,%7}, {%8,%9}, {%0,%1,%2,%3};" \
        : "+f"((d)[0]), "+f"((d)[1]), "+f"((d)[2]), "+f"((d)[3]) \
        : "r"((a)[0]), "r"((a)[1]), "r"((a)[2]), "r"((a)[3]), "r"(b0), "r"(b1))

// mainloop shared by both GEMM kernels; leaves results in acc
__device__ __forceinline__ void hgemm_main(
    const __half* Ah, const __half* Al, const __half* Bh, const __half* Bl,
    int bm, int bn, uint32_t sb, char* smem, int tid, float acc[2][8][4])
{
    const int lane = tid & 31, wid = tid >> 5;
    const int wm = wid & 3, wn = wid >> 2;
    const int lr0 = tid >> 2;
    const size_t aoff0 = ((size_t)(bm + lr0) << 10) + (size_t)(tid & 3) * 8;
    const size_t aoff1 = aoff0 + ((size_t)64 << 10);
    const size_t boff0 = ((size_t)(bn + lr0) << 10) + (size_t)(tid & 3) * 8;
    const size_t boff1 = boff0 + ((size_t)64 << 10);
    const uint32_t d0 = (uint32_t)lr0 * SROWB + (tid & 3) * 16;
    const uint32_t d1 = d0 + 64 * SROWB;

    CPA(sb + SM_AH(0) + d0, Ah + aoff0); CPA(sb + SM_AH(0) + d1, Ah + aoff1);
    CPA(sb + SM_AL(0) + d0, Al + aoff0); CPA(sb + SM_AL(0) + d1, Al + aoff1);
    CPA(sb + SM_BH(0) + d0, Bh + boff0); CPA(sb + SM_BH(0) + d1, Bh + boff1);
    CPA(sb + SM_BL(0) + d0, Bl + boff0); CPA(sb + SM_BL(0) + d1, Bl + boff1);
    CP_COMMIT();

#pragma unroll
    for (int i = 0; i < 2; i++)
#pragma unroll
        for (int j = 0; j < 8; j++)
#pragma unroll
            for (int k = 0; k < 4; k++) acc[i][j][k] = 0.f;

    const uint32_t aBase = (uint32_t)(wm * 32 + (lane & 15)) * SROWB + (lane >> 4) * 16;
    const uint32_t bBase = (uint32_t)(wn * 64 + ((lane >> 4) & 1) * 8 + (lane & 7)) * SROWB
                           + ((lane >> 3) & 1) * 16;

    for (int it = 0; it < NIT; it++) {
        const int p = it & 1;
        if (it + 1 < NIT) {
            const int np = p ^ 1;
            const int kb = (it + 1) * 32;
            CPA(sb + SM_AH(np) + d0, Ah + aoff0 + kb); CPA(sb + SM_AH(np) + d1, Ah + aoff1 + kb);
            CPA(sb + SM_AL(np) + d0, Al + aoff0 + kb); CPA(sb + SM_AL(np) + d1, Al + aoff1 + kb);
            CPA(sb + SM_BH(np) + d0, Bh + boff0 + kb); CPA(sb + SM_BH(np) + d1, Bh + boff1 + kb);
            CPA(sb + SM_BL(np) + d0, Bl + boff0 + kb); CPA(sb + SM_BL(np) + d1, Bl + boff1 + kb);
            CP_COMMIT();
            CP_WAIT(1);
        } else {
            CP_WAIT(0);
        }
        __syncthreads();

        const uint32_t sAH = sb + SM_AH(p) + aBase, sAL = sb + SM_AL(p) + aBase;
        const uint32_t sBH = sb + SM_BH(p) + bBase, sBL = sb + SM_BL(p) + bBase;
#pragma unroll
        for (int ks = 0; ks < 2; ks++) {
            const uint32_t ko = ks * 32;
            uint32_t ah[2][4], al[2][4];
            LDSM4(ah[0], sAH + ko);
            LDSM4(ah[1], sAH + ko + 16 * SROWB);
            LDSM4(al[0], sAL + ko);
            LDSM4(al[1], sAL + ko + 16 * SROWB);
#pragma unroll
            for (int q = 0; q < 4; q++) {
                uint32_t bh[4], bl[4];
                LDSM4(bh, sBH + ko + q * 16 * SROWB);
                LDSM4(bl, sBL + ko + q * 16 * SROWB);
#pragma unroll
                for (int mt = 0; mt < 2; mt++) {
                    MMA16816(acc[mt][2 * q + 0], ah[mt], bh[0], bh[1]);
                    MMA16816(acc[mt][2 * q + 0], ah[mt], bl[0], bl[1]);
                    MMA16816(acc[mt][2 * q + 0], al[mt], bh[0], bh[1]);
                    MMA16816(acc[mt][2 * q + 1], ah[mt], bh[2], bh[3]);
                    MMA16816(acc[mt][2 * q + 1], ah[mt], bl[2], bl[3]);
                    MMA16816(acc[mt][2 * q + 1], al[mt], bh[2], bh[3]);
                }
            }
        }
        __syncthreads();
    }
}

// ---- fused Q/K/V/D GEMM: B rows [0,3584) of concatenated weights ----
__global__ __launch_bounds__(256, 2) void hgemm_qkvd(
    const __half* __restrict__ Ah, const __half* __restrict__ Al,
    const __half* __restrict__ Bh, const __half* __restrict__ Bl,
    const float* __restrict__ bq, const float* __restrict__ bk,
    const float* __restrict__ bv, const float* __restrict__ bd,
    float* __restrict__ outQ, float* __restrict__ outK,
    float* __restrict__ outV, float* __restrict__ outD)
{
    extern __shared__ __align__(16) char smem[];
    const uint32_t sb = smem_u32(smem);
    const int tid = threadIdx.x, wid = tid >> 5, lane = tid & 31;
    const int bn = blockIdx.x * 128, bm = blockIdx.y * 128;
    float acc[2][8][4];
    hgemm_main(Ah, Al, Bh, Bl, bm, bn, sb, smem, tid, acc);

    const int seg = bn >> 10;              // 0..3
    const int cl = bn & 1023;              // local col base of segment
    const float* bias = seg == 0 ? bq : seg == 1 ? bk : seg == 2 ? bv : bd;
    const float scale = seg == 0 ? 0.125f : 1.f;
    const int wm = wid & 3, wn = wid >> 2;
    const int r0 = bm + wm * 32 + (lane >> 2);
    const int c0 = cl + wn * 64 + (lane & 3) * 2;
#pragma unroll
    for (int mt = 0; mt < 2; mt++) {
#pragma unroll
        for (int hf = 0; hf < 2; hf++) {
            const int r = r0 + mt * 16 + hf * 8;
            const int bb = r >> 12, ss = r & (SEQN - 1);
#pragma unroll
            for (int nt = 0; nt < 8; nt++) {
                const int col = c0 + nt * 8;
                const float2 bv2 = *(const float2*)(bias + col);
                float vx = (acc[mt][nt][hf * 2 + 0] + bv2.x) * scale;
                float vy = (acc[mt][nt][hf * 2 + 1] + bv2.y) * scale;
                float* op;
                size_t o;
                if (seg == 0) {
                    op = outQ;
                    o = ((size_t)(bb * NH + (col >> 6)) * SEQN + ss) * DHD + (col & 63);
                } else if (seg == 1) { op = outK; o = (size_t)r * DIM + col; }
                else if (seg == 2)   { op = outV; o = (size_t)r * DIM + col; }
                else                 { op = outD; o = (size_t)r * (NH * NL) + col; }
                *(float2*)(op + o) = make_float2(vx, vy);
            }
        }
    }
}

// ---- output GEMM: out = C @ Wo + bo, permuted to (s,b,DIM) ----
__global__ __launch_bounds__(256, 2) void hgemm_o(
    const __half* __restrict__ Ah, const __half* __restrict__ Al,
    const __half* __restrict__ Bh, const __half* __restrict__ Bl,
    const float* __restrict__ bias, float* __restrict__ out)
{
    extern __shared__ __align__(16) char smem[];
    const uint32_t sb = smem_u32(smem);
    const int tid = threadIdx.x, wid = tid >> 5, lane = tid & 31;
    const int bn = blockIdx.x * 128, bm = blockIdx.y * 128;
    float acc[2][8][4];
    hgemm_main(Ah, Al, Bh, Bl, bm, bn, sb, smem, tid, acc);

    const int wm = wid & 3, wn = wid >> 2;
    const int r0 = bm + wm * 32 + (lane >> 2);
    const int c0 = bn + wn * 64 + (lane & 3) * 2;
#pragma unroll
    for (int mt = 0; mt < 2; mt++) {
#pragma unroll
        for (int hf = 0; hf < 2; hf++) {
            const int r = r0 + mt * 16 + hf * 8;
            const int bb = r >> 12, ss = r & (SEQN - 1);
#pragma unroll
            for (int nt = 0; nt < 8; nt++) {
                const int col = c0 + nt * 8;
                const float2 bv2 = *(const float2*)(bias + col);
                float vx = acc[mt][nt][hf * 2 + 0] + bv2.x;
                float vy = acc[mt][nt][hf * 2 + 1] + bv2.y;
                *(float2*)(out + ((size_t)ss * BATCH + bb) * DIM + col) = make_float2(vx, vy);
            }
        }
    }
}

// ---- fp32 -> fp16 hi/lo split with (s,b)->(b,s) permute ----
__global__ __launch_bounds__(256) void split_perm_kernel(
    const float* __restrict__ X, __half* __restrict__ H, __half* __restrict__ L)
{
    int i = blockIdx.x * 256 + threadIdx.x;
    int r = i >> 8, k4 = i & 255;
    int b = r >> 12, s = r & (SEQN - 1);
    float4 v = *((const float4*)X + ((size_t)s * BATCH + b) * 256 + k4);
    __half h0 = __float2half_rn(v.x), h1 = __float2half_rn(v.y);
    __half h2 = __float2half_rn(v.z), h3 = __float2half_rn(v.w);
    __half2* Hp = (__half2*)(H + (size_t)i * 4);
    __half2* Lp = (__half2*)(L + (size_t)i * 4);
    Hp[0] = __halves2half2(h0, h1); Hp[1] = __halves2half2(h2, h3);
    Lp[0] = __halves2half2(__float2half_rn(v.x - __half2float(h0)),
                           __float2half_rn(v.y - __half2float(h1)));
    Lp[1] = __halves2half2(__float2half_rn(v.z - __half2float(h2)),
                           __float2half_rn(v.w - __half2float(h3)));
}

// ---- weight transpose + split ----
__global__ void wsplit_kernel(const float* __restrict__ W,
                              __half* __restrict__ Th, __half* __restrict__ Tl, int N)
{
    __shared__ float t[32][33];
    int n0 = blockIdx.x * 32, k0 = blockIdx.y * 32;
    int x = threadIdx.x, y = threadIdx.y;
#pragma unroll
    for (int i = 0; i < 32; i += 8)
        t[y + i][x] = W[(size_t)(k0 + y + i) * N + n0 + x];
    __syncthreads();
#pragma unroll
    for (int i = 0; i < 32; i += 8) {
        float v = t[x][y + i];
        __half h = __float2half_rn(v);
        size_t o = (size_t)(n0 + y + i) * DIM + k0 + x;
        Th[o] = h;
        Tl[o] = __float2half_rn(v - __half2float(h));
    }
}

// ---- LayerNorm over DIM, scatter head-split; y=0: K, y=1: V ----
__global__ __launch_bounds__(256) void ln_split2_kernel(
    const float* __restrict__ XK, const float* __restrict__ XV,
    const float* __restrict__ gamma, const float* __restrict__ beta,
    float* __restrict__ outK, float* __restrict__ outV)
{
    __shared__ float shs[8], shq[8];
    int r = blockIdx.x, tid = threadIdx.x;
    const float* X = blockIdx.y ? XV : XK;
    float* out = blockIdx.y ? outV : outK;
    const float4 v = ((const float4*)(X + (size_t)r * DIM))[tid];
    float s = v.x + v.y + v.z + v.w;
    float q = v.x*v.x + v.y*v.y + v.z*v.z + v.w*v.w;
    int lane = tid & 31, wid = tid >> 5;
#pragma unroll
    for (int o = 16; o; o >>= 1) {
        s += __shfl_xor_sync(~0u, s, o); q += __shfl_xor_sync(~0u, q, o);
    }
    if (lane == 0) { shs[wid] = s; shq[wid] = q; }
    __syncthreads();
    if (tid == 0) {
        float ts = 0, tq = 0;
        for (int i = 0; i < 8; i++) { ts += shs[i]; tq += shq[i]; }
        shs[0] = ts; shq[0] = tq;
    }
    __syncthreads();
    float mean = shs[0] * (1.f / DIM);
    float rstd = rsqrtf(shq[0] * (1.f / DIM) - mean * mean + 1e-5f);
    int c = tid * 4;
    float4 g4 = ((const float4*)gamma)[tid], b4 = ((const float4*)beta)[tid];
    float4 o;
    o.x = (v.x - mean) * rstd * g4.x + b4.x;
    o.y = (v.y - mean) * rstd * g4.y + b4.y;
    o.z = (v.z - mean) * rstd * g4.z + b4.z;
    o.w = (v.w - mean) * rstd * g4.w + b4.w;
    int b = r >> 12, sq = r & (SEQN - 1);
    *(float4*)(out + ((size_t)(b * NH + (c >> 6)) * SEQN + sq) * DHD + (c & 63)) = o;
}

// ---- transpose (b,s,512) -> (b,512,s) ----
__global__ void transpose_kernel(const float* __restrict__ D, float* __restrict__ P)
{
    __shared__ float t[32][33];
    int b = blockIdx.z, c0 = blockIdx.x * 32, s0 = blockIdx.y * 32;
    int x = threadIdx.x, y = threadIdx.y;
    const float* Db = D + (size_t)b * SEQN * (NH * NL);
    float* Pb = P + (size_t)b * (NH * NL) * SEQN;
#pragma unroll
    for (int i = 0; i < 32; i += 8)
        t[y + i][x] = Db[(size_t)(s0 + y + i) * (NH * NL) + c0 + x];
    __syncthreads();
#pragma unroll
    for (int i = 0; i < 32; i += 8)
        Pb[(size_t)(c0 + y + i) * SEQN + s0 + x] = t[x][y + i];
}

// ---- row softmax over 4096 ----
__global__ __launch_bounds__(256) void softmax_rows_kernel(float* __restrict__ P)
{
    __shared__ float sh[8];
    size_t base = (size_t)blockIdx.x * SEQN;
    int tid = threadIdx.x, lane = tid & 31, wid = tid >> 5;
    float v[16], m = -1e30f;
#pragma unroll
    for (int i = 0; i < 16; i++) { v[i] = P[base + tid + i * 256]; m = fmaxf(m, v[i]); }
#pragma unroll
    for (int o = 16; o; o >>= 1) m = fmaxf(m, __shfl_xor_sync(~0u, m, o));
    if (lane == 0) sh[wid] = m;
    __syncthreads();
    if (tid == 0) { float t = sh[0]; for (int i = 1; i < 8; i++) t = fmaxf(t, sh[i]); sh[0] = t; }
    __syncthreads();
    float M = sh[0];
    __syncthreads();
    float s = 0.f;
#pragma unroll
    for (int i = 0; i < 16; i++) { v[i] = __expf(v[i] - M); s += v[i]; }
#pragma unroll
    for (int o = 16; o; o >>= 1) s += __shfl_xor_sync(~0u, s, o);
    if (lane == 0) sh[wid] = s;
    __syncthreads();
    if (tid == 0) { float t = 0; for (int i = 0; i < 8; i++) t += sh[i]; sh[0] = t; }
    __syncthreads();
    float inv = 1.f / sh[0];
#pragma unroll
    for (int i = 0; i < 16; i++) P[base + tid + i * 256] = v[i] * inv;
}

// ---- Kc/Vc partials (split-K over s) ----
__global__ __launch_bounds__(256) void compress_partial_kernel(
    const float* __restrict__ P, const float* __restrict__ K,
    const float* __restrict__ V, float* __restrict__ partK, float* __restrict__ partV)
{
    __shared__ float Ps[NL][33];
    __shared__ float Ks[32][DHD];
    __shared__ float Vs[32][DHD];
    int bh = blockIdx.x, sp = blockIdx.y;
    int b = bh >> 4, h = bh & 15;
    int tid = threadIdx.x;
    int l = tid >> 3, qd = (tid & 7) * 8;
    float accK[8] = {}, accV[8] = {};
    const float* Pb = P + (size_t)(b * (NH * NL) + h * NL) * SEQN;
    const float* Kb = K + (size_t)bh * SEQN * DHD;
    const float* Vb = V + (size_t)bh * SEQN * DHD;
    for (int sc = 0; sc < SEQN / NSPLIT; sc += 32) {
        int s0 = sp * (SEQN / NSPLIT) + sc;
        {
            int pl = tid >> 3, ps = (tid & 7) * 4;
            float4 p4 = *(const float4*)(Pb + (size_t)pl * SEQN + s0 + ps);
            Ps[pl][ps] = p4.x; Ps[pl][ps+1] = p4.y; Ps[pl][ps+2] = p4.z; Ps[pl][ps+3] = p4.w;
        }
        {
            int ks = tid >> 3, kd = (tid & 7) * 8;
            const float* kp = Kb + (size_t)(s0 + ks) * DHD + kd;
            *(float4*)&Ks[ks][kd] = *(const float4*)kp;
            *(float4*)&Ks[ks][kd+4] = *(const float4*)(kp + 4);
            const float* vp = Vb + (size_t)(s0 + ks) * DHD + kd;
            *(float4*)&Vs[ks][kd] = *(const float4*)vp;
            *(float4*)&Vs[ks][kd+4] = *(const float4*)(vp + 4);
        }
        __syncthreads();
#pragma unroll 8
        for (int si = 0; si < 32; si++) {
            float p = Ps[l][si];
            float kf[8], vf[8];
            *(float4*)kf = *(float4*)&Ks[si][qd]; *(float4*)(kf+4) = *(float4*)&Ks[si][qd+4];
            *(float4*)vf = *(float4*)&Vs[si][qd]; *(float4*)(vf+4) = *(float4*)&Vs[si][qd+4];
#pragma unroll
            for (int j = 0; j < 8; j++) { accK[j] += p * kf[j]; accV[j] += p * vf[j]; }
        }
        __syncthreads();
    }
    size_t ob = (size_t)sp * CSIZE + ((size_t)bh * NL + l) * DHD + qd;
    *(float4*)(partK + ob)   = make_float4(accK[0], accK[1], accK[2], accK[3]);
    *(float4*)(partK + ob+4) = make_float4(accK[4], accK[5], accK[6], accK[7]);
    *(float4*)(partV + ob)   = make_float4(accV[0], accV[1], accV[2], accV[3]);
    *(float4*)(partV + ob+4) = make_float4(accV[4], accV[5], accV[6], accV[7]);
}

// ---- reduce partials + LN for Kc/Vc ----
__global__ __launch_bounds__(256) void compress_ln_kernel(
    const float* __restrict__ partK, const float* __restrict__ partV,
    const float* __restrict__ gamma, const float* __restrict__ beta,
    float* __restrict__ outK, float* __restrict__ outV)
{
    __shared__ float shs[8], shq[8];
    int bl = blockIdx.x, b = bl >> 5, l = bl & 31;
    const float* part = blockIdx.y ? partV : partK;
    float* out = blockIdx.y ? outV : outK;
    int tid = threadIdx.x, c = tid * 4;
    size_t base = ((size_t)(b * NH + (c >> 6)) * NL + l) * DHD + (c & 63);
    float4 acc = make_float4(0, 0, 0, 0);
#pragma unroll
    for (int sp = 0; sp < NSPLIT; sp++) {
        float4 p = *(const float4*)(part + (size_t)sp * CSIZE + base);
        acc.x += p.x; acc.y += p.y; acc.z += p.z; acc.w += p.w;
    }
    float s = acc.x + acc.y + acc.z + acc.w;
    float q = acc.x*acc.x + acc.y*acc.y + acc.z*acc.z + acc.w*acc.w;
    int lane = tid & 31, wid = tid >> 5;
#pragma unroll
    for (int o = 16; o; o >>= 1) {
        s += __shfl_xor_sync(~0u, s, o); q += __shfl_xor_sync(~0u, q, o);
    }
    if (lane == 0) { shs[wid] = s; shq[wid] = q; }
    __syncthreads();
    if (tid == 0) {
        float ts = 0, tq = 0;
        for (int i = 0; i < 8; i++) { ts += shs[i]; tq += shq[i]; }
        shs[0] = ts; shq[0] = tq;
    }
    __syncthreads();
    float mean = shs[0] * (1.f / DIM);
    float rstd = rsqrtf(shq[0] * (1.f / DIM) - mean * mean + 1e-5f);
    float4 g4 = ((const float4*)gamma)[tid], b4 = ((const float4*)beta)[tid];
    float4 o;
    o.x = (acc.x - mean) * rstd * g4.x + b4.x;
    o.y = (acc.y - mean) * rstd * g4.y + b4.y;
    o.z = (acc.z - mean) * rstd * g4.z + b4.z;
    o.w = (acc.w - mean) * rstd * g4.w + b4.w;
    *(float4*)(out + base) = o;
}

// ---- fused attention, 8 groups (64 queries) per block, fp16 hi/lo out ----
#define AT_KC 0
#define AT_VC (AT_KC + NL * (DHD + 1))
#define AT_KW (AT_VC + NL * (DHD + 1))
#define AT_VW (AT_KW + 72 * (DHD + 1))
#define AT_Q  (AT_VW + 72 * (DHD + 1))
#define AT_PR (AT_Q + 64 * (DHD + 1))
#define ATTN_FLOATS (AT_PR + 8 * 48)
#define ATTN_SMEM (ATTN_FLOATS * 4)

__global__ __launch_bounds__(256) void attn_kernel(
    const float* __restrict__ Q, const float* __restrict__ K,
    const float* __restrict__ V, const float* __restrict__ Kc,
    const float* __restrict__ Vc, __half* __restrict__ Ch, __half* __restrict__ Cl)
{
    extern __shared__ float sf[];
    int gblk = blockIdx.x, h = blockIdx.y, b = blockIdx.z;
    int bh = b * NH + h, tid = threadIdx.x;
    const int base = gblk * 64;

    {   // Kc/Vc tiles 32x64
        int l = tid >> 3, d0 = (tid & 7) * 8;
        size_t src = ((size_t)bh * NL + l) * DHD + d0;
        float tk[8], tv[8];
        *(float4*)tk = *(const float4*)(Kc + src); *(float4*)(tk+4) = *(const float4*)(Kc + src + 4);
        *(float4*)tv = *(const float4*)(Vc + src); *(float4*)(tv+4) = *(const float4*)(Vc + src + 4);
#pragma unroll
        for (int i = 0; i < 8; i++) {
            sf[AT_KC + l * (DHD + 1) + d0 + i] = tk[i];
            sf[AT_VC + l * (DHD + 1) + d0 + i] = tv[i];
        }
    }
    // window 72 rows, seq = base - 4 + row
    for (int idx = tid; idx < 72 * 16; idx += 256) {
        int row = idx >> 4, d = (idx & 15) * 4;
        int sk = base - EE + row;
        float4 kv = make_float4(0,0,0,0), vv = make_float4(0,0,0,0);
        if (sk >= 0 && sk < SEQN) {
            size_t src = ((size_t)bh * SEQN + sk) * DHD + d;
            kv = *(const float4*)(K + src); vv = *(const float4*)(V + src);
        }
        float* kwp = sf + AT_KW + row * (DHD + 1) + d;
        float* vwp = sf + AT_VW + row * (DHD + 1) + d;
        kwp[0] = kv.x; kwp[1] = kv.y; kwp[2] = kv.z; kwp[3] = kv.w;
        vwp[0] = vv.x; vwp[1] = vv.y; vwp[2] = vv.z; vwp[3] = vv.w;
    }
    // Q 64 rows
    for (int idx = tid; idx < 64 * 16; idx += 256) {
        int row = idx >> 4, d = (idx & 15) * 4;
        float4 qv = *(const float4*)(Q + ((size_t)bh * SEQN + base + row) * DHD + d);
        float* qp = sf + AT_Q + row * (DHD + 1) + d;
        qp[0] = qv.x; qp[1] = qv.y; qp[2] = qv.z; qp[3] = qv.w;
    }
    __syncthreads();

    const int warp = tid >> 5, lane = tid & 31;
    const int k = lane & 15;
    const int wrow = warp * 8 + k;                 // window row for this lane
    const int skg = base + warp * 8 + k - EE;      // global window seq
    const bool kvalid = (lane < BAND) && (skg >= 0) && (skg < SEQN);
    float* probs = sf + AT_PR + warp * 48;

#pragma unroll 1
    for (int q = 0; q < 8; q++) {
        const float* qrow = sf + AT_Q + (warp * 8 + q) * (DHD + 1);
        float sc = 0.f, sw = 0.f;
#pragma unroll
        for (int d = 0; d < DHD; d++) {
            float qd = qrow[d];
            sc += qd * sf[AT_KC + lane * (DHD + 1) + d];
            sw += qd * sf[AT_KW + wrow * (DHD + 1) + d];
        }
        float m = fmaxf(sc, kvalid ? sw : -1e30f);
#pragma unroll
        for (int o = 16; o; o >>= 1) m = fmaxf(m, __shfl_xor_sync(~0u, m, o));
        float e0 = __expf(sc - m);
        float e1 = kvalid ? __expf(sw - m) : 0.f;
        float t = e0 + e1;
#pragma unroll
        for (int o = 16; o; o >>= 1) t += __shfl_xor_sync(~0u, t, o);
        float inv = 1.f / t;
        probs[lane] = e0 * inv;
        if (lane < BAND) probs[NL + lane] = e1 * inv;
        __syncwarp();

        float a0 = 0.f, a1 = 0.f;
#pragma unroll
        for (int j = 0; j < NL; j++) {
            float p = probs[j];
            a0 += p * sf[AT_VC + j * (DHD + 1) + lane];
            a1 += p * sf[AT_VC + j * (DHD + 1) + lane + 32];
        }
#pragma unroll
        for (int kk = 0; kk < BAND; kk++) {
            float p = probs[NL + kk];
            a0 += p * sf[AT_VW + (warp * 8 + kk) * (DHD + 1) + lane];
            a1 += p * sf[AT_VW + (warp * 8 + kk) * (DHD + 1) + lane + 32];
        }
        __syncwarp();

        size_t off = ((size_t)(b * SEQN) + base + warp * 8 + q) * DIM + h * DHD;
        __half h0 = __float2half_rn(a0), h1 = __float2half_rn(a1);
        Ch[off + lane] = h0;
        Ch[off + 32 + lane] = h1;
        Cl[off + lane] = __float2half_rn(a0 - __half2float(h0));
        Cl[off + 32 + lane] = __float2half_rn(a1 - __half2float(h1));
    }
}

// ===========================================================================
extern "C" void kernel_launch(void* const* d_in, const int* in_sizes, int n_in,
                              void* d_out, int out_size)
{
    (void)in_sizes; (void)n_in; (void)out_size;
    const float* query = (const float*)d_in[0];
    const float* Wq = (const float*)d_in[1];  const float* bq = (const float*)d_in[2];
    const float* Wk = (const float*)d_in[3];  const float* bk = (const float*)d_in[4];
    const float* Wv = (const float*)d_in[5];  const float* bv = (const float*)d_in[6];
    const float* Wo = (const float*)d_in[7];  const float* bo = (const float*)d_in[8];
    const float* gl = (const float*)d_in[9];  const float* bl = (const float*)d_in[10];
    const float* gs = (const float*)d_in[11]; const float* bs = (const float*)d_in[12];
    const float* Wd = (const float*)d_in[13]; const float* bd = (const float*)d_in[14];
    float* out = (float*)d_out;

    float *pQ,*pK,*pV,*pTmp,*pTv,*pD,*pP,*pKcP,*pVcP,*pKc,*pVc;
    __half *pXh,*pXl,*pCh,*pCl,*pWth,*pWtl;
    cudaGetSymbolAddress((void**)&pQ, g_Q);
    cudaGetSymbolAddress((void**)&pK, g_K);
    cudaGetSymbolAddress((void**)&pV, g_V);
    cudaGetSymbolAddress((void**)&pTmp, g_tmp);
    cudaGetSymbolAddress((void**)&pTv, g_tv);
    cudaGetSymbolAddress((void**)&pD, g_D);
    cudaGetSymbolAddress((void**)&pP, g_P);
    cudaGetSymbolAddress((void**)&pKcP, g_KcP);
    cudaGetSymbolAddress((void**)&pVcP, g_VcP);
    cudaGetSymbolAddress((void**)&pKc, g_Kc);
    cudaGetSymbolAddress((void**)&pVc, g_Vc);
    cudaGetSymbolAddress((void**)&pXh, g_Xh);
    cudaGetSymbolAddress((void**)&pXl, g_Xl);
    cudaGetSymbolAddress((void**)&pCh, g_Ch);
    cudaGetSymbolAddress((void**)&pCl, g_Cl);
    cudaGetSymbolAddress((void**)&pWth, g_Wth);
    cudaGetSymbolAddress((void**)&pWtl, g_Wtl);

    cudaFuncSetAttribute(hgemm_qkvd, cudaFuncAttributeMaxDynamicSharedMemorySize, GEMM_SMEM);
    cudaFuncSetAttribute(hgemm_o, cudaFuncAttributeMaxDynamicSharedMemorySize, GEMM_SMEM);
    cudaFuncSetAttribute(attn_kernel, cudaFuncAttributeMaxDynamicSharedMemorySize, ATTN_SMEM);

    // operand prep
    split_perm_kernel<<<MROWS * DIM / 4 / 256, 256>>>(query, pXh, pXl);
    dim3 wt(DIM / 32, DIM / 32), wb(32, 8);
    wsplit_kernel<<<wt, wb>>>(Wq, pWth + WOFF_Q, pWtl + WOFF_Q, DIM);
    wsplit_kernel<<<wt, wb>>>(Wk, pWth + WOFF_K, pWtl + WOFF_K, DIM);
    wsplit_kernel<<<wt, wb>>>(Wv, pWth + WOFF_V, pWtl + WOFF_V, DIM);
    wsplit_kernel<<<dim3((NH * NL) / 32, DIM / 32), wb>>>(Wd, pWth + WOFF_D, pWtl + WOFF_D, NH * NL);
    wsplit_kernel<<<wt, wb>>>(Wo, pWth + WOFF_O, pWtl + WOFF_O, DIM);

    // fused Q/K/V/D projection GEMM
    hgemm_qkvd<<<dim3((3 * DIM + NH * NL) / 128, MROWS / 128), 256, GEMM_SMEM>>>(
        pXh, pXl, pWth, pWtl, bq, bk, bv, bd, pQ, pTmp, pTv, pD);

    ln_split2_kernel<<<dim3(MROWS, 2), 256>>>(pTmp, pTv, gl, bl, pK, pV);

    transpose_kernel<<<dim3((NH * NL) / 32, SEQN / 32, BATCH), dim3(32, 8)>>>(pD, pP);
    softmax_rows_kernel<<<BATCH * NH * NL, 256>>>(pP);
    compress_partial_kernel<<<dim3(BATCH * NH, NSPLIT), 256>>>(pP, pK, pV, pKcP, pVcP);
    compress_ln_kernel<<<dim3(BATCH * NL, 2), 256>>>(pKcP, pVcP, gs, bs, pKc, pVc);

    attn_kernel<<<dim3(NG / 8, NH, BATCH), 256, ATTN_SMEM>>>(pQ, pK, pV, pKc, pVc, pCh, pCl);

    hgemm_o<<<dim3(DIM / 128, MROWS / 128), 256, GEMM_SMEM>>>(
        pCh, pCl, pWth + WOFF_O, pWtl + WOFF_O, bo, out);
}

// round 8
// speedup vs baseline: 2.8340x; 1.2017x over previous
#include <cuda_runtime.h>
#include <cuda_fp16.h>
#include <math.h>
#include <stdint.h>

#define SEQN  4096
#define BATCH 4
#define DIM   1024
#define NH    16
#define DHD   64
#define NL    32
#define WW    8
#define EE    4
#define BAND  16
#define NG    (SEQN / WW)
#define MROWS (BATCH * SEQN)
#define NSPLIT 8
#define CSIZE (BATCH * NH * NL * DHD)

__device__ float g_Q  [BATCH * NH * SEQN * DHD];
__device__ float g_K  [BATCH * NH * SEQN * DHD];
__device__ float g_V  [BATCH * NH * SEQN * DHD];
__device__ float g_tmp[BATCH * SEQN * DIM];
__device__ float g_tv [BATCH * SEQN * DIM];
__device__ float g_D  [BATCH * SEQN * NH * NL];
__device__ float g_P  [BATCH * NH * NL * SEQN];
__device__ float g_KcP[NSPLIT * CSIZE];
__device__ float g_VcP[NSPLIT * CSIZE];
__device__ float g_Kc [CSIZE];
__device__ float g_Vc [CSIZE];

__device__ __align__(16) __half g_Xh[MROWS * DIM];
__device__ __align__(16) __half g_Xl[MROWS * DIM];
__device__ __align__(16) __half g_Ch[MROWS * DIM];
__device__ __align__(16) __half g_Cl[MROWS * DIM];
// weight rows: Q 0-1023, K 1024-2047, V 2048-3071, D 3072-3583, O 3584-4607
#define WOFF_Q 0
#define WOFF_K (1 * DIM * DIM)
#define WOFF_V (2 * DIM * DIM)
#define WOFF_D (3 * DIM * DIM)
#define WOFF_O (3 * DIM * DIM + (NH * NL) * DIM)
#define WT_TOTAL (4 * DIM * DIM + (NH * NL) * DIM)
__device__ __align__(16) __half g_Wth[WT_TOTAL];
__device__ __align__(16) __half g_Wtl[WT_TOTAL];

// =========================== HMMA GEMM core ================================
#define SROWB 80
#define TILEB (128 * SROWB)
#define NIT (DIM / 32)

__device__ __forceinline__ uint32_t smem_u32(const void* p) {
    uint32_t a;
    asm("{ .reg .u64 t; cvta.to.shared.u64 t, %1; cvt.u32.u64 %0, t; }" : "=r"(a) : "l"(p));
    return a;
}
#define CPA(dst, src) \
    asm volatile("cp.async.cg.shared.global [%0], [%1], 16;" :: "r"(dst), "l"(src))
#define CP_COMMIT() asm volatile("cp.async.commit_group;")
#define CP_WAIT(n)  asm volatile("cp.async.wait_group %0;" :: "n"(n))
#define LDSM4(R, addr) \
    asm volatile("ldmatrix.sync.aligned.m8n8.x4.shared.b16 {%0,%1,%2,%3}, [%4];" \
        : "=r"((R)[0]), "=r"((R)[1]), "=r"((R)[2]), "=r"((R)[3]) : "r"(addr))
#define MMA16816(d, a, b0, b1) \
    asm volatile("mma.sync.aligned.m16n8k16.row.col.f32.f16.f16.f32 " \
        "{%0,%1,%2,%3}, {%4,%5,%6,%7}, {%8,%9}, {%0,%1,%2,%3};" \
        : "+f"((d)[0]), "+f"((d)[1]), "+f"((d)[2]), "+f"((d)[3]) \
        : "r"((a)[0]), "r"((a)[1]), "r"((a)[2]), "r"((a)[3]), "r"(b0), "r"(b1))

// TERMS=3: Ah*Bh + Ah*Bl + Al*Bh.  TERMS=2: (Ah+Al)*Bh (no Bl stream at all).
template <int TERMS>
__device__ __forceinline__ void hgemm_main(
    const __half* Ah, const __half* Al, const __half* Bh, const __half* Bl,
    int bm, int bn, uint32_t sb, int tid, float acc[2][8][4])
{
    constexpr int NT = TERMS + 1;            // tiles per stage
    constexpr uint32_t STG = NT * TILEB;
    const uint32_t oAH = 0, oAL = TILEB, oBH = 2 * TILEB, oBL = 3 * TILEB;

    const int lane = tid & 31, wid = tid >> 5;
    const int wm = wid & 3, wn = wid >> 2;
    const int lr0 = tid >> 2;
    const size_t aoff0 = ((size_t)(bm + lr0) << 10) + (size_t)(tid & 3) * 8;
    const size_t aoff1 = aoff0 + ((size_t)64 << 10);
    const size_t boff0 = ((size_t)(bn + lr0) << 10) + (size_t)(tid & 3) * 8;
    const size_t boff1 = boff0 + ((size_t)64 << 10);
    const uint32_t d0 = (uint32_t)lr0 * SROWB + (tid & 3) * 16;
    const uint32_t d1 = d0 + 64 * SROWB;

    CPA(sb + oAH + d0, Ah + aoff0); CPA(sb + oAH + d1, Ah + aoff1);
    CPA(sb + oAL + d0, Al + aoff0); CPA(sb + oAL + d1, Al + aoff1);
    CPA(sb + oBH + d0, Bh + boff0); CPA(sb + oBH + d1, Bh + boff1);
    if (TERMS == 3) { CPA(sb + oBL + d0, Bl + boff0); CPA(sb + oBL + d1, Bl + boff1); }
    CP_COMMIT();

#pragma unroll
    for (int i = 0; i < 2; i++)
#pragma unroll
        for (int j = 0; j < 8; j++)
#pragma unroll
            for (int k = 0; k < 4; k++) acc[i][j][k] = 0.f;

    const uint32_t aBase = (uint32_t)(wm * 32 + (lane & 15)) * SROWB + (lane >> 4) * 16;
    const uint32_t bBase = (uint32_t)(wn * 64 + ((lane >> 4) & 1) * 8 + (lane & 7)) * SROWB
                           + ((lane >> 3) & 1) * 16;

    for (int it = 0; it < NIT; it++) {
        const uint32_t ps = (it & 1) * STG;
        if (it + 1 < NIT) {
            const uint32_t ns = ((it + 1) & 1) * STG;
            const int kb = (it + 1) * 32;
            CPA(sb + ns + oAH + d0, Ah + aoff0 + kb); CPA(sb + ns + oAH + d1, Ah + aoff1 + kb);
            CPA(sb + ns + oAL + d0, Al + aoff0 + kb); CPA(sb + ns + oAL + d1, Al + aoff1 + kb);
            CPA(sb + ns + oBH + d0, Bh + boff0 + kb); CPA(sb + ns + oBH + d1, Bh + boff1 + kb);
            if (TERMS == 3) {
                CPA(sb + ns + oBL + d0, Bl + boff0 + kb); CPA(sb + ns + oBL + d1, Bl + boff1 + kb);
            }
            CP_COMMIT();
            CP_WAIT(1);
        } else {
            CP_WAIT(0);
        }
        __syncthreads();

        const uint32_t sAH = sb + ps + oAH + aBase, sAL = sb + ps + oAL + aBase;
        const uint32_t sBH = sb + ps + oBH + bBase, sBL = sb + ps + oBL + bBase;
#pragma unroll
        for (int ks = 0; ks < 2; ks++) {
            const uint32_t ko = ks * 32;
            uint32_t ah[2][4], al[2][4];
            LDSM4(ah[0], sAH + ko);
            LDSM4(ah[1], sAH + ko + 16 * SROWB);
            LDSM4(al[0], sAL + ko);
            LDSM4(al[1], sAL + ko + 16 * SROWB);
#pragma unroll
            for (int q = 0; q < 4; q++) {
                uint32_t bh[4];
                LDSM4(bh, sBH + ko + q * 16 * SROWB);
                if (TERMS == 3) {
                    uint32_t bl[4];
                    LDSM4(bl, sBL + ko + q * 16 * SROWB);
#pragma unroll
                    for (int mt = 0; mt < 2; mt++) {
                        MMA16816(acc[mt][2 * q + 0], ah[mt], bh[0], bh[1]);
                        MMA16816(acc[mt][2 * q + 0], ah[mt], bl[0], bl[1]);
                        MMA16816(acc[mt][2 * q + 0], al[mt], bh[0], bh[1]);
                        MMA16816(acc[mt][2 * q + 1], ah[mt], bh[2], bh[3]);
                        MMA16816(acc[mt][2 * q + 1], ah[mt], bl[2], bl[3]);
                        MMA16816(acc[mt][2 * q + 1], al[mt], bh[2], bh[3]);
                    }
                } else {
#pragma unroll
                    for (int mt = 0; mt < 2; mt++) {
                        MMA16816(acc[mt][2 * q + 0], ah[mt], bh[0], bh[1]);
                        MMA16816(acc[mt][2 * q + 0], al[mt], bh[0], bh[1]);
                        MMA16816(acc[mt][2 * q + 1], ah[mt], bh[2], bh[3]);
                        MMA16816(acc[mt][2 * q + 1], al[mt], bh[2], bh[3]);
                    }
                }
            }
        }
        __syncthreads();
    }
}
#define GEMM_SMEM2 (2 * 3 * TILEB)
#define GEMM_SMEM3 (2 * 4 * TILEB)

// ---- fused Q/K/V/D GEMM (2-term) ----
__global__ __launch_bounds__(256, 2) void hgemm_qkvd(
    const __half* __restrict__ Ah, const __half* __restrict__ Al,
    const __half* __restrict__ Bh, const __half* __restrict__ Bl,
    const float* __restrict__ bq, const float* __restrict__ bk,
    const float* __restrict__ bv, const float* __restrict__ bd,
    float* __restrict__ outQ, float* __restrict__ outK,
    float* __restrict__ outV, float* __restrict__ outD)
{
    extern __shared__ __align__(16) char smem[];
    const uint32_t sb = smem_u32(smem);
    const int tid = threadIdx.x, wid = tid >> 5, lane = tid & 31;
    const int bn = blockIdx.x * 128, bm = blockIdx.y * 128;
    float acc[2][8][4];
    hgemm_main<2>(Ah, Al, Bh, Bl, bm, bn, sb, tid, acc);

    const int seg = bn >> 10;
    const int cl = bn & 1023;
    const float* bias = seg == 0 ? bq : seg == 1 ? bk : seg == 2 ? bv : bd;
    const float scale = seg == 0 ? 0.125f : 1.f;
    const int wm = wid & 3, wn = wid >> 2;
    const int r0 = bm + wm * 32 + (lane >> 2);
    const int c0 = cl + wn * 64 + (lane & 3) * 2;
#pragma unroll
    for (int mt = 0; mt < 2; mt++) {
#pragma unroll
        for (int hf = 0; hf < 2; hf++) {
            const int r = r0 + mt * 16 + hf * 8;
            const int bb = r >> 12, ss = r & (SEQN - 1);
#pragma unroll
            for (int nt = 0; nt < 8; nt++) {
                const int col = c0 + nt * 8;
                const float2 bv2 = *(const float2*)(bias + col);
                float vx = (acc[mt][nt][hf * 2 + 0] + bv2.x) * scale;
                float vy = (acc[mt][nt][hf * 2 + 1] + bv2.y) * scale;
                float* op; size_t o;
                if (seg == 0) {
                    op = outQ;
                    o = ((size_t)(bb * NH + (col >> 6)) * SEQN + ss) * DHD + (col & 63);
                } else if (seg == 1) { op = outK; o = (size_t)r * DIM + col; }
                else if (seg == 2)   { op = outV; o = (size_t)r * DIM + col; }
                else                 { op = outD; o = (size_t)r * (NH * NL) + col; }
                *(float2*)(op + o) = make_float2(vx, vy);
            }
        }
    }
}

// ---- output GEMM (3-term): out = C @ Wo + bo, (s,b,DIM) ----
__global__ __launch_bounds__(256, 2) void hgemm_o(
    const __half* __restrict__ Ah, const __half* __restrict__ Al,
    const __half* __restrict__ Bh, const __half* __restrict__ Bl,
    const float* __restrict__ bias, float* __restrict__ out)
{
    extern __shared__ __align__(16) char smem[];
    const uint32_t sb = smem_u32(smem);
    const int tid = threadIdx.x, wid = tid >> 5, lane = tid & 31;
    const int bn = blockIdx.x * 128, bm = blockIdx.y * 128;
    float acc[2][8][4];
    hgemm_main<3>(Ah, Al, Bh, Bl, bm, bn, sb, tid, acc);

    const int wm = wid & 3, wn = wid >> 2;
    const int r0 = bm + wm * 32 + (lane >> 2);
    const int c0 = bn + wn * 64 + (lane & 3) * 2;
#pragma unroll
    for (int mt = 0; mt < 2; mt++) {
#pragma unroll
        for (int hf = 0; hf < 2; hf++) {
            const int r = r0 + mt * 16 + hf * 8;
            const int bb = r >> 12, ss = r & (SEQN - 1);
#pragma unroll
            for (int nt = 0; nt < 8; nt++) {
                const int col = c0 + nt * 8;
                const float2 bv2 = *(const float2*)(bias + col);
                *(float2*)(out + ((size_t)ss * BATCH + bb) * DIM + col) =
                    make_float2(acc[mt][nt][hf * 2 + 0] + bv2.x,
                                acc[mt][nt][hf * 2 + 1] + bv2.y);
            }
        }
    }
}

// ---- fp32 -> fp16 hi/lo split with (s,b)->(b,s) permute ----
__global__ __launch_bounds__(256) void split_perm_kernel(
    const float* __restrict__ X, __half* __restrict__ H, __half* __restrict__ L)
{
    int i = blockIdx.x * 256 + threadIdx.x;
    int r = i >> 8, k4 = i & 255;
    int b = r >> 12, s = r & (SEQN - 1);
    float4 v = *((const float4*)X + ((size_t)s * BATCH + b) * 256 + k4);
    __half h0 = __float2half_rn(v.x), h1 = __float2half_rn(v.y);
    __half h2 = __float2half_rn(v.z), h3 = __float2half_rn(v.w);
    __half2* Hp = (__half2*)(H + (size_t)i * 4);
    __half2* Lp = (__half2*)(L + (size_t)i * 4);
    Hp[0] = __halves2half2(h0, h1); Hp[1] = __halves2half2(h2, h3);
    Lp[0] = __halves2half2(__float2half_rn(v.x - __half2float(h0)),
                           __float2half_rn(v.y - __half2float(h1)));
    Lp[1] = __halves2half2(__float2half_rn(v.z - __half2float(h2)),
                           __float2half_rn(v.w - __half2float(h3)));
}

// ---- all 5 weight transposes + splits in one launch (z = segment) ----
__global__ void wsplit_all_kernel(
    const float* __restrict__ Wq, const float* __restrict__ Wk,
    const float* __restrict__ Wv, const float* __restrict__ Wd,
    const float* __restrict__ Wo, __half* __restrict__ Th, __half* __restrict__ Tl)
{
    __shared__ float t[32][33];
    int z = blockIdx.z;
    int N = (z == 3) ? (NH * NL) : DIM;
    if (blockIdx.x * 32 >= N) return;
    const float* W = z == 0 ? Wq : z == 1 ? Wk : z == 2 ? Wv : z == 3 ? Wd : Wo;
    size_t woff = z <= 3 ? (size_t)z * DIM * DIM : (size_t)WOFF_O;
    int n0 = blockIdx.x * 32, k0 = blockIdx.y * 32;
    int x = threadIdx.x, y = threadIdx.y;
#pragma unroll
    for (int i = 0; i < 32; i += 8)
        t[y + i][x] = W[(size_t)(k0 + y + i) * N + n0 + x];
    __syncthreads();
#pragma unroll
    for (int i = 0; i < 32; i += 8) {
        float v = t[x][y + i];
        __half h = __float2half_rn(v);
        size_t o = woff + (size_t)(n0 + y + i) * DIM + k0 + x;
        Th[o] = h;
        Tl[o] = __float2half_rn(v - __half2float(h));
    }
}

// ---- LayerNorm over DIM, scatter head-split; y=0: K, y=1: V ----
__global__ __launch_bounds__(256) void ln_split2_kernel(
    const float* __restrict__ XK, const float* __restrict__ XV,
    const float* __restrict__ gamma, const float* __restrict__ beta,
    float* __restrict__ outK, float* __restrict__ outV)
{
    __shared__ float shs[8], shq[8];
    int r = blockIdx.x, tid = threadIdx.x;
    const float* X = blockIdx.y ? XV : XK;
    float* out = blockIdx.y ? outV : outK;
    const float4 v = ((const float4*)(X + (size_t)r * DIM))[tid];
    float s = v.x + v.y + v.z + v.w;
    float q = v.x*v.x + v.y*v.y + v.z*v.z + v.w*v.w;
    int lane = tid & 31, wid = tid >> 5;
#pragma unroll
    for (int o = 16; o; o >>= 1) {
        s += __shfl_xor_sync(~0u, s, o); q += __shfl_xor_sync(~0u, q, o);
    }
    if (lane == 0) { shs[wid] = s; shq[wid] = q; }
    __syncthreads();
    if (tid == 0) {
        float ts = 0, tq = 0;
        for (int i = 0; i < 8; i++) { ts += shs[i]; tq += shq[i]; }
        shs[0] = ts; shq[0] = tq;
    }
    __syncthreads();
    float mean = shs[0] * (1.f / DIM);
    float rstd = rsqrtf(shq[0] * (1.f / DIM) - mean * mean + 1e-5f);
    int c = tid * 4;
    float4 g4 = ((const float4*)gamma)[tid], b4 = ((const float4*)beta)[tid];
    float4 o;
    o.x = (v.x - mean) * rstd * g4.x + b4.x;
    o.y = (v.y - mean) * rstd * g4.y + b4.y;
    o.z = (v.z - mean) * rstd * g4.z + b4.z;
    o.w = (v.w - mean) * rstd * g4.w + b4.w;
    int b = r >> 12, sq = r & (SEQN - 1);
    *(float4*)(out + ((size_t)(b * NH + (c >> 6)) * SEQN + sq) * DHD + (c & 63)) = o;
}

// ---- transpose (b,s,512) -> (b,512,s) ----
__global__ void transpose_kernel(const float* __restrict__ D, float* __restrict__ P)
{
    __shared__ float t[32][33];
    int b = blockIdx.z, c0 = blockIdx.x * 32, s0 = blockIdx.y * 32;
    int x = threadIdx.x, y = threadIdx.y;
    const float* Db = D + (size_t)b * SEQN * (NH * NL);
    float* Pb = P + (size_t)b * (NH * NL) * SEQN;
#pragma unroll
    for (int i = 0; i < 32; i += 8)
        t[y + i][x] = Db[(size_t)(s0 + y + i) * (NH * NL) + c0 + x];
    __syncthreads();
#pragma unroll
    for (int i = 0; i < 32; i += 8)
        Pb[(size_t)(c0 + y + i) * SEQN + s0 + x] = t[x][y + i];
}

// ---- row softmax over 4096 ----
__global__ __launch_bounds__(256) void softmax_rows_kernel(float* __restrict__ P)
{
    __shared__ float sh[8];
    size_t base = (size_t)blockIdx.x * SEQN;
    int tid = threadIdx.x, lane = tid & 31, wid = tid >> 5;
    float v[16], m = -1e30f;
#pragma unroll
    for (int i = 0; i < 16; i++) { v[i] = P[base + tid + i * 256]; m = fmaxf(m, v[i]); }
#pragma unroll
    for (int o = 16; o; o >>= 1) m = fmaxf(m, __shfl_xor_sync(~0u, m, o));
    if (lane == 0) sh[wid] = m;
    __syncthreads();
    if (tid == 0) { float t = sh[0]; for (int i = 1; i < 8; i++) t = fmaxf(t, sh[i]); sh[0] = t; }
    __syncthreads();
    float M = sh[0];
    __syncthreads();
    float s = 0.f;
#pragma unroll
    for (int i = 0; i < 16; i++) { v[i] = __expf(v[i] - M); s += v[i]; }
#pragma unroll
    for (int o = 16; o; o >>= 1) s += __shfl_xor_sync(~0u, s, o);
    if (lane == 0) sh[wid] = s;
    __syncthreads();
    if (tid == 0) { float t = 0; for (int i = 0; i < 8; i++) t += sh[i]; sh[0] = t; }
    __syncthreads();
    float inv = 1.f / sh[0];
#pragma unroll
    for (int i = 0; i < 16; i++) P[base + tid + i * 256] = v[i] * inv;
}

// ---- Kc/Vc partials (split-K over s) ----
__global__ __launch_bounds__(256) void compress_partial_kernel(
    const float* __restrict__ P, const float* __restrict__ K,
    const float* __restrict__ V, float* __restrict__ partK, float* __restrict__ partV)
{
    __shared__ float Ps[NL][33];
    __shared__ float Ks[32][DHD];
    __shared__ float Vs[32][DHD];
    int bh = blockIdx.x, sp = blockIdx.y;
    int b = bh >> 4, h = bh & 15;
    int tid = threadIdx.x;
    int l = tid >> 3, qd = (tid & 7) * 8;
    float accK[8] = {}, accV[8] = {};
    const float* Pb = P + (size_t)(b * (NH * NL) + h * NL) * SEQN;
    const float* Kb = K + (size_t)bh * SEQN * DHD;
    const float* Vb = V + (size_t)bh * SEQN * DHD;
    for (int sc = 0; sc < SEQN / NSPLIT; sc += 32) {
        int s0 = sp * (SEQN / NSPLIT) + sc;
        {
            int pl = tid >> 3, ps = (tid & 7) * 4;
            float4 p4 = *(const float4*)(Pb + (size_t)pl * SEQN + s0 + ps);
            Ps[pl][ps] = p4.x; Ps[pl][ps+1] = p4.y; Ps[pl][ps+2] = p4.z; Ps[pl][ps+3] = p4.w;
        }
        {
            int ks = tid >> 3, kd = (tid & 7) * 8;
            const float* kp = Kb + (size_t)(s0 + ks) * DHD + kd;
            *(float4*)&Ks[ks][kd] = *(const float4*)kp;
            *(float4*)&Ks[ks][kd+4] = *(const float4*)(kp + 4);
            const float* vp = Vb + (size_t)(s0 + ks) * DHD + kd;
            *(float4*)&Vs[ks][kd] = *(const float4*)vp;
            *(float4*)&Vs[ks][kd+4] = *(const float4*)(vp + 4);
        }
        __syncthreads();
#pragma unroll 8
        for (int si = 0; si < 32; si++) {
            float p = Ps[l][si];
            float kf[8], vf[8];
            *(float4*)kf = *(float4*)&Ks[si][qd]; *(float4*)(kf+4) = *(float4*)&Ks[si][qd+4];
            *(float4*)vf = *(float4*)&Vs[si][qd]; *(float4*)(vf+4) = *(float4*)&Vs[si][qd+4];
#pragma unroll
            for (int j = 0; j < 8; j++) { accK[j] += p * kf[j]; accV[j] += p * vf[j]; }
        }
        __syncthreads();
    }
    size_t ob = (size_t)sp * CSIZE + ((size_t)bh * NL + l) * DHD + qd;
    *(float4*)(partK + ob)   = make_float4(accK[0], accK[1], accK[2], accK[3]);
    *(float4*)(partK + ob+4) = make_float4(accK[4], accK[5], accK[6], accK[7]);
    *(float4*)(partV + ob)   = make_float4(accV[0], accV[1], accV[2], accV[3]);
    *(float4*)(partV + ob+4) = make_float4(accV[4], accV[5], accV[6], accV[7]);
}

// ---- reduce partials + LN for Kc/Vc ----
__global__ __launch_bounds__(256) void compress_ln_kernel(
    const float* __restrict__ partK, const float* __restrict__ partV,
    const float* __restrict__ gamma, const float* __restrict__ beta,
    float* __restrict__ outK, float* __restrict__ outV)
{
    __shared__ float shs[8], shq[8];
    int bl = blockIdx.x, b = bl >> 5, l = bl & 31;
    const float* part = blockIdx.y ? partV : partK;
    float* out = blockIdx.y ? outV : outK;
    int tid = threadIdx.x, c = tid * 4;
    size_t base = ((size_t)(b * NH + (c >> 6)) * NL + l) * DHD + (c & 63);
    float4 acc = make_float4(0, 0, 0, 0);
#pragma unroll
    for (int sp = 0; sp < NSPLIT; sp++) {
        float4 p = *(const float4*)(part + (size_t)sp * CSIZE + base);
        acc.x += p.x; acc.y += p.y; acc.z += p.z; acc.w += p.w;
    }
    float s = acc.x + acc.y + acc.z + acc.w;
    float q = acc.x*acc.x + acc.y*acc.y + acc.z*acc.z + acc.w*acc.w;
    int lane = tid & 31, wid = tid >> 5;
#pragma unroll
    for (int o = 16; o; o >>= 1) {
        s += __shfl_xor_sync(~0u, s, o); q += __shfl_xor_sync(~0u, q, o);
    }
    if (lane == 0) { shs[wid] = s; shq[wid] = q; }
    __syncthreads();
    if (tid == 0) {
        float ts = 0, tq = 0;
        for (int i = 0; i < 8; i++) { ts += shs[i]; tq += shq[i]; }
        shs[0] = ts; shq[0] = tq;
    }
    __syncthreads();
    float mean = shs[0] * (1.f / DIM);
    float rstd = rsqrtf(shq[0] * (1.f / DIM) - mean * mean + 1e-5f);
    float4 g4 = ((const float4*)gamma)[tid], b4 = ((const float4*)beta)[tid];
    float4 o;
    o.x = (acc.x - mean) * rstd * g4.x + b4.x;
    o.y = (acc.y - mean) * rstd * g4.y + b4.y;
    o.z = (acc.z - mean) * rstd * g4.z + b4.z;
    o.w = (acc.w - mean) * rstd * g4.w + b4.w;
    *(float4*)(out + base) = o;
}

// ---- fused attention, 8 groups/block, float4 smem reads, fp16 hi/lo out ----
#define PADD 68
#define AT_KC 0
#define AT_VC (AT_KC + NL * PADD)
#define AT_KW (AT_VC + NL * PADD)
#define AT_VW (AT_KW + 72 * PADD)
#define AT_Q  (AT_VW + 72 * PADD)
#define AT_PR (AT_Q + 64 * PADD)
#define ATTN_FLOATS (AT_PR + 8 * 48)
#define ATTN_SMEM (ATTN_FLOATS * 4)

__global__ __launch_bounds__(256) void attn_kernel(
    const float* __restrict__ Q, const float* __restrict__ K,
    const float* __restrict__ V, const float* __restrict__ Kc,
    const float* __restrict__ Vc, __half* __restrict__ Ch, __half* __restrict__ Cl)
{
    extern __shared__ float sf[];
    int gblk = blockIdx.x, h = blockIdx.y, b = blockIdx.z;
    int bh = b * NH + h, tid = threadIdx.x;
    const int base = gblk * 64;

    {   // Kc/Vc 32x64
        int l = tid >> 3, d0 = (tid & 7) * 8;
        size_t src = ((size_t)bh * NL + l) * DHD + d0;
        float4 k0 = *(const float4*)(Kc + src), k1 = *(const float4*)(Kc + src + 4);
        float4 v0 = *(const float4*)(Vc + src), v1 = *(const float4*)(Vc + src + 4);
        *(float4*)(sf + AT_KC + l * PADD + d0)     = k0;
        *(float4*)(sf + AT_KC + l * PADD + d0 + 4) = k1;
        *(float4*)(sf + AT_VC + l * PADD + d0)     = v0;
        *(float4*)(sf + AT_VC + l * PADD + d0 + 4) = v1;
    }
    for (int idx = tid; idx < 72 * 16; idx += 256) {
        int row = idx >> 4, d = (idx & 15) * 4;
        int sk = base - EE + row;
        float4 kv = make_float4(0,0,0,0), vv = make_float4(0,0,0,0);
        if (sk >= 0 && sk < SEQN) {
            size_t src = ((size_t)bh * SEQN + sk) * DHD + d;
            kv = *(const float4*)(K + src); vv = *(const float4*)(V + src);
        }
        *(float4*)(sf + AT_KW + row * PADD + d) = kv;
        *(float4*)(sf + AT_VW + row * PADD + d) = vv;
    }
    for (int idx = tid; idx < 64 * 16; idx += 256) {
        int row = idx >> 4, d = (idx & 15) * 4;
        *(float4*)(sf + AT_Q + row * PADD + d) =
            *(const float4*)(Q + ((size_t)bh * SEQN + base + row) * DHD + d);
    }
    __syncthreads();

    const int warp = tid >> 5, lane = tid & 31;
    const int k = lane & 15;
    const int wrow = warp * 8 + k;
    const int skg = base + warp * 8 + k - EE;
    const bool kvalid = (lane < BAND) && (skg >= 0) && (skg < SEQN);
    float* probs = sf + AT_PR + warp * 48;
    const float4* kcr = (const float4*)(sf + AT_KC + lane * PADD);
    const float4* kwr = (const float4*)(sf + AT_KW + wrow * PADD);

#pragma unroll 1
    for (int q = 0; q < 8; q++) {
        const float4* qr = (const float4*)(sf + AT_Q + (warp * 8 + q) * PADD);
        float sc = 0.f, sw = 0.f;
#pragma unroll
        for (int d4 = 0; d4 < 16; d4++) {
            float4 qv = qr[d4], kc = kcr[d4], kw = kwr[d4];
            sc += qv.x*kc.x + qv.y*kc.y + qv.z*kc.z + qv.w*kc.w;
            sw += qv.x*kw.x + qv.y*kw.y + qv.z*kw.z + qv.w*kw.w;
        }
        float m = fmaxf(sc, kvalid ? sw : -1e30f);
#pragma unroll
        for (int o = 16; o; o >>= 1) m = fmaxf(m, __shfl_xor_sync(~0u, m, o));
        float e0 = __expf(sc - m);
        float e1 = kvalid ? __expf(sw - m) : 0.f;
        float t = e0 + e1;
#pragma unroll
        for (int o = 16; o; o >>= 1) t += __shfl_xor_sync(~0u, t, o);
        float inv = 1.f / t;
        probs[lane] = e0 * inv;
        if (lane < BAND) probs[NL + lane] = e1 * inv;
        __syncwarp();

        float a0 = 0.f, a1 = 0.f;
#pragma unroll
        for (int j = 0; j < NL; j++) {
            float p = probs[j];
            a0 += p * sf[AT_VC + j * PADD + lane];
            a1 += p * sf[AT_VC + j * PADD + lane + 32];
        }
#pragma unroll
        for (int kk = 0; kk < BAND; kk++) {
            float p = probs[NL + kk];
            a0 += p * sf[AT_VW + (warp * 8 + kk) * PADD + lane];
            a1 += p * sf[AT_VW + (warp * 8 + kk) * PADD + lane + 32];
        }
        __syncwarp();

        size_t off = ((size_t)(b * SEQN) + base + warp * 8 + q) * DIM + h * DHD;
        __half h0 = __float2half_rn(a0), h1 = __float2half_rn(a1);
        Ch[off + lane] = h0;
        Ch[off + 32 + lane] = h1;
        Cl[off + lane] = __float2half_rn(a0 - __half2float(h0));
        Cl[off + 32 + lane] = __float2half_rn(a1 - __half2float(h1));
    }
}

// ===========================================================================
extern "C" void kernel_launch(void* const* d_in, const int* in_sizes, int n_in,
                              void* d_out, int out_size)
{
    (void)in_sizes; (void)n_in; (void)out_size;
    const float* query = (const float*)d_in[0];
    const float* Wq = (const float*)d_in[1];  const float* bq = (const float*)d_in[2];
    const float* Wk = (const float*)d_in[3];  const float* bk = (const float*)d_in[4];
    const float* Wv = (const float*)d_in[5];  const float* bv = (const float*)d_in[6];
    const float* Wo = (const float*)d_in[7];  const float* bo = (const float*)d_in[8];
    const float* gl = (const float*)d_in[9];  const float* bl = (const float*)d_in[10];
    const float* gs = (const float*)d_in[11]; const float* bs = (const float*)d_in[12];
    const float* Wd = (const float*)d_in[13]; const float* bd = (const float*)d_in[14];
    float* out = (float*)d_out;

    float *pQ,*pK,*pV,*pTmp,*pTv,*pD,*pP,*pKcP,*pVcP,*pKc,*pVc;
    __half *pXh,*pXl,*pCh,*pCl,*pWth,*pWtl;
    cudaGetSymbolAddress((void**)&pQ, g_Q);
    cudaGetSymbolAddress((void**)&pK, g_K);
    cudaGetSymbolAddress((void**)&pV, g_V);
    cudaGetSymbolAddress((void**)&pTmp, g_tmp);
    cudaGetSymbolAddress((void**)&pTv, g_tv);
    cudaGetSymbolAddress((void**)&pD, g_D);
    cudaGetSymbolAddress((void**)&pP, g_P);
    cudaGetSymbolAddress((void**)&pKcP, g_KcP);
    cudaGetSymbolAddress((void**)&pVcP, g_VcP);
    cudaGetSymbolAddress((void**)&pKc, g_Kc);
    cudaGetSymbolAddress((void**)&pVc, g_Vc);
    cudaGetSymbolAddress((void**)&pXh, g_Xh);
    cudaGetSymbolAddress((void**)&pXl, g_Xl);
    cudaGetSymbolAddress((void**)&pCh, g_Ch);
    cudaGetSymbolAddress((void**)&pCl, g_Cl);
    cudaGetSymbolAddress((void**)&pWth, g_Wth);
    cudaGetSymbolAddress((void**)&pWtl, g_Wtl);

    cudaFuncSetAttribute(hgemm_qkvd, cudaFuncAttributeMaxDynamicSharedMemorySize, GEMM_SMEM2);
    cudaFuncSetAttribute(hgemm_o, cudaFuncAttributeMaxDynamicSharedMemorySize, GEMM_SMEM3);
    cudaFuncSetAttribute(attn_kernel, cudaFuncAttributeMaxDynamicSharedMemorySize, ATTN_SMEM);

    split_perm_kernel<<<MROWS * DIM / 4 / 256, 256>>>(query, pXh, pXl);
    wsplit_all_kernel<<<dim3(DIM / 32, DIM / 32, 5), dim3(32, 8)>>>(
        Wq, Wk, Wv, Wd, Wo, pWth, pWtl);

    hgemm_qkvd<<<dim3((3 * DIM + NH * NL) / 128, MROWS / 128), 256, GEMM_SMEM2>>>(
        pXh, pXl, pWth, pWtl, bq, bk, bv, bd, pQ, pTmp, pTv, pD);

    ln_split2_kernel<<<dim3(MROWS, 2), 256>>>(pTmp, pTv, gl, bl, pK, pV);

    transpose_kernel<<<dim3((NH * NL) / 32, SEQN / 32, BATCH), dim3(32, 8)>>>(pD, pP);
    softmax_rows_kernel<<<BATCH * NH * NL, 256>>>(pP);
    compress_partial_kernel<<<dim3(BATCH * NH, NSPLIT), 256>>>(pP, pK, pV, pKcP, pVcP);
    compress_ln_kernel<<<dim3(BATCH * NL, 2), 256>>>(pKcP, pVcP, gs, bs, pKc, pVc);

    attn_kernel<<<dim3(NG / 8, NH, BATCH), 256, ATTN_SMEM>>>(pQ, pK, pV, pKc, pVc, pCh, pCl);

    hgemm_o<<<dim3(DIM / 128, MROWS / 128), 256, GEMM_SMEM3>>>(
        pCh, pCl, pWth + WOFF_O, pWtl + WOFF_O, bo, out);
}

// round 9
// speedup vs baseline: 3.6180x; 1.2766x over previous
#include <cuda_runtime.h>
#include <cuda_fp16.h>
#include <math.h>
#include <stdint.h>

#define SEQN  4096
#define BATCH 4
#define DIM   1024
#define NH    16
#define DHD   64
#define NL    32
#define WW    8
#define EE    4
#define BAND  16
#define NG    (SEQN / WW)
#define MROWS (BATCH * SEQN)
#define NSPLIT 8
#define CSIZE (BATCH * NH * NL * DHD)

__device__ float g_Q  [BATCH * NH * SEQN * DHD];
__device__ float g_K  [BATCH * NH * SEQN * DHD];
__device__ float g_V  [BATCH * NH * SEQN * DHD];
__device__ float g_tmp[BATCH * SEQN * DIM];
__device__ float g_tv [BATCH * SEQN * DIM];
__device__ float g_D  [BATCH * SEQN * NH * NL];
__device__ float g_P  [BATCH * NH * NL * SEQN];
__device__ float g_KcP[NSPLIT * CSIZE];
__device__ float g_VcP[NSPLIT * CSIZE];
__device__ float g_Kc [CSIZE];
__device__ float g_Vc [CSIZE];

__device__ __align__(16) __half g_Xh[MROWS * DIM];
__device__ __align__(16) __half g_Xl[MROWS * DIM];
__device__ __align__(16) __half g_Ch[MROWS * DIM];
__device__ __align__(16) __half g_Cl[MROWS * DIM];
__device__ __align__(16) __half g_KhF[BATCH * NH * SEQN * DHD];  // fp16 K (head-split)
__device__ __align__(16) __half g_VhF[BATCH * NH * SEQN * DHD];  // fp16 V
__device__ __align__(16) __half g_Ph [BATCH * NH * NL * SEQN];   // fp16 probs hi
__device__ __align__(16) __half g_Pl [BATCH * NH * NL * SEQN];   // fp16 probs lo
// weight rows: Q 0-1023, K 1024-2047, V 2048-3071, D 3072-3583, O 3584-4607
#define WOFF_O (3 * DIM * DIM + (NH * NL) * DIM)
#define WT_TOTAL (4 * DIM * DIM + (NH * NL) * DIM)
__device__ __align__(16) __half g_Wth[WT_TOTAL];
__device__ __align__(16) __half g_Wtl[WT_TOTAL];

// =========================== HMMA GEMM core ================================
#define SROWB 80
#define TILEB (128 * SROWB)
#define NIT (DIM / 32)

__device__ __forceinline__ uint32_t smem_u32(const void* p) {
    uint32_t a;
    asm("{ .reg .u64 t; cvta.to.shared.u64 t, %1; cvt.u32.u64 %0, t; }" : "=r"(a) : "l"(p));
    return a;
}
#define CPA(dst, src) \
    asm volatile("cp.async.cg.shared.global [%0], [%1], 16;" :: "r"(dst), "l"(src))
#define CP_COMMIT() asm volatile("cp.async.commit_group;")
#define CP_WAIT(n)  asm volatile("cp.async.wait_group %0;" :: "n"(n))
#define LDSM4(R, addr) \
    asm volatile("ldmatrix.sync.aligned.m8n8.x4.shared.b16 {%0,%1,%2,%3}, [%4];" \
        : "=r"((R)[0]), "=r"((R)[1]), "=r"((R)[2]), "=r"((R)[3]) : "r"(addr))
#define LDSM4T(R, addr) \
    asm volatile("ldmatrix.sync.aligned.m8n8.x4.trans.shared.b16 {%0,%1,%2,%3}, [%4];" \
        : "=r"((R)[0]), "=r"((R)[1]), "=r"((R)[2]), "=r"((R)[3]) : "r"(addr))
#define MMA16816(d, a, b0, b1) \
    asm volatile("mma.sync.aligned.m16n8k16.row.col.f32.f16.f16.f32 " \
        "{%0,%1,%2,%3}, {%4,%5,%6,%7}, {%8,%9}, {%0,%1,%2,%3};" \
        : "+f"((d)[0]), "+f"((d)[1]), "+f"((d)[2]), "+f"((d)[3]) \
        : "r"((a)[0]), "r"((a)[1]), "r"((a)[2]), "r"((a)[3]), "r"(b0), "r"(b1))

// TERMS=3: Ah*Bh + Ah*Bl + Al*Bh.  TERMS=2: (Ah+Al)*Bh.
template <int TERMS>
__device__ __forceinline__ void hgemm_main(
    const __half* Ah, const __half* Al, const __half* Bh, const __half* Bl,
    int bm, int bn, uint32_t sb, int tid, float acc[2][8][4])
{
    constexpr uint32_t STG = (TERMS + 1) * TILEB;
    const uint32_t oAH = 0, oAL = TILEB, oBH = 2 * TILEB, oBL = 3 * TILEB;

    const int lane = tid & 31, wid = tid >> 5;
    const int wm = wid & 3, wn = wid >> 2;
    const int lr0 = tid >> 2;
    const size_t aoff0 = ((size_t)(bm + lr0) << 10) + (size_t)(tid & 3) * 8;
    const size_t aoff1 = aoff0 + ((size_t)64 << 10);
    const size_t boff0 = ((size_t)(bn + lr0) << 10) + (size_t)(tid & 3) * 8;
    const size_t boff1 = boff0 + ((size_t)64 << 10);
    const uint32_t d0 = (uint32_t)lr0 * SROWB + (tid & 3) * 16;
    const uint32_t d1 = d0 + 64 * SROWB;

    CPA(sb + oAH + d0, Ah + aoff0); CPA(sb + oAH + d1, Ah + aoff1);
    CPA(sb + oAL + d0, Al + aoff0); CPA(sb + oAL + d1, Al + aoff1);
    CPA(sb + oBH + d0, Bh + boff0); CPA(sb + oBH + d1, Bh + boff1);
    if (TERMS == 3) { CPA(sb + oBL + d0, Bl + boff0); CPA(sb + oBL + d1, Bl + boff1); }
    CP_COMMIT();

#pragma unroll
    for (int i = 0; i < 2; i++)
#pragma unroll
        for (int j = 0; j < 8; j++)
#pragma unroll
            for (int k = 0; k < 4; k++) acc[i][j][k] = 0.f;

    const uint32_t aBase = (uint32_t)(wm * 32 + (lane & 15)) * SROWB + (lane >> 4) * 16;
    const uint32_t bBase = (uint32_t)(wn * 64 + ((lane >> 4) & 1) * 8 + (lane & 7)) * SROWB
                           + ((lane >> 3) & 1) * 16;

    for (int it = 0; it < NIT; it++) {
        const uint32_t ps = (it & 1) * STG;
        if (it + 1 < NIT) {
            const uint32_t ns = ((it + 1) & 1) * STG;
            const int kb = (it + 1) * 32;
            CPA(sb + ns + oAH + d0, Ah + aoff0 + kb); CPA(sb + ns + oAH + d1, Ah + aoff1 + kb);
            CPA(sb + ns + oAL + d0, Al + aoff0 + kb); CPA(sb + ns + oAL + d1, Al + aoff1 + kb);
            CPA(sb + ns + oBH + d0, Bh + boff0 + kb); CPA(sb + ns + oBH + d1, Bh + boff1 + kb);
            if (TERMS == 3) {
                CPA(sb + ns + oBL + d0, Bl + boff0 + kb); CPA(sb + ns + oBL + d1, Bl + boff1 + kb);
            }
            CP_COMMIT();
            CP_WAIT(1);
        } else {
            CP_WAIT(0);
        }
        __syncthreads();

        const uint32_t sAH = sb + ps + oAH + aBase, sAL = sb + ps + oAL + aBase;
        const uint32_t sBH = sb + ps + oBH + bBase, sBL = sb + ps + oBL + bBase;
#pragma unroll
        for (int ks = 0; ks < 2; ks++) {
            const uint32_t ko = ks * 32;
            uint32_t ah[2][4], al[2][4];
            LDSM4(ah[0], sAH + ko);
            LDSM4(ah[1], sAH + ko + 16 * SROWB);
            LDSM4(al[0], sAL + ko);
            LDSM4(al[1], sAL + ko + 16 * SROWB);
#pragma unroll
            for (int q = 0; q < 4; q++) {
                uint32_t bh[4];
                LDSM4(bh, sBH + ko + q * 16 * SROWB);
                if (TERMS == 3) {
                    uint32_t bl[4];
                    LDSM4(bl, sBL + ko + q * 16 * SROWB);
#pragma unroll
                    for (int mt = 0; mt < 2; mt++) {
                        MMA16816(acc[mt][2 * q + 0], ah[mt], bh[0], bh[1]);
                        MMA16816(acc[mt][2 * q + 0], ah[mt], bl[0], bl[1]);
                        MMA16816(acc[mt][2 * q + 0], al[mt], bh[0], bh[1]);
                        MMA16816(acc[mt][2 * q + 1], ah[mt], bh[2], bh[3]);
                        MMA16816(acc[mt][2 * q + 1], ah[mt], bl[2], bl[3]);
                        MMA16816(acc[mt][2 * q + 1], al[mt], bh[2], bh[3]);
                    }
                } else {
#pragma unroll
                    for (int mt = 0; mt < 2; mt++) {
                        MMA16816(acc[mt][2 * q + 0], ah[mt], bh[0], bh[1]);
                        MMA16816(acc[mt][2 * q + 0], al[mt], bh[0], bh[1]);
                        MMA16816(acc[mt][2 * q + 1], ah[mt], bh[2], bh[3]);
                        MMA16816(acc[mt][2 * q + 1], al[mt], bh[2], bh[3]);
                    }
                }
            }
        }
        __syncthreads();
    }
}
#define GEMM_SMEM2 (2 * 3 * TILEB)

// ---- fused Q/K/V/D GEMM (2-term) ----
__global__ __launch_bounds__(256, 2) void hgemm_qkvd(
    const __half* __restrict__ Ah, const __half* __restrict__ Al,
    const __half* __restrict__ Bh, const __half* __restrict__ Bl,
    const float* __restrict__ bq, const float* __restrict__ bk,
    const float* __restrict__ bv, const float* __restrict__ bd,
    float* __restrict__ outQ, float* __restrict__ outK,
    float* __restrict__ outV, float* __restrict__ outD)
{
    extern __shared__ __align__(16) char smem[];
    const uint32_t sb = smem_u32(smem);
    const int tid = threadIdx.x, wid = tid >> 5, lane = tid & 31;
    const int bn = blockIdx.x * 128, bm = blockIdx.y * 128;
    float acc[2][8][4];
    hgemm_main<2>(Ah, Al, Bh, Bl, bm, bn, sb, tid, acc);

    const int seg = bn >> 10;
    const int cl = bn & 1023;
    const float* bias = seg == 0 ? bq : seg == 1 ? bk : seg == 2 ? bv : bd;
    const float scale = seg == 0 ? 0.125f : 1.f;
    const int wm = wid & 3, wn = wid >> 2;
    const int r0 = bm + wm * 32 + (lane >> 2);
    const int c0 = cl + wn * 64 + (lane & 3) * 2;
#pragma unroll
    for (int mt = 0; mt < 2; mt++) {
#pragma unroll
        for (int hf = 0; hf < 2; hf++) {
            const int r = r0 + mt * 16 + hf * 8;
            const int bb = r >> 12, ss = r & (SEQN - 1);
#pragma unroll
            for (int nt = 0; nt < 8; nt++) {
                const int col = c0 + nt * 8;
                const float2 bv2 = *(const float2*)(bias + col);
                float vx = (acc[mt][nt][hf * 2 + 0] + bv2.x) * scale;
                float vy = (acc[mt][nt][hf * 2 + 1] + bv2.y) * scale;
                float* op; size_t o;
                if (seg == 0) {
                    op = outQ;
                    o = ((size_t)(bb * NH + (col >> 6)) * SEQN + ss) * DHD + (col & 63);
                } else if (seg == 1) { op = outK; o = (size_t)r * DIM + col; }
                else if (seg == 2)   { op = outV; o = (size_t)r * DIM + col; }
                else                 { op = outD; o = (size_t)r * (NH * NL) + col; }
                *(float2*)(op + o) = make_float2(vx, vy);
            }
        }
    }
}

// ---- output GEMM (2-term): out = C @ Wo + bo, (s,b,DIM) ----
__global__ __launch_bounds__(256, 2) void hgemm_o(
    const __half* __restrict__ Ah, const __half* __restrict__ Al,
    const __half* __restrict__ Bh, const __half* __restrict__ Bl,
    const float* __restrict__ bias, float* __restrict__ out)
{
    extern __shared__ __align__(16) char smem[];
    const uint32_t sb = smem_u32(smem);
    const int tid = threadIdx.x, wid = tid >> 5, lane = tid & 31;
    const int bn = blockIdx.x * 128, bm = blockIdx.y * 128;
    float acc[2][8][4];
    hgemm_main<2>(Ah, Al, Bh, Bl, bm, bn, sb, tid, acc);

    const int wm = wid & 3, wn = wid >> 2;
    const int r0 = bm + wm * 32 + (lane >> 2);
    const int c0 = bn + wn * 64 + (lane & 3) * 2;
#pragma unroll
    for (int mt = 0; mt < 2; mt++) {
#pragma unroll
        for (int hf = 0; hf < 2; hf++) {
            const int r = r0 + mt * 16 + hf * 8;
            const int bb = r >> 12, ss = r & (SEQN - 1);
#pragma unroll
            for (int nt = 0; nt < 8; nt++) {
                const int col = c0 + nt * 8;
                const float2 bv2 = *(const float2*)(bias + col);
                *(float2*)(out + ((size_t)ss * BATCH + bb) * DIM + col) =
                    make_float2(acc[mt][nt][hf * 2 + 0] + bv2.x,
                                acc[mt][nt][hf * 2 + 1] + bv2.y);
            }
        }
    }
}

// ================= HMMA compress: Kc/Vc partials ===========================
// partK[sp][bh][l][d] = sum_{s in sp-chunk} P[l][s] * K[s][d]  (and V)
// A = P fp16 hi/lo [l][s] (s contig, ldmatrix); B = K/V fp16 [s][d] (d contig,
// ldmatrix.trans gives k-contiguous fragment). 2 terms: (Ph+Pl)*Kh.
#define CPROW 144                     // 64 halves + 16B pad
#define CPS_PH 0
#define CPS_PL (32 * CPROW)           // 4608
#define CPS_K  (64 * CPROW)           // 9216
#define CPS_V  (128 * CPROW)          // 18432
#define CP_STG (192 * CPROW)          // 27648
#define COMP_SMEM (2 * CP_STG)

__global__ __launch_bounds__(256, 2) void compress_hmma(
    const __half* __restrict__ Ph, const __half* __restrict__ Pl,
    const __half* __restrict__ Kh, const __half* __restrict__ Vh,
    float* __restrict__ partK, float* __restrict__ partV)
{
    extern __shared__ __align__(16) char smem[];
    const uint32_t sb = smem_u32(smem);
    const int bh = blockIdx.x, sp = blockIdx.y;
    const int b = bh >> 4, h = bh & 15;
    const int tid = threadIdx.x, lane = tid & 31, wid = tid >> 5;

    const size_t pbase = ((size_t)(b * (NH * NL) + h * NL)) * SEQN + sp * 512;
    const size_t kbase = ((size_t)bh * SEQN + sp * 512) * DHD;

    // loader mapping
    const int prow = tid >> 3, pseg = tid & 7;     // 32 rows x 8 16B-segs
    const uint32_t pDst = prow * CPROW + pseg * 16;
    const size_t pSrc = (size_t)prow * SEQN + pseg * 8;
    const uint32_t kDst0 = prow * CPROW + pseg * 16;
    const uint32_t kDst1 = (prow + 32) * CPROW + pseg * 16;
    const size_t kSrc0 = (size_t)prow * DHD + pseg * 8;
    const size_t kSrc1 = (size_t)(prow + 32) * DHD + pseg * 8;

    // prologue: chunk 0
    CPA(sb + CPS_PH + pDst, Ph + pbase + pSrc);
    CPA(sb + CPS_PL + pDst, Pl + pbase + pSrc);
    CPA(sb + CPS_K + kDst0, Kh + kbase + kSrc0);
    CPA(sb + CPS_K + kDst1, Kh + kbase + kSrc1);
    CPA(sb + CPS_V + kDst0, Vh + kbase + kSrc0);
    CPA(sb + CPS_V + kDst1, Vh + kbase + kSrc1);
    CP_COMMIT();

    float acc[4][4];
#pragma unroll
    for (int i = 0; i < 4; i++)
#pragma unroll
        for (int j = 0; j < 4; j++) acc[i][j] = 0.f;

    const int outv = wid >> 2;             // 0: K, 1: V
    const int mt = wid & 1, nh2 = (wid >> 1) & 1;
    const uint32_t aOff = (uint32_t)(mt * 16 + (lane & 15)) * CPROW + (lane >> 4) * 16;
    const uint32_t bRow = (lane & 7) + ((lane >> 3) & 1) * 8;
    const uint32_t bCol = ((lane >> 4) & 1) * 16 + nh2 * 64;
    const uint32_t kvOff = outv ? CPS_V : CPS_K;

    for (int c = 0; c < 8; c++) {
        const uint32_t ps = (c & 1) * CP_STG;
        if (c + 1 < 8) {
            const uint32_t ns = ((c + 1) & 1) * CP_STG;
            const int so = (c + 1) * 64;                 // s offset within sp chunk
            CPA(sb + ns + CPS_PH + pDst, Ph + pbase + so + pSrc);
            CPA(sb + ns + CPS_PL + pDst, Pl + pbase + so + pSrc);
            CPA(sb + ns + CPS_K + kDst0, Kh + kbase + (size_t)so * DHD + kSrc0);
            CPA(sb + ns + CPS_K + kDst1, Kh + kbase + (size_t)so * DHD + kSrc1);
            CPA(sb + ns + CPS_V + kDst0, Vh + kbase + (size_t)so * DHD + kSrc0);
            CPA(sb + ns + CPS_V + kDst1, Vh + kbase + (size_t)so * DHD + kSrc1);
            CP_COMMIT();
            CP_WAIT(1);
        } else {
            CP_WAIT(0);
        }
        __syncthreads();

        const uint32_t sP0 = sb + ps + CPS_PH + aOff;
        const uint32_t sP1 = sb + ps + CPS_PL + aOff;
        const uint32_t sKV = sb + ps + kvOff;
#pragma unroll
        for (int ks = 0; ks < 4; ks++) {
            uint32_t ah[4], al[4], b0[4], b1[4];
            LDSM4(ah, sP0 + ks * 32);
            LDSM4(al, sP1 + ks * 32);
            const uint32_t ba = sKV + (ks * 16 + bRow) * CPROW + bCol;
            LDSM4T(b0, ba);
            LDSM4T(b1, ba + 32);
            MMA16816(acc[0], ah, b0[0], b0[1]);
            MMA16816(acc[0], al, b0[0], b0[1]);
            MMA16816(acc[1], ah, b0[2], b0[3]);
            MMA16816(acc[1], al, b0[2], b0[3]);
            MMA16816(acc[2], ah, b1[0], b1[1]);
            MMA16816(acc[2], al, b1[0], b1[1]);
            MMA16816(acc[3], ah, b1[2], b1[3]);
            MMA16816(acc[3], al, b1[2], b1[3]);
        }
        __syncthreads();
    }

    float* outp = outv ? partV : partK;
    const size_t ob = (size_t)sp * CSIZE + (size_t)bh * NL * DHD;
    const int l0 = mt * 16 + (lane >> 2);
    const int db = nh2 * 32 + (lane & 3) * 2;
#pragma unroll
    for (int nt = 0; nt < 4; nt++) {
        const int d = db + nt * 8;
        *(float2*)(outp + ob + (size_t)l0 * DHD + d) = make_float2(acc[nt][0], acc[nt][1]);
        *(float2*)(outp + ob + (size_t)(l0 + 8) * DHD + d) = make_float2(acc[nt][2], acc[nt][3]);
    }
}

// ---- fp32 -> fp16 hi/lo split with (s,b)->(b,s) permute ----
__global__ __launch_bounds__(256) void split_perm_kernel(
    const float* __restrict__ X, __half* __restrict__ H, __half* __restrict__ L)
{
    int i = blockIdx.x * 256 + threadIdx.x;
    int r = i >> 8, k4 = i & 255;
    int b = r >> 12, s = r & (SEQN - 1);
    float4 v = *((const float4*)X + ((size_t)s * BATCH + b) * 256 + k4);
    __half h0 = __float2half_rn(v.x), h1 = __float2half_rn(v.y);
    __half h2 = __float2half_rn(v.z), h3 = __float2half_rn(v.w);
    __half2* Hp = (__half2*)(H + (size_t)i * 4);
    __half2* Lp = (__half2*)(L + (size_t)i * 4);
    Hp[0] = __halves2half2(h0, h1); Hp[1] = __halves2half2(h2, h3);
    Lp[0] = __halves2half2(__float2half_rn(v.x - __half2float(h0)),
                           __float2half_rn(v.y - __half2float(h1)));
    Lp[1] = __halves2half2(__float2half_rn(v.z - __half2float(h2)),
                           __float2half_rn(v.w - __half2float(h3)));
}

// ---- all 5 weight transposes + splits in one launch ----
__global__ void wsplit_all_kernel(
    const float* __restrict__ Wq, const float* __restrict__ Wk,
    const float* __restrict__ Wv, const float* __restrict__ Wd,
    const float* __restrict__ Wo, __half* __restrict__ Th, __half* __restrict__ Tl)
{
    __shared__ float t[32][33];
    int z = blockIdx.z;
    int N = (z == 3) ? (NH * NL) : DIM;
    if (blockIdx.x * 32 >= N) return;
    const float* W = z == 0 ? Wq : z == 1 ? Wk : z == 2 ? Wv : z == 3 ? Wd : Wo;
    size_t woff = z <= 3 ? (size_t)z * DIM * DIM : (size_t)WOFF_O;
    int n0 = blockIdx.x * 32, k0 = blockIdx.y * 32;
    int x = threadIdx.x, y = threadIdx.y;
#pragma unroll
    for (int i = 0; i < 32; i += 8)
        t[y + i][x] = W[(size_t)(k0 + y + i) * N + n0 + x];
    __syncthreads();
#pragma unroll
    for (int i = 0; i < 32; i += 8) {
        float v = t[x][y + i];
        __half h = __float2half_rn(v);
        size_t o = woff + (size_t)(n0 + y + i) * DIM + k0 + x;
        Th[o] = h;
        Tl[o] = __float2half_rn(v - __half2float(h));
    }
}

// ---- LayerNorm over DIM, head-split scatter; also emits fp16 copies ----
__global__ __launch_bounds__(256) void ln_split2_kernel(
    const float* __restrict__ XK, const float* __restrict__ XV,
    const float* __restrict__ gamma, const float* __restrict__ beta,
    float* __restrict__ outK, float* __restrict__ outV,
    __half* __restrict__ outKh, __half* __restrict__ outVh)
{
    __shared__ float shs[8], shq[8];
    int r = blockIdx.x, tid = threadIdx.x;
    const float* X = blockIdx.y ? XV : XK;
    float* out = blockIdx.y ? outV : outK;
    __half* outh = blockIdx.y ? outVh : outKh;
    const float4 v = ((const float4*)(X + (size_t)r * DIM))[tid];
    float s = v.x + v.y + v.z + v.w;
    float q = v.x*v.x + v.y*v.y + v.z*v.z + v.w*v.w;
    int lane = tid & 31, wid = tid >> 5;
#pragma unroll
    for (int o = 16; o; o >>= 1) {
        s += __shfl_xor_sync(~0u, s, o); q += __shfl_xor_sync(~0u, q, o);
    }
    if (lane == 0) { shs[wid] = s; shq[wid] = q; }
    __syncthreads();
    if (tid == 0) {
        float ts = 0, tq = 0;
        for (int i = 0; i < 8; i++) { ts += shs[i]; tq += shq[i]; }
        shs[0] = ts; shq[0] = tq;
    }
    __syncthreads();
    float mean = shs[0] * (1.f / DIM);
    float rstd = rsqrtf(shq[0] * (1.f / DIM) - mean * mean + 1e-5f);
    int c = tid * 4;
    float4 g4 = ((const float4*)gamma)[tid], b4 = ((const float4*)beta)[tid];
    float4 o;
    o.x = (v.x - mean) * rstd * g4.x + b4.x;
    o.y = (v.y - mean) * rstd * g4.y + b4.y;
    o.z = (v.z - mean) * rstd * g4.z + b4.z;
    o.w = (v.w - mean) * rstd * g4.w + b4.w;
    int b = r >> 12, sq = r & (SEQN - 1);
    size_t base = ((size_t)(b * NH + (c >> 6)) * SEQN + sq) * DHD + (c & 63);
    *(float4*)(out + base) = o;
    __half2* hp = (__half2*)(outh + base);
    hp[0] = __halves2half2(__float2half_rn(o.x), __float2half_rn(o.y));
    hp[1] = __halves2half2(__float2half_rn(o.z), __float2half_rn(o.w));
}

// ---- transpose (b,s,512) -> (b,512,s) ----
__global__ void transpose_kernel(const float* __restrict__ D, float* __restrict__ P)
{
    __shared__ float t[32][33];
    int b = blockIdx.z, c0 = blockIdx.x * 32, s0 = blockIdx.y * 32;
    int x = threadIdx.x, y = threadIdx.y;
    const float* Db = D + (size_t)b * SEQN * (NH * NL);
    float* Pb = P + (size_t)b * (NH * NL) * SEQN;
#pragma unroll
    for (int i = 0; i < 32; i += 8)
        t[y + i][x] = Db[(size_t)(s0 + y + i) * (NH * NL) + c0 + x];
    __syncthreads();
#pragma unroll
    for (int i = 0; i < 32; i += 8)
        Pb[(size_t)(c0 + y + i) * SEQN + s0 + x] = t[x][y + i];
}

// ---- row softmax over 4096; emits fp16 hi/lo probs ----
__global__ __launch_bounds__(256) void softmax_rows_kernel(
    const float* __restrict__ P, __half* __restrict__ Ph, __half* __restrict__ Pl)
{
    __shared__ float sh[8];
    size_t base = (size_t)blockIdx.x * SEQN;
    int tid = threadIdx.x, lane = tid & 31, wid = tid >> 5;
    float v[16], m = -1e30f;
#pragma unroll
    for (int i = 0; i < 16; i++) { v[i] = P[base + tid + i * 256]; m = fmaxf(m, v[i]); }
#pragma unroll
    for (int o = 16; o; o >>= 1) m = fmaxf(m, __shfl_xor_sync(~0u, m, o));
    if (lane == 0) sh[wid] = m;
    __syncthreads();
    if (tid == 0) { float t = sh[0]; for (int i = 1; i < 8; i++) t = fmaxf(t, sh[i]); sh[0] = t; }
    __syncthreads();
    float M = sh[0];
    __syncthreads();
    float s = 0.f;
#pragma unroll
    for (int i = 0; i < 16; i++) { v[i] = __expf(v[i] - M); s += v[i]; }
#pragma unroll
    for (int o = 16; o; o >>= 1) s += __shfl_xor_sync(~0u, s, o);
    if (lane == 0) sh[wid] = s;
    __syncthreads();
    if (tid == 0) { float t = 0; for (int i = 0; i < 8; i++) t += sh[i]; sh[0] = t; }
    __syncthreads();
    float inv = 1.f / sh[0];
#pragma unroll
    for (int i = 0; i < 16; i++) {
        float p = v[i] * inv;
        __half h = __float2half_rn(p);
        Ph[base + tid + i * 256] = h;
        Pl[base + tid + i * 256] = __float2half_rn(p - __half2float(h));
    }
}

// ---- reduce partials + LN for Kc/Vc ----
__global__ __launch_bounds__(256) void compress_ln_kernel(
    const float* __restrict__ partK, const float* __restrict__ partV,
    const float* __restrict__ gamma, const float* __restrict__ beta,
    float* __restrict__ outK, float* __restrict__ outV)
{
    __shared__ float shs[8], shq[8];
    int bl = blockIdx.x, b = bl >> 5, l = bl & 31;
    const float* part = blockIdx.y ? partV : partK;
    float* out = blockIdx.y ? outV : outK;
    int tid = threadIdx.x, c = tid * 4;
    size_t base = ((size_t)(b * NH + (c >> 6)) * NL + l) * DHD + (c & 63);
    float4 acc = make_float4(0, 0, 0, 0);
#pragma unroll
    for (int sp = 0; sp < NSPLIT; sp++) {
        float4 p = *(const float4*)(part + (size_t)sp * CSIZE + base);
        acc.x += p.x; acc.y += p.y; acc.z += p.z; acc.w += p.w;
    }
    float s = acc.x + acc.y + acc.z + acc.w;
    float q = acc.x*acc.x + acc.y*acc.y + acc.z*acc.z + acc.w*acc.w;
    int lane = tid & 31, wid = tid >> 5;
#pragma unroll
    for (int o = 16; o; o >>= 1) {
        s += __shfl_xor_sync(~0u, s, o); q += __shfl_xor_sync(~0u, q, o);
    }
    if (lane == 0) { shs[wid] = s; shq[wid] = q; }
    __syncthreads();
    if (tid == 0) {
        float ts = 0, tq = 0;
        for (int i = 0; i < 8; i++) { ts += shs[i]; tq += shq[i]; }
        shs[0] = ts; shq[0] = tq;
    }
    __syncthreads();
    float mean = shs[0] * (1.f / DIM);
    float rstd = rsqrtf(shq[0] * (1.f / DIM) - mean * mean + 1e-5f);
    float4 g4 = ((const float4*)gamma)[tid], b4 = ((const float4*)beta)[tid];
    float4 o;
    o.x = (acc.x - mean) * rstd * g4.x + b4.x;
    o.y = (acc.y - mean) * rstd * g4.y + b4.y;
    o.z = (acc.z - mean) * rstd * g4.z + b4.z;
    o.w = (acc.w - mean) * rstd * g4.w + b4.w;
    *(float4*)(out + base) = o;
}

// ---- fused attention, 8 groups/block, float4 smem reads, fp16 hi/lo out ----
#define PADD 68
#define AT_KC 0
#define AT_VC (AT_KC + NL * PADD)
#define AT_KW (AT_VC + NL * PADD)
#define AT_VW (AT_KW + 72 * PADD)
#define AT_Q  (AT_VW + 72 * PADD)
#define AT_PR (AT_Q + 64 * PADD)
#define ATTN_FLOATS (AT_PR + 8 * 48)
#define ATTN_SMEM (ATTN_FLOATS * 4)

__global__ __launch_bounds__(256) void attn_kernel(
    const float* __restrict__ Q, const float* __restrict__ K,
    const float* __restrict__ V, const float* __restrict__ Kc,
    const float* __restrict__ Vc, __half* __restrict__ Ch, __half* __restrict__ Cl)
{
    extern __shared__ float sf[];
    int gblk = blockIdx.x, h = blockIdx.y, b = blockIdx.z;
    int bh = b * NH + h, tid = threadIdx.x;
    const int base = gblk * 64;

    {
        int l = tid >> 3, d0 = (tid & 7) * 8;
        size_t src = ((size_t)bh * NL + l) * DHD + d0;
        float4 k0 = *(const float4*)(Kc + src), k1 = *(const float4*)(Kc + src + 4);
        float4 v0 = *(const float4*)(Vc + src), v1 = *(const float4*)(Vc + src + 4);
        *(float4*)(sf + AT_KC + l * PADD + d0)     = k0;
        *(float4*)(sf + AT_KC + l * PADD + d0 + 4) = k1;
        *(float4*)(sf + AT_VC + l * PADD + d0)     = v0;
        *(float4*)(sf + AT_VC + l * PADD + d0 + 4) = v1;
    }
    for (int idx = tid; idx < 72 * 16; idx += 256) {
        int row = idx >> 4, d = (idx & 15) * 4;
        int sk = base - EE + row;
        float4 kv = make_float4(0,0,0,0), vv = make_float4(0,0,0,0);
        if (sk >= 0 && sk < SEQN) {
            size_t src = ((size_t)bh * SEQN + sk) * DHD + d;
            kv = *(const float4*)(K + src); vv = *(const float4*)(V + src);
        }
        *(float4*)(sf + AT_KW + row * PADD + d) = kv;
        *(float4*)(sf + AT_VW + row * PADD + d) = vv;
    }
    for (int idx = tid; idx < 64 * 16; idx += 256) {
        int row = idx >> 4, d = (idx & 15) * 4;
        *(float4*)(sf + AT_Q + row * PADD + d) =
            *(const float4*)(Q + ((size_t)bh * SEQN + base + row) * DHD + d);
    }
    __syncthreads();

    const int warp = tid >> 5, lane = tid & 31;
    const int k = lane & 15;
    const int wrow = warp * 8 + k;
    const int skg = base + warp * 8 + k - EE;
    const bool kvalid = (lane < BAND) && (skg >= 0) && (skg < SEQN);
    float* probs = sf + AT_PR + warp * 48;
    const float4* kcr = (const float4*)(sf + AT_KC + lane * PADD);
    const float4* kwr = (const float4*)(sf + AT_KW + wrow * PADD);

#pragma unroll 1
    for (int q = 0; q < 8; q++) {
        const float4* qr = (const float4*)(sf + AT_Q + (warp * 8 + q) * PADD);
        float sc = 0.f, sw = 0.f;
#pragma unroll
        for (int d4 = 0; d4 < 16; d4++) {
            float4 qv = qr[d4], kc = kcr[d4], kw = kwr[d4];
            sc += qv.x*kc.x + qv.y*kc.y + qv.z*kc.z + qv.w*kc.w;
            sw += qv.x*kw.x + qv.y*kw.y + qv.z*kw.z + qv.w*kw.w;
        }
        float m = fmaxf(sc, kvalid ? sw : -1e30f);
#pragma unroll
        for (int o = 16; o; o >>= 1) m = fmaxf(m, __shfl_xor_sync(~0u, m, o));
        float e0 = __expf(sc - m);
        float e1 = kvalid ? __expf(sw - m) : 0.f;
        float t = e0 + e1;
#pragma unroll
        for (int o = 16; o; o >>= 1) t += __shfl_xor_sync(~0u, t, o);
        float inv = 1.f / t;
        probs[lane] = e0 * inv;
        if (lane < BAND) probs[NL + lane] = e1 * inv;
        __syncwarp();

        float a0 = 0.f, a1 = 0.f;
#pragma unroll
        for (int j = 0; j < NL; j++) {
            float p = probs[j];
            a0 += p * sf[AT_VC + j * PADD + lane];
            a1 += p * sf[AT_VC + j * PADD + lane + 32];
        }
#pragma unroll
        for (int kk = 0; kk < BAND; kk++) {
            float p = probs[NL + kk];
            a0 += p * sf[AT_VW + (warp * 8 + kk) * PADD + lane];
            a1 += p * sf[AT_VW + (warp * 8 + kk) * PADD + lane + 32];
        }
        __syncwarp();

        size_t off = ((size_t)(b * SEQN) + base + warp * 8 + q) * DIM + h * DHD;
        __half h0 = __float2half_rn(a0), h1 = __float2half_rn(a1);
        Ch[off + lane] = h0;
        Ch[off + 32 + lane] = h1;
        Cl[off + lane] = __float2half_rn(a0 - __half2float(h0));
        Cl[off + 32 + lane] = __float2half_rn(a1 - __half2float(h1));
    }
}

// ===========================================================================
extern "C" void kernel_launch(void* const* d_in, const int* in_sizes, int n_in,
                              void* d_out, int out_size)
{
    (void)in_sizes; (void)n_in; (void)out_size;
    const float* query = (const float*)d_in[0];
    const float* Wq = (const float*)d_in[1];  const float* bq = (const float*)d_in[2];
    const float* Wk = (const float*)d_in[3];  const float* bk = (const float*)d_in[4];
    const float* Wv = (const float*)d_in[5];  const float* bv = (const float*)d_in[6];
    const float* Wo = (const float*)d_in[7];  const float* bo = (const float*)d_in[8];
    const float* gl = (const float*)d_in[9];  const float* bl = (const float*)d_in[10];
    const float* gs = (const float*)d_in[11]; const float* bs = (const float*)d_in[12];
    const float* Wd = (const float*)d_in[13]; const float* bd = (const float*)d_in[14];
    float* out = (float*)d_out;

    float *pQ,*pK,*pV,*pTmp,*pTv,*pD,*pP,*pKcP,*pVcP,*pKc,*pVc;
    __half *pXh,*pXl,*pCh,*pCl,*pWth,*pWtl,*pKhF,*pVhF,*pPh,*pPl;
    cudaGetSymbolAddress((void**)&pQ, g_Q);
    cudaGetSymbolAddress((void**)&pK, g_K);
    cudaGetSymbolAddress((void**)&pV, g_V);
    cudaGetSymbolAddress((void**)&pTmp, g_tmp);
    cudaGetSymbolAddress((void**)&pTv, g_tv);
    cudaGetSymbolAddress((void**)&pD, g_D);
    cudaGetSymbolAddress((void**)&pP, g_P);
    cudaGetSymbolAddress((void**)&pKcP, g_KcP);
    cudaGetSymbolAddress((void**)&pVcP, g_VcP);
    cudaGetSymbolAddress((void**)&pKc, g_Kc);
    cudaGetSymbolAddress((void**)&pVc, g_Vc);
    cudaGetSymbolAddress((void**)&pXh, g_Xh);
    cudaGetSymbolAddress((void**)&pXl, g_Xl);
    cudaGetSymbolAddress((void**)&pCh, g_Ch);
    cudaGetSymbolAddress((void**)&pCl, g_Cl);
    cudaGetSymbolAddress((void**)&pWth, g_Wth);
    cudaGetSymbolAddress((void**)&pWtl, g_Wtl);
    cudaGetSymbolAddress((void**)&pKhF, g_KhF);
    cudaGetSymbolAddress((void**)&pVhF, g_VhF);
    cudaGetSymbolAddress((void**)&pPh, g_Ph);
    cudaGetSymbolAddress((void**)&pPl, g_Pl);

    cudaFuncSetAttribute(hgemm_qkvd, cudaFuncAttributeMaxDynamicSharedMemorySize, GEMM_SMEM2);
    cudaFuncSetAttribute(hgemm_o, cudaFuncAttributeMaxDynamicSharedMemorySize, GEMM_SMEM2);
    cudaFuncSetAttribute(compress_hmma, cudaFuncAttributeMaxDynamicSharedMemorySize, COMP_SMEM);
    cudaFuncSetAttribute(attn_kernel, cudaFuncAttributeMaxDynamicSharedMemorySize, ATTN_SMEM);

    split_perm_kernel<<<MROWS * DIM / 4 / 256, 256>>>(query, pXh, pXl);
    wsplit_all_kernel<<<dim3(DIM / 32, DIM / 32, 5), dim3(32, 8)>>>(
        Wq, Wk, Wv, Wd, Wo, pWth, pWtl);

    hgemm_qkvd<<<dim3((3 * DIM + NH * NL) / 128, MROWS / 128), 256, GEMM_SMEM2>>>(
        pXh, pXl, pWth, pWtl, bq, bk, bv, bd, pQ, pTmp, pTv, pD);

    ln_split2_kernel<<<dim3(MROWS, 2), 256>>>(pTmp, pTv, gl, bl, pK, pV, pKhF, pVhF);

    transpose_kernel<<<dim3((NH * NL) / 32, SEQN / 32, BATCH), dim3(32, 8)>>>(pD, pP);
    softmax_rows_kernel<<<BATCH * NH * NL, 256>>>(pP, pPh, pPl);

    compress_hmma<<<dim3(BATCH * NH, NSPLIT), 256, COMP_SMEM>>>(
        pPh, pPl, pKhF, pVhF, pKcP, pVcP);
    compress_ln_kernel<<<dim3(BATCH * NL, 2), 256>>>(pKcP, pVcP, gs, bs, pKc, pVc);

    attn_kernel<<<dim3(NG / 8, NH, BATCH), 256, ATTN_SMEM>>>(pQ, pK, pV, pKc, pVc, pCh, pCl);

    hgemm_o<<<dim3(DIM / 128, MROWS / 128), 256, GEMM_SMEM2>>>(
        pCh, pCl, pWth + WOFF_O, pWtl + WOFF_O, bo, out);
}

// round 10
// speedup vs baseline: 4.0167x; 1.1102x over previous
#include <cuda_runtime.h>
#include <cuda_fp16.h>
#include <math.h>
#include <stdint.h>

#define SEQN  4096
#define BATCH 4
#define DIM   1024
#define NH    16
#define DHD   64
#define NL    32
#define WW    8
#define EE    4
#define BAND  16
#define NG    (SEQN / WW)
#define MROWS (BATCH * SEQN)
#define NSPLIT 8
#define CSIZE (BATCH * NH * NL * DHD)

__device__ float g_tmp[BATCH * SEQN * DIM];
__device__ float g_tv [BATCH * SEQN * DIM];
__device__ float g_D  [BATCH * SEQN * NH * NL];
__device__ float g_P  [BATCH * NH * NL * SEQN];
__device__ float g_KcP[NSPLIT * CSIZE];
__device__ float g_VcP[NSPLIT * CSIZE];

__device__ __align__(16) __half g_Xh[MROWS * DIM];
__device__ __align__(16) __half g_Xl[MROWS * DIM];
__device__ __align__(16) __half g_Ch[MROWS * DIM];
__device__ __align__(16) __half g_Cl[MROWS * DIM];
__device__ __align__(16) __half g_Qh[BATCH * NH * SEQN * DHD];
__device__ __align__(16) __half g_Ql[BATCH * NH * SEQN * DHD];
__device__ __align__(16) __half g_KhF[BATCH * NH * SEQN * DHD];
__device__ __align__(16) __half g_KlF[BATCH * NH * SEQN * DHD];
__device__ __align__(16) __half g_VhF[BATCH * NH * SEQN * DHD];
__device__ __align__(16) __half g_VlF[BATCH * NH * SEQN * DHD];
__device__ __align__(16) __half g_Ph [BATCH * NH * NL * SEQN];
__device__ __align__(16) __half g_Pl [BATCH * NH * NL * SEQN];
__device__ __align__(16) __half g_Kch[CSIZE];
__device__ __align__(16) __half g_Kcl[CSIZE];
__device__ __align__(16) __half g_Vch[CSIZE];
__device__ __align__(16) __half g_Vcl[CSIZE];
// weight rows: Q 0-1023, K 1024-2047, V 2048-3071, D 3072-3583, O 3584-4607
#define WOFF_O (3 * DIM * DIM + (NH * NL) * DIM)
#define WT_TOTAL (4 * DIM * DIM + (NH * NL) * DIM)
__device__ __align__(16) __half g_Wth[WT_TOTAL];
__device__ __align__(16) __half g_Wtl[WT_TOTAL];

// =========================== common asm helpers ============================
__device__ __forceinline__ uint32_t smem_u32(const void* p) {
    uint32_t a;
    asm("{ .reg .u64 t; cvta.to.shared.u64 t, %1; cvt.u32.u64 %0, t; }" : "=r"(a) : "l"(p));
    return a;
}
#define CPA(dst, src) \
    asm volatile("cp.async.cg.shared.global [%0], [%1], 16;" :: "r"(dst), "l"(src))
#define CP_COMMIT() asm volatile("cp.async.commit_group;")
#define CP_WAIT(n)  asm volatile("cp.async.wait_group %0;" :: "n"(n))
#define LDSM4(R, addr) \
    asm volatile("ldmatrix.sync.aligned.m8n8.x4.shared.b16 {%0,%1,%2,%3}, [%4];" \
        : "=r"((R)[0]), "=r"((R)[1]), "=r"((R)[2]), "=r"((R)[3]) : "r"(addr))
#define LDSM4T(R, addr) \
    asm volatile("ldmatrix.sync.aligned.m8n8.x4.trans.shared.b16 {%0,%1,%2,%3}, [%4];" \
        : "=r"((R)[0]), "=r"((R)[1]), "=r"((R)[2]), "=r"((R)[3]) : "r"(addr))
#define MMA16816(d, a, b0, b1) \
    asm volatile("mma.sync.aligned.m16n8k16.row.col.f32.f16.f16.f32 " \
        "{%0,%1,%2,%3}, {%4,%5,%6,%7}, {%8,%9}, {%0,%1,%2,%3};" \
        : "+f"((d)[0]), "+f"((d)[1]), "+f"((d)[2]), "+f"((d)[3]) \
        : "r"((a)[0]), "r"((a)[1]), "r"((a)[2]), "r"((a)[3]), "r"(b0), "r"(b1))

__device__ __forceinline__ uint32_t pack_h2(float lo, float hi) {
    __half2 h = __halves2half2(__float2half_rn(lo), __float2half_rn(hi));
    return *(uint32_t*)&h;
}

// =========================== HMMA GEMM core ================================
#define SROWB 80
#define TILEB (128 * SROWB)
#define NIT (DIM / 32)

template <int TERMS>
__device__ __forceinline__ void hgemm_main(
    const __half* Ah, const __half* Al, const __half* Bh, const __half* Bl,
    int bm, int bn, uint32_t sb, int tid, float acc[2][8][4])
{
    constexpr uint32_t STG = (TERMS + 1) * TILEB;
    const uint32_t oAH = 0, oAL = TILEB, oBH = 2 * TILEB, oBL = 3 * TILEB;

    const int lane = tid & 31, wid = tid >> 5;
    const int wm = wid & 3, wn = wid >> 2;
    const int lr0 = tid >> 2;
    const size_t aoff0 = ((size_t)(bm + lr0) << 10) + (size_t)(tid & 3) * 8;
    const size_t aoff1 = aoff0 + ((size_t)64 << 10);
    const size_t boff0 = ((size_t)(bn + lr0) << 10) + (size_t)(tid & 3) * 8;
    const size_t boff1 = boff0 + ((size_t)64 << 10);
    const uint32_t d0 = (uint32_t)lr0 * SROWB + (tid & 3) * 16;
    const uint32_t d1 = d0 + 64 * SROWB;

    CPA(sb + oAH + d0, Ah + aoff0); CPA(sb + oAH + d1, Ah + aoff1);
    CPA(sb + oAL + d0, Al + aoff0); CPA(sb + oAL + d1, Al + aoff1);
    CPA(sb + oBH + d0, Bh + boff0); CPA(sb + oBH + d1, Bh + boff1);
    if (TERMS == 3) { CPA(sb + oBL + d0, Bl + boff0); CPA(sb + oBL + d1, Bl + boff1); }
    CP_COMMIT();

#pragma unroll
    for (int i = 0; i < 2; i++)
#pragma unroll
        for (int j = 0; j < 8; j++)
#pragma unroll
            for (int k = 0; k < 4; k++) acc[i][j][k] = 0.f;

    const uint32_t aBase = (uint32_t)(wm * 32 + (lane & 15)) * SROWB + (lane >> 4) * 16;
    const uint32_t bBase = (uint32_t)(wn * 64 + ((lane >> 4) & 1) * 8 + (lane & 7)) * SROWB
                           + ((lane >> 3) & 1) * 16;

    for (int it = 0; it < NIT; it++) {
        const uint32_t ps = (it & 1) * STG;
        if (it + 1 < NIT) {
            const uint32_t ns = ((it + 1) & 1) * STG;
            const int kb = (it + 1) * 32;
            CPA(sb + ns + oAH + d0, Ah + aoff0 + kb); CPA(sb + ns + oAH + d1, Ah + aoff1 + kb);
            CPA(sb + ns + oAL + d0, Al + aoff0 + kb); CPA(sb + ns + oAL + d1, Al + aoff1 + kb);
            CPA(sb + ns + oBH + d0, Bh + boff0 + kb); CPA(sb + ns + oBH + d1, Bh + boff1 + kb);
            if (TERMS == 3) {
                CPA(sb + ns + oBL + d0, Bl + boff0 + kb); CPA(sb + ns + oBL + d1, Bl + boff1 + kb);
            }
            CP_COMMIT();
            CP_WAIT(1);
        } else {
            CP_WAIT(0);
        }
        __syncthreads();

        const uint32_t sAH = sb + ps + oAH + aBase, sAL = sb + ps + oAL + aBase;
        const uint32_t sBH = sb + ps + oBH + bBase, sBL = sb + ps + oBL + bBase;
#pragma unroll
        for (int ks = 0; ks < 2; ks++) {
            const uint32_t ko = ks * 32;
            uint32_t ah[2][4], al[2][4];
            LDSM4(ah[0], sAH + ko);
            LDSM4(ah[1], sAH + ko + 16 * SROWB);
            LDSM4(al[0], sAL + ko);
            LDSM4(al[1], sAL + ko + 16 * SROWB);
#pragma unroll
            for (int q = 0; q < 4; q++) {
                uint32_t bh[4];
                LDSM4(bh, sBH + ko + q * 16 * SROWB);
                if (TERMS == 3) {
                    uint32_t bl[4];
                    LDSM4(bl, sBL + ko + q * 16 * SROWB);
#pragma unroll
                    for (int mt = 0; mt < 2; mt++) {
                        MMA16816(acc[mt][2 * q + 0], ah[mt], bh[0], bh[1]);
                        MMA16816(acc[mt][2 * q + 0], ah[mt], bl[0], bl[1]);
                        MMA16816(acc[mt][2 * q + 0], al[mt], bh[0], bh[1]);
                        MMA16816(acc[mt][2 * q + 1], ah[mt], bh[2], bh[3]);
                        MMA16816(acc[mt][2 * q + 1], ah[mt], bl[2], bl[3]);
                        MMA16816(acc[mt][2 * q + 1], al[mt], bh[2], bh[3]);
                    }
                } else {
#pragma unroll
                    for (int mt = 0; mt < 2; mt++) {
                        MMA16816(acc[mt][2 * q + 0], ah[mt], bh[0], bh[1]);
                        MMA16816(acc[mt][2 * q + 0], al[mt], bh[0], bh[1]);
                        MMA16816(acc[mt][2 * q + 1], ah[mt], bh[2], bh[3]);
                        MMA16816(acc[mt][2 * q + 1], al[mt], bh[2], bh[3]);
                    }
                }
            }
        }
        __syncthreads();
    }
}
#define GEMM_SMEM2 (2 * 3 * TILEB)

// ---- fused Q/K/V/D GEMM (2-term); Q emitted as fp16 hi/lo ----
__global__ __launch_bounds__(256, 2) void hgemm_qkvd(
    const __half* __restrict__ Ah, const __half* __restrict__ Al,
    const __half* __restrict__ Bh, const __half* __restrict__ Bl,
    const float* __restrict__ bq, const float* __restrict__ bk,
    const float* __restrict__ bv, const float* __restrict__ bd,
    __half* __restrict__ outQh, __half* __restrict__ outQl,
    float* __restrict__ outK, float* __restrict__ outV, float* __restrict__ outD)
{
    extern __shared__ __align__(16) char smem[];
    const uint32_t sb = smem_u32(smem);
    const int tid = threadIdx.x, wid = tid >> 5, lane = tid & 31;
    const int bn = blockIdx.x * 128, bm = blockIdx.y * 128;
    float acc[2][8][4];
    hgemm_main<2>(Ah, Al, Bh, Bl, bm, bn, sb, tid, acc);

    const int seg = bn >> 10;
    const int cl = bn & 1023;
    const float* bias = seg == 0 ? bq : seg == 1 ? bk : seg == 2 ? bv : bd;
    const float scale = seg == 0 ? 0.125f : 1.f;
    const int wm = wid & 3, wn = wid >> 2;
    const int r0 = bm + wm * 32 + (lane >> 2);
    const int c0 = cl + wn * 64 + (lane & 3) * 2;
#pragma unroll
    for (int mt = 0; mt < 2; mt++) {
#pragma unroll
        for (int hf = 0; hf < 2; hf++) {
            const int r = r0 + mt * 16 + hf * 8;
            const int bb = r >> 12, ss = r & (SEQN - 1);
#pragma unroll
            for (int nt = 0; nt < 8; nt++) {
                const int col = c0 + nt * 8;
                const float2 bv2 = *(const float2*)(bias + col);
                float vx = (acc[mt][nt][hf * 2 + 0] + bv2.x) * scale;
                float vy = (acc[mt][nt][hf * 2 + 1] + bv2.y) * scale;
                if (seg == 0) {
                    size_t o = ((size_t)(bb * NH + (col >> 6)) * SEQN + ss) * DHD + (col & 63);
                    __half hx = __float2half_rn(vx), hy = __float2half_rn(vy);
                    *(__half2*)(outQh + o) = __halves2half2(hx, hy);
                    *(__half2*)(outQl + o) = __halves2half2(
                        __float2half_rn(vx - __half2float(hx)),
                        __float2half_rn(vy - __half2float(hy)));
                } else {
                    float* op; size_t o;
                    if (seg == 1)      { op = outK; o = (size_t)r * DIM + col; }
                    else if (seg == 2) { op = outV; o = (size_t)r * DIM + col; }
                    else               { op = outD; o = (size_t)r * (NH * NL) + col; }
                    *(float2*)(op + o) = make_float2(vx, vy);
                }
            }
        }
    }
}

// ---- output GEMM (2-term): out = C @ Wo + bo, (s,b,DIM) ----
__global__ __launch_bounds__(256, 2) void hgemm_o(
    const __half* __restrict__ Ah, const __half* __restrict__ Al,
    const __half* __restrict__ Bh, const __half* __restrict__ Bl,
    const float* __restrict__ bias, float* __restrict__ out)
{
    extern __shared__ __align__(16) char smem[];
    const uint32_t sb = smem_u32(smem);
    const int tid = threadIdx.x, wid = tid >> 5, lane = tid & 31;
    const int bn = blockIdx.x * 128, bm = blockIdx.y * 128;
    float acc[2][8][4];
    hgemm_main<2>(Ah, Al, Bh, Bl, bm, bn, sb, tid, acc);

    const int wm = wid & 3, wn = wid >> 2;
    const int r0 = bm + wm * 32 + (lane >> 2);
    const int c0 = bn + wn * 64 + (lane & 3) * 2;
#pragma unroll
    for (int mt = 0; mt < 2; mt++) {
#pragma unroll
        for (int hf = 0; hf < 2; hf++) {
            const int r = r0 + mt * 16 + hf * 8;
            const int bb = r >> 12, ss = r & (SEQN - 1);
#pragma unroll
            for (int nt = 0; nt < 8; nt++) {
                const int col = c0 + nt * 8;
                const float2 bv2 = *(const float2*)(bias + col);
                *(float2*)(out + ((size_t)ss * BATCH + bb) * DIM + col) =
                    make_float2(acc[mt][nt][hf * 2 + 0] + bv2.x,
                                acc[mt][nt][hf * 2 + 1] + bv2.y);
            }
        }
    }
}

// ================= HMMA compress: Kc/Vc partials ===========================
#define CPROW 144
#define CPS_PH 0
#define CPS_PL (32 * CPROW)
#define CPS_K  (64 * CPROW)
#define CPS_V  (128 * CPROW)
#define CP_STG (192 * CPROW)
#define COMP_SMEM (2 * CP_STG)

__global__ __launch_bounds__(256, 2) void compress_hmma(
    const __half* __restrict__ Ph, const __half* __restrict__ Pl,
    const __half* __restrict__ Kh, const __half* __restrict__ Vh,
    float* __restrict__ partK, float* __restrict__ partV)
{
    extern __shared__ __align__(16) char smem[];
    const uint32_t sb = smem_u32(smem);
    const int bh = blockIdx.x, sp = blockIdx.y;
    const int b = bh >> 4, h = bh & 15;
    const int tid = threadIdx.x, lane = tid & 31, wid = tid >> 5;

    const size_t pbase = ((size_t)(b * (NH * NL) + h * NL)) * SEQN + sp * 512;
    const size_t kbase = ((size_t)bh * SEQN + sp * 512) * DHD;

    const int prow = tid >> 3, pseg = tid & 7;
    const uint32_t pDst = prow * CPROW + pseg * 16;
    const size_t pSrc = (size_t)prow * SEQN + pseg * 8;
    const uint32_t kDst0 = prow * CPROW + pseg * 16;
    const uint32_t kDst1 = (prow + 32) * CPROW + pseg * 16;
    const size_t kSrc0 = (size_t)prow * DHD + pseg * 8;
    const size_t kSrc1 = (size_t)(prow + 32) * DHD + pseg * 8;

    CPA(sb + CPS_PH + pDst, Ph + pbase + pSrc);
    CPA(sb + CPS_PL + pDst, Pl + pbase + pSrc);
    CPA(sb + CPS_K + kDst0, Kh + kbase + kSrc0);
    CPA(sb + CPS_K + kDst1, Kh + kbase + kSrc1);
    CPA(sb + CPS_V + kDst0, Vh + kbase + kSrc0);
    CPA(sb + CPS_V + kDst1, Vh + kbase + kSrc1);
    CP_COMMIT();

    float acc[4][4];
#pragma unroll
    for (int i = 0; i < 4; i++)
#pragma unroll
        for (int j = 0; j < 4; j++) acc[i][j] = 0.f;

    const int outv = wid >> 2;
    const int mt = wid & 1, nh2 = (wid >> 1) & 1;
    const uint32_t aOff = (uint32_t)(mt * 16 + (lane & 15)) * CPROW + (lane >> 4) * 16;
    const uint32_t bRow = (lane & 7) + ((lane >> 3) & 1) * 8;
    const uint32_t bCol = ((lane >> 4) & 1) * 16 + nh2 * 64;
    const uint32_t kvOff = outv ? CPS_V : CPS_K;

    for (int c = 0; c < 8; c++) {
        const uint32_t ps = (c & 1) * CP_STG;
        if (c + 1 < 8) {
            const uint32_t ns = ((c + 1) & 1) * CP_STG;
            const int so = (c + 1) * 64;
            CPA(sb + ns + CPS_PH + pDst, Ph + pbase + so + pSrc);
            CPA(sb + ns + CPS_PL + pDst, Pl + pbase + so + pSrc);
            CPA(sb + ns + CPS_K + kDst0, Kh + kbase + (size_t)so * DHD + kSrc0);
            CPA(sb + ns + CPS_K + kDst1, Kh + kbase + (size_t)so * DHD + kSrc1);
            CPA(sb + ns + CPS_V + kDst0, Vh + kbase + (size_t)so * DHD + kSrc0);
            CPA(sb + ns + CPS_V + kDst1, Vh + kbase + (size_t)so * DHD + kSrc1);
            CP_COMMIT();
            CP_WAIT(1);
        } else {
            CP_WAIT(0);
        }
        __syncthreads();

        const uint32_t sP0 = sb + ps + CPS_PH + aOff;
        const uint32_t sP1 = sb + ps + CPS_PL + aOff;
        const uint32_t sKV = sb + ps + kvOff;
#pragma unroll
        for (int ks = 0; ks < 4; ks++) {
            uint32_t ah[4], al[4], b0[4], b1[4];
            LDSM4(ah, sP0 + ks * 32);
            LDSM4(al, sP1 + ks * 32);
            const uint32_t ba = sKV + (ks * 16 + bRow) * CPROW + bCol;
            LDSM4T(b0, ba);
            LDSM4T(b1, ba + 32);
            MMA16816(acc[0], ah, b0[0], b0[1]);
            MMA16816(acc[0], al, b0[0], b0[1]);
            MMA16816(acc[1], ah, b0[2], b0[3]);
            MMA16816(acc[1], al, b0[2], b0[3]);
            MMA16816(acc[2], ah, b1[0], b1[1]);
            MMA16816(acc[2], al, b1[0], b1[1]);
            MMA16816(acc[3], ah, b1[2], b1[3]);
            MMA16816(acc[3], al, b1[2], b1[3]);
        }
        __syncthreads();
    }

    float* outp = outv ? partV : partK;
    const size_t ob = (size_t)sp * CSIZE + (size_t)bh * NL * DHD;
    const int l0 = mt * 16 + (lane >> 2);
    const int db = nh2 * 32 + (lane & 3) * 2;
#pragma unroll
    for (int nt = 0; nt < 4; nt++) {
        const int d = db + nt * 8;
        *(float2*)(outp + ob + (size_t)l0 * DHD + d) = make_float2(acc[nt][0], acc[nt][1]);
        *(float2*)(outp + ob + (size_t)(l0 + 8) * DHD + d) = make_float2(acc[nt][2], acc[nt][3]);
    }
}

// ---- fp32 -> fp16 hi/lo split with (s,b)->(b,s) permute ----
__global__ __launch_bounds__(256) void split_perm_kernel(
    const float* __restrict__ X, __half* __restrict__ H, __half* __restrict__ L)
{
    int i = blockIdx.x * 256 + threadIdx.x;
    int r = i >> 8, k4 = i & 255;
    int b = r >> 12, s = r & (SEQN - 1);
    float4 v = *((const float4*)X + ((size_t)s * BATCH + b) * 256 + k4);
    __half h0 = __float2half_rn(v.x), h1 = __float2half_rn(v.y);
    __half h2 = __float2half_rn(v.z), h3 = __float2half_rn(v.w);
    __half2* Hp = (__half2*)(H + (size_t)i * 4);
    __half2* Lp = (__half2*)(L + (size_t)i * 4);
    Hp[0] = __halves2half2(h0, h1); Hp[1] = __halves2half2(h2, h3);
    Lp[0] = __halves2half2(__float2half_rn(v.x - __half2float(h0)),
                           __float2half_rn(v.y - __half2float(h1)));
    Lp[1] = __halves2half2(__float2half_rn(v.z - __half2float(h2)),
                           __float2half_rn(v.w - __half2float(h3)));
}

// ---- all 5 weight transposes + splits in one launch ----
__global__ void wsplit_all_kernel(
    const float* __restrict__ Wq, const float* __restrict__ Wk,
    const float* __restrict__ Wv, const float* __restrict__ Wd,
    const float* __restrict__ Wo, __half* __restrict__ Th, __half* __restrict__ Tl)
{
    __shared__ float t[32][33];
    int z = blockIdx.z;
    int N = (z == 3) ? (NH * NL) : DIM;
    if (blockIdx.x * 32 >= N) return;
    const float* W = z == 0 ? Wq : z == 1 ? Wk : z == 2 ? Wv : z == 3 ? Wd : Wo;
    size_t woff = z <= 3 ? (size_t)z * DIM * DIM : (size_t)WOFF_O;
    int n0 = blockIdx.x * 32, k0 = blockIdx.y * 32;
    int x = threadIdx.x, y = threadIdx.y;
#pragma unroll
    for (int i = 0; i < 32; i += 8)
        t[y + i][x] = W[(size_t)(k0 + y + i) * N + n0 + x];
    __syncthreads();
#pragma unroll
    for (int i = 0; i < 32; i += 8) {
        float v = t[x][y + i];
        __half h = __float2half_rn(v);
        size_t o = woff + (size_t)(n0 + y + i) * DIM + k0 + x;
        Th[o] = h;
        Tl[o] = __float2half_rn(v - __half2float(h));
    }
}

// ---- LayerNorm over DIM, head-split; fp16 hi/lo outputs only ----
__global__ __launch_bounds__(256) void ln_split2_kernel(
    const float* __restrict__ XK, const float* __restrict__ XV,
    const float* __restrict__ gamma, const float* __restrict__ beta,
    __half* __restrict__ oKh, __half* __restrict__ oKl,
    __half* __restrict__ oVh, __half* __restrict__ oVl)
{
    __shared__ float shs[8], shq[8];
    int r = blockIdx.x, tid = threadIdx.x;
    const float* X = blockIdx.y ? XV : XK;
    __half* outh = blockIdx.y ? oVh : oKh;
    __half* outl = blockIdx.y ? oVl : oKl;
    const float4 v = ((const float4*)(X + (size_t)r * DIM))[tid];
    float s = v.x + v.y + v.z + v.w;
    float q = v.x*v.x + v.y*v.y + v.z*v.z + v.w*v.w;
    int lane = tid & 31, wid = tid >> 5;
#pragma unroll
    for (int o = 16; o; o >>= 1) {
        s += __shfl_xor_sync(~0u, s, o); q += __shfl_xor_sync(~0u, q, o);
    }
    if (lane == 0) { shs[wid] = s; shq[wid] = q; }
    __syncthreads();
    if (tid == 0) {
        float ts = 0, tq = 0;
        for (int i = 0; i < 8; i++) { ts += shs[i]; tq += shq[i]; }
        shs[0] = ts; shq[0] = tq;
    }
    __syncthreads();
    float mean = shs[0] * (1.f / DIM);
    float rstd = rsqrtf(shq[0] * (1.f / DIM) - mean * mean + 1e-5f);
    int c = tid * 4;
    float4 g4 = ((const float4*)gamma)[tid], b4 = ((const float4*)beta)[tid];
    float o0 = (v.x - mean) * rstd * g4.x + b4.x;
    float o1 = (v.y - mean) * rstd * g4.y + b4.y;
    float o2 = (v.z - mean) * rstd * g4.z + b4.z;
    float o3 = (v.w - mean) * rstd * g4.w + b4.w;
    int b = r >> 12, sq = r & (SEQN - 1);
    size_t base = ((size_t)(b * NH + (c >> 6)) * SEQN + sq) * DHD + (c & 63);
    __half h0 = __float2half_rn(o0), h1 = __float2half_rn(o1);
    __half h2 = __float2half_rn(o2), h3 = __float2half_rn(o3);
    __half2* hp = (__half2*)(outh + base);
    hp[0] = __halves2half2(h0, h1); hp[1] = __halves2half2(h2, h3);
    __half2* lp = (__half2*)(outl + base);
    lp[0] = __halves2half2(__float2half_rn(o0 - __half2float(h0)),
                           __float2half_rn(o1 - __half2float(h1)));
    lp[1] = __halves2half2(__float2half_rn(o2 - __half2float(h2)),
                           __float2half_rn(o3 - __half2float(h3)));
}

// ---- transpose (b,s,512) -> (b,512,s) ----
__global__ void transpose_kernel(const float* __restrict__ D, float* __restrict__ P)
{
    __shared__ float t[32][33];
    int b = blockIdx.z, c0 = blockIdx.x * 32, s0 = blockIdx.y * 32;
    int x = threadIdx.x, y = threadIdx.y;
    const float* Db = D + (size_t)b * SEQN * (NH * NL);
    float* Pb = P + (size_t)b * (NH * NL) * SEQN;
#pragma unroll
    for (int i = 0; i < 32; i += 8)
        t[y + i][x] = Db[(size_t)(s0 + y + i) * (NH * NL) + c0 + x];
    __syncthreads();
#pragma unroll
    for (int i = 0; i < 32; i += 8)
        Pb[(size_t)(c0 + y + i) * SEQN + s0 + x] = t[x][y + i];
}

// ---- row softmax over 4096; emits fp16 hi/lo probs ----
__global__ __launch_bounds__(256) void softmax_rows_kernel(
    const float* __restrict__ P, __half* __restrict__ Ph, __half* __restrict__ Pl)
{
    __shared__ float sh[8];
    size_t base = (size_t)blockIdx.x * SEQN;
    int tid = threadIdx.x, lane = tid & 31, wid = tid >> 5;
    float v[16], m = -1e30f;
#pragma unroll
    for (int i = 0; i < 16; i++) { v[i] = P[base + tid + i * 256]; m = fmaxf(m, v[i]); }
#pragma unroll
    for (int o = 16; o; o >>= 1) m = fmaxf(m, __shfl_xor_sync(~0u, m, o));
    if (lane == 0) sh[wid] = m;
    __syncthreads();
    if (tid == 0) { float t = sh[0]; for (int i = 1; i < 8; i++) t = fmaxf(t, sh[i]); sh[0] = t; }
    __syncthreads();
    float M = sh[0];
    __syncthreads();
    float s = 0.f;
#pragma unroll
    for (int i = 0; i < 16; i++) { v[i] = __expf(v[i] - M); s += v[i]; }
#pragma unroll
    for (int o = 16; o; o >>= 1) s += __shfl_xor_sync(~0u, s, o);
    if (lane == 0) sh[wid] = s;
    __syncthreads();
    if (tid == 0) { float t = 0; for (int i = 0; i < 8; i++) t += sh[i]; sh[0] = t; }
    __syncthreads();
    float inv = 1.f / sh[0];
#pragma unroll
    for (int i = 0; i < 16; i++) {
        float p = v[i] * inv;
        __half h = __float2half_rn(p);
        Ph[base + tid + i * 256] = h;
        Pl[base + tid + i * 256] = __float2half_rn(p - __half2float(h));
    }
}

// ---- reduce partials + LN for Kc/Vc; fp16 hi/lo outputs ----
__global__ __launch_bounds__(256) void compress_ln_kernel(
    const float* __restrict__ partK, const float* __restrict__ partV,
    const float* __restrict__ gamma, const float* __restrict__ beta,
    __half* __restrict__ oKh, __half* __restrict__ oKl,
    __half* __restrict__ oVh, __half* __restrict__ oVl)
{
    __shared__ float shs[8], shq[8];
    int bl = blockIdx.x, b = bl >> 5, l = bl & 31;
    const float* part = blockIdx.y ? partV : partK;
    __half* outh = blockIdx.y ? oVh : oKh;
    __half* outl = blockIdx.y ? oVl : oKl;
    int tid = threadIdx.x, c = tid * 4;
    size_t base = ((size_t)(b * NH + (c >> 6)) * NL + l) * DHD + (c & 63);
    float4 acc = make_float4(0, 0, 0, 0);
#pragma unroll
    for (int sp = 0; sp < NSPLIT; sp++) {
        float4 p = *(const float4*)(part + (size_t)sp * CSIZE + base);
        acc.x += p.x; acc.y += p.y; acc.z += p.z; acc.w += p.w;
    }
    float s = acc.x + acc.y + acc.z + acc.w;
    float q = acc.x*acc.x + acc.y*acc.y + acc.z*acc.z + acc.w*acc.w;
    int lane = tid & 31, wid = tid >> 5;
#pragma unroll
    for (int o = 16; o; o >>= 1) {
        s += __shfl_xor_sync(~0u, s, o); q += __shfl_xor_sync(~0u, q, o);
    }
    if (lane == 0) { shs[wid] = s; shq[wid] = q; }
    __syncthreads();
    if (tid == 0) {
        float ts = 0, tq = 0;
        for (int i = 0; i < 8; i++) { ts += shs[i]; tq += shq[i]; }
        shs[0] = ts; shq[0] = tq;
    }
    __syncthreads();
    float mean = shs[0] * (1.f / DIM);
    float rstd = rsqrtf(shq[0] * (1.f / DIM) - mean * mean + 1e-5f);
    float4 g4 = ((const float4*)gamma)[tid], b4 = ((const float4*)beta)[tid];
    float o0 = (acc.x - mean) * rstd * g4.x + b4.x;
    float o1 = (acc.y - mean) * rstd * g4.y + b4.y;
    float o2 = (acc.z - mean) * rstd * g4.z + b4.z;
    float o3 = (acc.w - mean) * rstd * g4.w + b4.w;
    __half h0 = __float2half_rn(o0), h1 = __float2half_rn(o1);
    __half h2 = __float2half_rn(o2), h3 = __float2half_rn(o3);
    __half2* hp = (__half2*)(outh + base);
    hp[0] = __halves2half2(h0, h1); hp[1] = __halves2half2(h2, h3);
    __half2* lp = (__half2*)(outl + base);
    lp[0] = __halves2half2(__float2half_rn(o0 - __half2float(h0)),
                           __float2half_rn(o1 - __half2float(h1)));
    lp[1] = __halves2half2(__float2half_rn(o2 - __half2float(h2)),
                           __float2half_rn(o3 - __half2float(h3)));
}

// ================= HMMA attention ==========================================
// Block: 64 queries x (b,h). Scores S[64 x 112] = Q @ [Kc(32); Kwin(80)]^T
// (3-term hi/lo), band+seq masking in fragments, row softmax via 4-lane
// shuffles, then C = P @ [Vc; Vwin] (3-term). 4 warps, each m16 rows.
#define AROWB 144                      // 64 halves + 16B pad
#define AS_QH 0
#define AS_QL (64 * AROWB)
#define AS_KH (128 * AROWB)
#define AS_KL (240 * AROWB)
#define AS_VH (352 * AROWB)
#define AS_VL (464 * AROWB)
#define ATTN_SMEM (576 * AROWB)        // 82944 B

__global__ __launch_bounds__(128) void attn_hmma(
    const __half* __restrict__ Qh, const __half* __restrict__ Ql,
    const __half* __restrict__ Kh, const __half* __restrict__ Kl,
    const __half* __restrict__ Vh, const __half* __restrict__ Vl,
    const __half* __restrict__ Kch, const __half* __restrict__ Kcl,
    const __half* __restrict__ Vch, const __half* __restrict__ Vcl,
    __half* __restrict__ Ch, __half* __restrict__ Cl)
{
    extern __shared__ __align__(16) char smem[];
    const uint32_t sb = smem_u32(smem);
    const int h = blockIdx.y, bb = blockIdx.z;
    const int bh = bb * NH + h;
    const int qbase = blockIdx.x * 64;
    const int tid = threadIdx.x, lane = tid & 31, warp = tid >> 5;

    // fill K/V (rows 0-31 compressed, 32-111 window), zero OOB
    for (int idx = tid; idx < 112 * 8; idx += 128) {
        const int row = idx >> 3, seg = idx & 7;
        const uint32_t dst = row * AROWB + seg * 16;
        uint4 kh4 = {0,0,0,0}, kl4 = {0,0,0,0}, vh4 = {0,0,0,0}, vl4 = {0,0,0,0};
        if (row < 32) {
            size_t src = ((size_t)bh * NL + row) * DHD + seg * 8;
            kh4 = *(const uint4*)(Kch + src); kl4 = *(const uint4*)(Kcl + src);
            vh4 = *(const uint4*)(Vch + src); vl4 = *(const uint4*)(Vcl + src);
        } else {
            const int seq = qbase - EE + (row - 32);
            if (seq >= 0 && seq < SEQN) {
                size_t src = ((size_t)bh * SEQN + seq) * DHD + seg * 8;
                kh4 = *(const uint4*)(Kh + src); kl4 = *(const uint4*)(Kl + src);
                vh4 = *(const uint4*)(Vh + src); vl4 = *(const uint4*)(Vl + src);
            }
        }
        *(uint4*)(smem + AS_KH + dst) = kh4;
        *(uint4*)(smem + AS_KL + dst) = kl4;
        *(uint4*)(smem + AS_VH + dst) = vh4;
        *(uint4*)(smem + AS_VL + dst) = vl4;
    }
    for (int idx = tid; idx < 64 * 8; idx += 128) {
        const int row = idx >> 3, seg = idx & 7;
        const uint32_t dst = row * AROWB + seg * 16;
        size_t src = ((size_t)bh * SEQN + qbase + row) * DHD + seg * 8;
        *(uint4*)(smem + AS_QH + dst) = *(const uint4*)(Qh + src);
        *(uint4*)(smem + AS_QL + dst) = *(const uint4*)(Ql + src);
    }
    __syncthreads();

    // ---- scores: 14 n8 tiles x m16 ----
    const int r0 = warp * 16;
    float sacc[14][4];
#pragma unroll
    for (int j = 0; j < 14; j++)
#pragma unroll
        for (int e = 0; e < 4; e++) sacc[j][e] = 0.f;

    const uint32_t aOff = (uint32_t)(r0 + (lane & 15)) * AROWB + (lane >> 4) * 16;
    const uint32_t bOffS = (uint32_t)(((lane >> 4) & 1) * 8 + (lane & 7)) * AROWB
                           + ((lane >> 3) & 1) * 16;
#pragma unroll
    for (int ks = 0; ks < 4; ks++) {
        uint32_t ah[4], al[4];
        LDSM4(ah, sb + AS_QH + aOff + ks * 32);
        LDSM4(al, sb + AS_QL + aOff + ks * 32);
#pragma unroll
        for (int i = 0; i < 7; i++) {
            const uint32_t bo = bOffS + (uint32_t)(i * 16) * AROWB + ks * 32;
            uint32_t bh4[4], bl4[4];
            LDSM4(bh4, sb + AS_KH + bo);
            LDSM4(bl4, sb + AS_KL + bo);
            MMA16816(sacc[2*i+0], ah, bh4[0], bh4[1]);
            MMA16816(sacc[2*i+0], al, bh4[0], bh4[1]);
            MMA16816(sacc[2*i+0], ah, bl4[0], bl4[1]);
            MMA16816(sacc[2*i+1], ah, bh4[2], bh4[3]);
            MMA16816(sacc[2*i+1], al, bh4[2], bh4[3]);
            MMA16816(sacc[2*i+1], ah, bl4[2], bl4[3]);
        }
    }

    // ---- mask + softmax (rows ra = r0+(lane>>2), rb = ra+8) ----
    const int ra = r0 + (lane >> 2), rb = ra + 8;
    const int ga = ra >> 3, gb = rb >> 3;
    float mxa = -1e30f, mxb = -1e30f;
    bool vld[14][4];
#pragma unroll
    for (int j = 0; j < 14; j++) {
#pragma unroll
        for (int e = 0; e < 2; e++) {
            const int col = j * 8 + (lane & 3) * 2 + e;
            bool va, vb;
            if (col < 32) { va = true; vb = true; }
            else {
                const int w = col - 32;
                const int seq = qbase - EE + w;
                const bool sv = (seq >= 0) && (seq < SEQN);
                va = sv && (w >= ga * 8) && (w < ga * 8 + BAND);
                vb = sv && (w >= gb * 8) && (w < gb * 8 + BAND);
            }
            vld[j][e] = va; vld[j][2 + e] = vb;
            if (va) mxa = fmaxf(mxa, sacc[j][e]);
            if (vb) mxb = fmaxf(mxb, sacc[j][2 + e]);
        }
    }
#pragma unroll
    for (int o = 1; o <= 2; o <<= 1) {
        mxa = fmaxf(mxa, __shfl_xor_sync(~0u, mxa, o));
        mxb = fmaxf(mxb, __shfl_xor_sync(~0u, mxb, o));
    }
    float sma = 0.f, smb = 0.f;
#pragma unroll
    for (int j = 0; j < 14; j++) {
#pragma unroll
        for (int e = 0; e < 2; e++) {
            float pa = vld[j][e]     ? __expf(sacc[j][e]     - mxa) : 0.f;
            float pb = vld[j][2 + e] ? __expf(sacc[j][2 + e] - mxb) : 0.f;
            sacc[j][e] = pa; sacc[j][2 + e] = pb;
            sma += pa; smb += pb;
        }
    }
#pragma unroll
    for (int o = 1; o <= 2; o <<= 1) {
        sma += __shfl_xor_sync(~0u, sma, o);
        smb += __shfl_xor_sync(~0u, smb, o);
    }
    const float iva = 1.f / sma, ivb = 1.f / smb;
#pragma unroll
    for (int j = 0; j < 14; j++) {
        sacc[j][0] *= iva; sacc[j][1] *= iva;
        sacc[j][2] *= ivb; sacc[j][3] *= ivb;
    }

    // ---- PV: C[16 x 64] += P[16 x 112] @ V'[112 x 64], 3-term ----
    float pacc[8][4];
#pragma unroll
    for (int i = 0; i < 8; i++)
#pragma unroll
        for (int e = 0; e < 4; e++) pacc[i][e] = 0.f;

    const uint32_t bRowV = (uint32_t)((lane & 7) + ((lane >> 3) & 1) * 8);
    const uint32_t bColV = ((lane >> 4) & 1) * 16;
#pragma unroll
    for (int ks = 0; ks < 7; ks++) {
        const int j0 = 2 * ks, j1 = 2 * ks + 1;
        uint32_t Pf[4], Pr[4];
        {
            float a0 = sacc[j0][0], a1 = sacc[j0][1];
            float b0 = sacc[j0][2], b1 = sacc[j0][3];
            float c0 = sacc[j1][0], c1 = sacc[j1][1];
            float d0 = sacc[j1][2], d1 = sacc[j1][3];
            Pf[0] = pack_h2(a0, a1); Pf[1] = pack_h2(b0, b1);
            Pf[2] = pack_h2(c0, c1); Pf[3] = pack_h2(d0, d1);
            Pr[0] = pack_h2(a0 - __half2float(__float2half_rn(a0)),
                            a1 - __half2float(__float2half_rn(a1)));
            Pr[1] = pack_h2(b0 - __half2float(__float2half_rn(b0)),
                            b1 - __half2float(__float2half_rn(b1)));
            Pr[2] = pack_h2(c0 - __half2float(__float2half_rn(c0)),
                            c1 - __half2float(__float2half_rn(c1)));
            Pr[3] = pack_h2(d0 - __half2float(__float2half_rn(d0)),
                            d1 - __half2float(__float2half_rn(d1)));
        }
        const uint32_t vbase = (uint32_t)(ks * 16 + bRowV) * AROWB + bColV;
#pragma unroll
        for (int m = 0; m < 4; m++) {
            uint32_t bvh[4], bvl[4];
            LDSM4T(bvh, sb + AS_VH + vbase + m * 32);
            LDSM4T(bvl, sb + AS_VL + vbase + m * 32);
            MMA16816(pacc[2*m+0], Pf, bvh[0], bvh[1]);
            MMA16816(pacc[2*m+0], Pr, bvh[0], bvh[1]);
            MMA16816(pacc[2*m+0], Pf, bvl[0], bvl[1]);
            MMA16816(pacc[2*m+1], Pf, bvh[2], bvh[3]);
            MMA16816(pacc[2*m+1], Pr, bvh[2], bvh[3]);
            MMA16816(pacc[2*m+1], Pf, bvl[2], bvl[3]);
        }
    }

    // ---- epilogue: write Ch/Cl at (b, s, h*64 + d) ----
    const size_t rowA = ((size_t)(bb * SEQN) + qbase + ra) * DIM + h * DHD;
    const size_t rowB = ((size_t)(bb * SEQN) + qbase + rb) * DIM + h * DHD;
#pragma unroll
    for (int nt = 0; nt < 8; nt++) {
        const int d = nt * 8 + (lane & 3) * 2;
        float a0 = pacc[nt][0], a1 = pacc[nt][1];
        float b0 = pacc[nt][2], b1 = pacc[nt][3];
        __half ha0 = __float2half_rn(a0), ha1 = __float2half_rn(a1);
        __half hb0 = __float2half_rn(b0), hb1 = __float2half_rn(b1);
        *(__half2*)(Ch + rowA + d) = __halves2half2(ha0, ha1);
        *(__half2*)(Ch + rowB + d) = __halves2half2(hb0, hb1);
        *(__half2*)(Cl + rowA + d) = __halves2half2(
            __float2half_rn(a0 - __half2float(ha0)), __float2half_rn(a1 - __half2float(ha1)));
        *(__half2*)(Cl + rowB + d) = __halves2half2(
            __float2half_rn(b0 - __half2float(hb0)), __float2half_rn(b1 - __half2float(hb1)));
    }
}

// ===========================================================================
extern "C" void kernel_launch(void* const* d_in, const int* in_sizes, int n_in,
                              void* d_out, int out_size)
{
    (void)in_sizes; (void)n_in; (void)out_size;
    const float* query = (const float*)d_in[0];
    const float* Wq = (const float*)d_in[1];  const float* bq = (const float*)d_in[2];
    const float* Wk = (const float*)d_in[3];  const float* bk = (const float*)d_in[4];
    const float* Wv = (const float*)d_in[5];  const float* bv = (const float*)d_in[6];
    const float* Wo = (const float*)d_in[7];  const float* bo = (const float*)d_in[8];
    const float* gl = (const float*)d_in[9];  const float* bl = (const float*)d_in[10];
    const float* gs = (const float*)d_in[11]; const float* bs = (const float*)d_in[12];
    const float* Wd = (const float*)d_in[13]; const float* bd = (const float*)d_in[14];
    float* out = (float*)d_out;

    float *pTmp,*pTv,*pD,*pP,*pKcP,*pVcP;
    __half *pXh,*pXl,*pCh,*pCl,*pWth,*pWtl,*pQh,*pQl;
    __half *pKhF,*pKlF,*pVhF,*pVlF,*pPh,*pPl,*pKch,*pKcl,*pVch,*pVcl;
    cudaGetSymbolAddress((void**)&pTmp, g_tmp);
    cudaGetSymbolAddress((void**)&pTv, g_tv);
    cudaGetSymbolAddress((void**)&pD, g_D);
    cudaGetSymbolAddress((void**)&pP, g_P);
    cudaGetSymbolAddress((void**)&pKcP, g_KcP);
    cudaGetSymbolAddress((void**)&pVcP, g_VcP);
    cudaGetSymbolAddress((void**)&pXh, g_Xh);
    cudaGetSymbolAddress((void**)&pXl, g_Xl);
    cudaGetSymbolAddress((void**)&pCh, g_Ch);
    cudaGetSymbolAddress((void**)&pCl, g_Cl);
    cudaGetSymbolAddress((void**)&pWth, g_Wth);
    cudaGetSymbolAddress((void**)&pWtl, g_Wtl);
    cudaGetSymbolAddress((void**)&pQh, g_Qh);
    cudaGetSymbolAddress((void**)&pQl, g_Ql);
    cudaGetSymbolAddress((void**)&pKhF, g_KhF);
    cudaGetSymbolAddress((void**)&pKlF, g_KlF);
    cudaGetSymbolAddress((void**)&pVhF, g_VhF);
    cudaGetSymbolAddress((void**)&pVlF, g_VlF);
    cudaGetSymbolAddress((void**)&pPh, g_Ph);
    cudaGetSymbolAddress((void**)&pPl, g_Pl);
    cudaGetSymbolAddress((void**)&pKch, g_Kch);
    cudaGetSymbolAddress((void**)&pKcl, g_Kcl);
    cudaGetSymbolAddress((void**)&pVch, g_Vch);
    cudaGetSymbolAddress((void**)&pVcl, g_Vcl);

    cudaFuncSetAttribute(hgemm_qkvd, cudaFuncAttributeMaxDynamicSharedMemorySize, GEMM_SMEM2);
    cudaFuncSetAttribute(hgemm_o, cudaFuncAttributeMaxDynamicSharedMemorySize, GEMM_SMEM2);
    cudaFuncSetAttribute(compress_hmma, cudaFuncAttributeMaxDynamicSharedMemorySize, COMP_SMEM);
    cudaFuncSetAttribute(attn_hmma, cudaFuncAttributeMaxDynamicSharedMemorySize, ATTN_SMEM);

    split_perm_kernel<<<MROWS * DIM / 4 / 256, 256>>>(query, pXh, pXl);
    wsplit_all_kernel<<<dim3(DIM / 32, DIM / 32, 5), dim3(32, 8)>>>(
        Wq, Wk, Wv, Wd, Wo, pWth, pWtl);

    hgemm_qkvd<<<dim3((3 * DIM + NH * NL) / 128, MROWS / 128), 256, GEMM_SMEM2>>>(
        pXh, pXl, pWth, pWtl, bq, bk, bv, bd, pQh, pQl, pTmp, pTv, pD);

    ln_split2_kernel<<<dim3(MROWS, 2), 256>>>(pTmp, pTv, gl, bl, pKhF, pKlF, pVhF, pVlF);

    transpose_kernel<<<dim3((NH * NL) / 32, SEQN / 32, BATCH), dim3(32, 8)>>>(pD, pP);
    softmax_rows_kernel<<<BATCH * NH * NL, 256>>>(pP, pPh, pPl);

    compress_hmma<<<dim3(BATCH * NH, NSPLIT), 256, COMP_SMEM>>>(
        pPh, pPl, pKhF, pVhF, pKcP, pVcP);
    compress_ln_kernel<<<dim3(BATCH * NL, 2), 256>>>(
        pKcP, pVcP, gs, bs, pKch, pKcl, pVch, pVcl);

    attn_hmma<<<dim3(SEQN / 64, NH, BATCH), 128, ATTN_SMEM>>>(
        pQh, pQl, pKhF, pKlF, pVhF, pVlF, pKch, pKcl, pVch, pVcl, pCh, pCl);

    hgemm_o<<<dim3(DIM / 128, MROWS / 128), 256, GEMM_SMEM2>>>(
        pCh, pCl, pWth + WOFF_O, pWtl + WOFF_O, bo, out);
}

// round 11
// speedup vs baseline: 5.6148x; 1.3979x over previous
#include <cuda_runtime.h>
#include <cuda_fp16.h>
#include <math.h>
#include <stdint.h>

#define SEQN  4096
#define BATCH 4
#define DIM   1024
#define NH    16
#define DHD   64
#define NL    32
#define WW    8
#define EE    4
#define BAND  16
#define NG    (SEQN / WW)
#define MROWS (BATCH * SEQN)
#define NSPLIT 8
#define CSIZE (BATCH * NH * NL * DHD)

__device__ float g_tmp[BATCH * SEQN * DIM];
__device__ float g_tv [BATCH * SEQN * DIM];
__device__ float g_D  [BATCH * SEQN * NH * NL];
__device__ float g_P  [BATCH * NH * NL * SEQN];
__device__ float g_KcP[NSPLIT * CSIZE];
__device__ float g_VcP[NSPLIT * CSIZE];

__device__ __align__(16) __half g_Xh[MROWS * DIM];
__device__ __align__(16) __half g_Ch[MROWS * DIM];
__device__ __align__(16) __half g_Qh[BATCH * NH * SEQN * DHD];
__device__ __align__(16) __half g_Ql[BATCH * NH * SEQN * DHD];
__device__ __align__(16) __half g_KhF[BATCH * NH * SEQN * DHD];
__device__ __align__(16) __half g_KlF[BATCH * NH * SEQN * DHD];
__device__ __align__(16) __half g_VhF[BATCH * NH * SEQN * DHD];
__device__ __align__(16) __half g_VlF[BATCH * NH * SEQN * DHD];
__device__ __align__(16) __half g_Ph [BATCH * NH * NL * SEQN];
__device__ __align__(16) __half g_Pl [BATCH * NH * NL * SEQN];
__device__ __align__(16) __half g_Kch[CSIZE];
__device__ __align__(16) __half g_Kcl[CSIZE];
__device__ __align__(16) __half g_Vch[CSIZE];
__device__ __align__(16) __half g_Vcl[CSIZE];
// weight rows: Q 0-1023, K 1024-2047, V 2048-3071, D 3072-3583, O 3584-4607
#define WOFF_O (3 * DIM * DIM + (NH * NL) * DIM)
#define WT_TOTAL (4 * DIM * DIM + (NH * NL) * DIM)
__device__ __align__(16) __half g_Wth[WT_TOTAL];

// =========================== common asm helpers ============================
__device__ __forceinline__ uint32_t smem_u32(const void* p) {
    uint32_t a;
    asm("{ .reg .u64 t; cvta.to.shared.u64 t, %1; cvt.u32.u64 %0, t; }" : "=r"(a) : "l"(p));
    return a;
}
#define CPA(dst, src) \
    asm volatile("cp.async.cg.shared.global [%0], [%1], 16;" :: "r"(dst), "l"(src))
#define CP_COMMIT() asm volatile("cp.async.commit_group;")
#define CP_WAIT(n)  asm volatile("cp.async.wait_group %0;" :: "n"(n))
#define LDSM4(R, addr) \
    asm volatile("ldmatrix.sync.aligned.m8n8.x4.shared.b16 {%0,%1,%2,%3}, [%4];" \
        : "=r"((R)[0]), "=r"((R)[1]), "=r"((R)[2]), "=r"((R)[3]) : "r"(addr))
#define LDSM4T(R, addr) \
    asm volatile("ldmatrix.sync.aligned.m8n8.x4.trans.shared.b16 {%0,%1,%2,%3}, [%4];" \
        : "=r"((R)[0]), "=r"((R)[1]), "=r"((R)[2]), "=r"((R)[3]) : "r"(addr))
#define MMA16816(d, a, b0, b1) \
    asm volatile("mma.sync.aligned.m16n8k16.row.col.f32.f16.f16.f32 " \
        "{%0,%1,%2,%3}, {%4,%5,%6,%7}, {%8,%9}, {%0,%1,%2,%3};" \
        : "+f"((d)[0]), "+f"((d)[1]), "+f"((d)[2]), "+f"((d)[3]) \
        : "r"((a)[0]), "r"((a)[1]), "r"((a)[2]), "r"((a)[3]), "r"(b0), "r"(b1))

__device__ __forceinline__ uint32_t pack_h2(float lo, float hi) {
    __half2 h = __halves2half2(__float2half_rn(lo), __float2half_rn(hi));
    return *(uint32_t*)&h;
}

// =========================== HMMA GEMM core ================================
#define SROWB 80
#define TILEB (128 * SROWB)
#define NIT (DIM / 32)

// TERMS=1: Ah*Bh only. TERMS=2: (Ah+Al)*Bh. (3-term no longer used)
template <int TERMS>
__device__ __forceinline__ void hgemm_main(
    const __half* Ah, const __half* Al, const __half* Bh,
    int bm, int bn, uint32_t sb, int tid, float acc[2][8][4])
{
    constexpr uint32_t STG = (TERMS + 1) * TILEB;
    constexpr uint32_t oAH = 0;
    constexpr uint32_t oAL = TILEB;                            // only if TERMS>=2
    constexpr uint32_t oBH = (TERMS >= 2) ? 2 * TILEB : TILEB;

    const int lane = tid & 31, wid = tid >> 5;
    const int wm = wid & 3, wn = wid >> 2;
    const int lr0 = tid >> 2;
    const size_t aoff0 = ((size_t)(bm + lr0) << 10) + (size_t)(tid & 3) * 8;
    const size_t aoff1 = aoff0 + ((size_t)64 << 10);
    const size_t boff0 = ((size_t)(bn + lr0) << 10) + (size_t)(tid & 3) * 8;
    const size_t boff1 = boff0 + ((size_t)64 << 10);
    const uint32_t d0 = (uint32_t)lr0 * SROWB + (tid & 3) * 16;
    const uint32_t d1 = d0 + 64 * SROWB;

    CPA(sb + oAH + d0, Ah + aoff0); CPA(sb + oAH + d1, Ah + aoff1);
    if (TERMS >= 2) { CPA(sb + oAL + d0, Al + aoff0); CPA(sb + oAL + d1, Al + aoff1); }
    CPA(sb + oBH + d0, Bh + boff0); CPA(sb + oBH + d1, Bh + boff1);
    CP_COMMIT();

#pragma unroll
    for (int i = 0; i < 2; i++)
#pragma unroll
        for (int j = 0; j < 8; j++)
#pragma unroll
            for (int k = 0; k < 4; k++) acc[i][j][k] = 0.f;

    const uint32_t aBase = (uint32_t)(wm * 32 + (lane & 15)) * SROWB + (lane >> 4) * 16;
    const uint32_t bBase = (uint32_t)(wn * 64 + ((lane >> 4) & 1) * 8 + (lane & 7)) * SROWB
                           + ((lane >> 3) & 1) * 16;

    for (int it = 0; it < NIT; it++) {
        const uint32_t ps = (it & 1) * STG;
        if (it + 1 < NIT) {
            const uint32_t ns = ((it + 1) & 1) * STG;
            const int kb = (it + 1) * 32;
            CPA(sb + ns + oAH + d0, Ah + aoff0 + kb); CPA(sb + ns + oAH + d1, Ah + aoff1 + kb);
            if (TERMS >= 2) {
                CPA(sb + ns + oAL + d0, Al + aoff0 + kb); CPA(sb + ns + oAL + d1, Al + aoff1 + kb);
            }
            CPA(sb + ns + oBH + d0, Bh + boff0 + kb); CPA(sb + ns + oBH + d1, Bh + boff1 + kb);
            CP_COMMIT();
            CP_WAIT(1);
        } else {
            CP_WAIT(0);
        }
        __syncthreads();

        const uint32_t sAH = sb + ps + oAH + aBase;
        const uint32_t sAL = sb + ps + oAL + aBase;
        const uint32_t sBH = sb + ps + oBH + bBase;
#pragma unroll
        for (int ks = 0; ks < 2; ks++) {
            const uint32_t ko = ks * 32;
            uint32_t ah[2][4], al[2][4];
            LDSM4(ah[0], sAH + ko);
            LDSM4(ah[1], sAH + ko + 16 * SROWB);
            if (TERMS >= 2) {
                LDSM4(al[0], sAL + ko);
                LDSM4(al[1], sAL + ko + 16 * SROWB);
            }
#pragma unroll
            for (int q = 0; q < 4; q++) {
                uint32_t bh[4];
                LDSM4(bh, sBH + ko + q * 16 * SROWB);
#pragma unroll
                for (int mt = 0; mt < 2; mt++) {
                    MMA16816(acc[mt][2 * q + 0], ah[mt], bh[0], bh[1]);
                    MMA16816(acc[mt][2 * q + 1], ah[mt], bh[2], bh[3]);
                    if (TERMS >= 2) {
                        MMA16816(acc[mt][2 * q + 0], al[mt], bh[0], bh[1]);
                        MMA16816(acc[mt][2 * q + 1], al[mt], bh[2], bh[3]);
                    }
                }
            }
        }
        __syncthreads();
    }
}
#define GEMM_SMEM1 (2 * 2 * TILEB)

// ---- fused Q/K/V/D GEMM (1-term); Q emitted as fp16 hi/lo ----
__global__ __launch_bounds__(256, 2) void hgemm_qkvd(
    const __half* __restrict__ Ah, const __half* __restrict__ Bh,
    const float* __restrict__ bq, const float* __restrict__ bk,
    const float* __restrict__ bv, const float* __restrict__ bd,
    __half* __restrict__ outQh, __half* __restrict__ outQl,
    float* __restrict__ outK, float* __restrict__ outV, float* __restrict__ outD)
{
    extern __shared__ __align__(16) char smem[];
    const uint32_t sb = smem_u32(smem);
    const int tid = threadIdx.x, wid = tid >> 5, lane = tid & 31;
    const int bn = blockIdx.x * 128, bm = blockIdx.y * 128;
    float acc[2][8][4];
    hgemm_main<1>(Ah, nullptr, Bh, bm, bn, sb, tid, acc);

    const int seg = bn >> 10;
    const int cl = bn & 1023;
    const float* bias = seg == 0 ? bq : seg == 1 ? bk : seg == 2 ? bv : bd;
    const float scale = seg == 0 ? 0.125f : 1.f;
    const int wm = wid & 3, wn = wid >> 2;
    const int r0 = bm + wm * 32 + (lane >> 2);
    const int c0 = cl + wn * 64 + (lane & 3) * 2;
#pragma unroll
    for (int mt = 0; mt < 2; mt++) {
#pragma unroll
        for (int hf = 0; hf < 2; hf++) {
            const int r = r0 + mt * 16 + hf * 8;
            const int bb = r >> 12, ss = r & (SEQN - 1);
#pragma unroll
            for (int nt = 0; nt < 8; nt++) {
                const int col = c0 + nt * 8;
                const float2 bv2 = *(const float2*)(bias + col);
                float vx = (acc[mt][nt][hf * 2 + 0] + bv2.x) * scale;
                float vy = (acc[mt][nt][hf * 2 + 1] + bv2.y) * scale;
                if (seg == 0) {
                    size_t o = ((size_t)(bb * NH + (col >> 6)) * SEQN + ss) * DHD + (col & 63);
                    __half hx = __float2half_rn(vx), hy = __float2half_rn(vy);
                    *(__half2*)(outQh + o) = __halves2half2(hx, hy);
                    *(__half2*)(outQl + o) = __halves2half2(
                        __float2half_rn(vx - __half2float(hx)),
                        __float2half_rn(vy - __half2float(hy)));
                } else {
                    float* op; size_t o;
                    if (seg == 1)      { op = outK; o = (size_t)r * DIM + col; }
                    else if (seg == 2) { op = outV; o = (size_t)r * DIM + col; }
                    else               { op = outD; o = (size_t)r * (NH * NL) + col; }
                    *(float2*)(op + o) = make_float2(vx, vy);
                }
            }
        }
    }
}

// ---- output GEMM (1-term): out = C @ Wo + bo, (s,b,DIM) ----
__global__ __launch_bounds__(256, 2) void hgemm_o(
    const __half* __restrict__ Ah, const __half* __restrict__ Bh,
    const float* __restrict__ bias, float* __restrict__ out)
{
    extern __shared__ __align__(16) char smem[];
    const uint32_t sb = smem_u32(smem);
    const int tid = threadIdx.x, wid = tid >> 5, lane = tid & 31;
    const int bn = blockIdx.x * 128, bm = blockIdx.y * 128;
    float acc[2][8][4];
    hgemm_main<1>(Ah, nullptr, Bh, bm, bn, sb, tid, acc);

    const int wm = wid & 3, wn = wid >> 2;
    const int r0 = bm + wm * 32 + (lane >> 2);
    const int c0 = bn + wn * 64 + (lane & 3) * 2;
#pragma unroll
    for (int mt = 0; mt < 2; mt++) {
#pragma unroll
        for (int hf = 0; hf < 2; hf++) {
            const int r = r0 + mt * 16 + hf * 8;
            const int bb = r >> 12, ss = r & (SEQN - 1);
#pragma unroll
            for (int nt = 0; nt < 8; nt++) {
                const int col = c0 + nt * 8;
                const float2 bv2 = *(const float2*)(bias + col);
                *(float2*)(out + ((size_t)ss * BATCH + bb) * DIM + col) =
                    make_float2(acc[mt][nt][hf * 2 + 0] + bv2.x,
                                acc[mt][nt][hf * 2 + 1] + bv2.y);
            }
        }
    }
}

// ================= HMMA compress: Kc/Vc partials ===========================
#define CPROW 144
#define CPS_PH 0
#define CPS_PL (32 * CPROW)
#define CPS_K  (64 * CPROW)
#define CPS_V  (128 * CPROW)
#define CP_STG (192 * CPROW)
#define COMP_SMEM (2 * CP_STG)

__global__ __launch_bounds__(256, 2) void compress_hmma(
    const __half* __restrict__ Ph, const __half* __restrict__ Pl,
    const __half* __restrict__ Kh, const __half* __restrict__ Vh,
    float* __restrict__ partK, float* __restrict__ partV)
{
    extern __shared__ __align__(16) char smem[];
    const uint32_t sb = smem_u32(smem);
    const int bh = blockIdx.x, sp = blockIdx.y;
    const int b = bh >> 4, h = bh & 15;
    const int tid = threadIdx.x, lane = tid & 31, wid = tid >> 5;

    const size_t pbase = ((size_t)(b * (NH * NL) + h * NL)) * SEQN + sp * 512;
    const size_t kbase = ((size_t)bh * SEQN + sp * 512) * DHD;

    const int prow = tid >> 3, pseg = tid & 7;
    const uint32_t pDst = prow * CPROW + pseg * 16;
    const size_t pSrc = (size_t)prow * SEQN + pseg * 8;
    const uint32_t kDst0 = prow * CPROW + pseg * 16;
    const uint32_t kDst1 = (prow + 32) * CPROW + pseg * 16;
    const size_t kSrc0 = (size_t)prow * DHD + pseg * 8;
    const size_t kSrc1 = (size_t)(prow + 32) * DHD + pseg * 8;

    CPA(sb + CPS_PH + pDst, Ph + pbase + pSrc);
    CPA(sb + CPS_PL + pDst, Pl + pbase + pSrc);
    CPA(sb + CPS_K + kDst0, Kh + kbase + kSrc0);
    CPA(sb + CPS_K + kDst1, Kh + kbase + kSrc1);
    CPA(sb + CPS_V + kDst0, Vh + kbase + kSrc0);
    CPA(sb + CPS_V + kDst1, Vh + kbase + kSrc1);
    CP_COMMIT();

    float acc[4][4];
#pragma unroll
    for (int i = 0; i < 4; i++)
#pragma unroll
        for (int j = 0; j < 4; j++) acc[i][j] = 0.f;

    const int outv = wid >> 2;
    const int mt = wid & 1, nh2 = (wid >> 1) & 1;
    const uint32_t aOff = (uint32_t)(mt * 16 + (lane & 15)) * CPROW + (lane >> 4) * 16;
    const uint32_t bRow = (lane & 7) + ((lane >> 3) & 1) * 8;
    const uint32_t bCol = ((lane >> 4) & 1) * 16 + nh2 * 64;
    const uint32_t kvOff = outv ? CPS_V : CPS_K;

    for (int c = 0; c < 8; c++) {
        const uint32_t ps = (c & 1) * CP_STG;
        if (c + 1 < 8) {
            const uint32_t ns = ((c + 1) & 1) * CP_STG;
            const int so = (c + 1) * 64;
            CPA(sb + ns + CPS_PH + pDst, Ph + pbase + so + pSrc);
            CPA(sb + ns + CPS_PL + pDst, Pl + pbase + so + pSrc);
            CPA(sb + ns + CPS_K + kDst0, Kh + kbase + (size_t)so * DHD + kSrc0);
            CPA(sb + ns + CPS_K + kDst1, Kh + kbase + (size_t)so * DHD + kSrc1);
            CPA(sb + ns + CPS_V + kDst0, Vh + kbase + (size_t)so * DHD + kSrc0);
            CPA(sb + ns + CPS_V + kDst1, Vh + kbase + (size_t)so * DHD + kSrc1);
            CP_COMMIT();
            CP_WAIT(1);
        } else {
            CP_WAIT(0);
        }
        __syncthreads();

        const uint32_t sP0 = sb + ps + CPS_PH + aOff;
        const uint32_t sP1 = sb + ps + CPS_PL + aOff;
        const uint32_t sKV = sb + ps + kvOff;
#pragma unroll
        for (int ks = 0; ks < 4; ks++) {
            uint32_t ah[4], al[4], b0[4], b1[4];
            LDSM4(ah, sP0 + ks * 32);
            LDSM4(al, sP1 + ks * 32);
            const uint32_t ba = sKV + (ks * 16 + bRow) * CPROW + bCol;
            LDSM4T(b0, ba);
            LDSM4T(b1, ba + 32);
            MMA16816(acc[0], ah, b0[0], b0[1]);
            MMA16816(acc[0], al, b0[0], b0[1]);
            MMA16816(acc[1], ah, b0[2], b0[3]);
            MMA16816(acc[1], al, b0[2], b0[3]);
            MMA16816(acc[2], ah, b1[0], b1[1]);
            MMA16816(acc[2], al, b1[0], b1[1]);
            MMA16816(acc[3], ah, b1[2], b1[3]);
            MMA16816(acc[3], al, b1[2], b1[3]);
        }
        __syncthreads();
    }

    float* outp = outv ? partV : partK;
    const size_t ob = (size_t)sp * CSIZE + (size_t)bh * NL * DHD;
    const int l0 = mt * 16 + (lane >> 2);
    const int db = nh2 * 32 + (lane & 3) * 2;
#pragma unroll
    for (int nt = 0; nt < 4; nt++) {
        const int d = db + nt * 8;
        *(float2*)(outp + ob + (size_t)l0 * DHD + d) = make_float2(acc[nt][0], acc[nt][1]);
        *(float2*)(outp + ob + (size_t)(l0 + 8) * DHD + d) = make_float2(acc[nt][2], acc[nt][3]);
    }
}

// ---- fp32 -> fp16 with (s,b)->(b,s) permute (hi only) ----
__global__ __launch_bounds__(256) void split_perm_kernel(
    const float* __restrict__ X, __half* __restrict__ H)
{
    int i = blockIdx.x * 256 + threadIdx.x;
    int r = i >> 8, k4 = i & 255;
    int b = r >> 12, s = r & (SEQN - 1);
    float4 v = *((const float4*)X + ((size_t)s * BATCH + b) * 256 + k4);
    __half2* Hp = (__half2*)(H + (size_t)i * 4);
    Hp[0] = __halves2half2(__float2half_rn(v.x), __float2half_rn(v.y));
    Hp[1] = __halves2half2(__float2half_rn(v.z), __float2half_rn(v.w));
}

// ---- all 5 weight transposes (fp16 hi only) in one launch ----
__global__ void wsplit_all_kernel(
    const float* __restrict__ Wq, const float* __restrict__ Wk,
    const float* __restrict__ Wv, const float* __restrict__ Wd,
    const float* __restrict__ Wo, __half* __restrict__ Th)
{
    __shared__ float t[32][33];
    int z = blockIdx.z;
    int N = (z == 3) ? (NH * NL) : DIM;
    if (blockIdx.x * 32 >= N) return;
    const float* W = z == 0 ? Wq : z == 1 ? Wk : z == 2 ? Wv : z == 3 ? Wd : Wo;
    size_t woff = z <= 3 ? (size_t)z * DIM * DIM : (size_t)WOFF_O;
    int n0 = blockIdx.x * 32, k0 = blockIdx.y * 32;
    int x = threadIdx.x, y = threadIdx.y;
#pragma unroll
    for (int i = 0; i < 32; i += 8)
        t[y + i][x] = W[(size_t)(k0 + y + i) * N + n0 + x];
    __syncthreads();
#pragma unroll
    for (int i = 0; i < 32; i += 8)
        Th[woff + (size_t)(n0 + y + i) * DIM + k0 + x] = __float2half_rn(t[x][y + i]);
}

// ---- LayerNorm over DIM, head-split; fp16 hi/lo outputs ----
__global__ __launch_bounds__(256) void ln_split2_kernel(
    const float* __restrict__ XK, const float* __restrict__ XV,
    const float* __restrict__ gamma, const float* __restrict__ beta,
    __half* __restrict__ oKh, __half* __restrict__ oKl,
    __half* __restrict__ oVh, __half* __restrict__ oVl)
{
    __shared__ float shs[8], shq[8];
    int r = blockIdx.x, tid = threadIdx.x;
    const float* X = blockIdx.y ? XV : XK;
    __half* outh = blockIdx.y ? oVh : oKh;
    __half* outl = blockIdx.y ? oVl : oKl;
    const float4 v = ((const float4*)(X + (size_t)r * DIM))[tid];
    float s = v.x + v.y + v.z + v.w;
    float q = v.x*v.x + v.y*v.y + v.z*v.z + v.w*v.w;
    int lane = tid & 31, wid = tid >> 5;
#pragma unroll
    for (int o = 16; o; o >>= 1) {
        s += __shfl_xor_sync(~0u, s, o); q += __shfl_xor_sync(~0u, q, o);
    }
    if (lane == 0) { shs[wid] = s; shq[wid] = q; }
    __syncthreads();
    if (tid == 0) {
        float ts = 0, tq = 0;
        for (int i = 0; i < 8; i++) { ts += shs[i]; tq += shq[i]; }
        shs[0] = ts; shq[0] = tq;
    }
    __syncthreads();
    float mean = shs[0] * (1.f / DIM);
    float rstd = rsqrtf(shq[0] * (1.f / DIM) - mean * mean + 1e-5f);
    int c = tid * 4;
    float4 g4 = ((const float4*)gamma)[tid], b4 = ((const float4*)beta)[tid];
    float o0 = (v.x - mean) * rstd * g4.x + b4.x;
    float o1 = (v.y - mean) * rstd * g4.y + b4.y;
    float o2 = (v.z - mean) * rstd * g4.z + b4.z;
    float o3 = (v.w - mean) * rstd * g4.w + b4.w;
    int b = r >> 12, sq = r & (SEQN - 1);
    size_t base = ((size_t)(b * NH + (c >> 6)) * SEQN + sq) * DHD + (c & 63);
    __half h0 = __float2half_rn(o0), h1 = __float2half_rn(o1);
    __half h2 = __float2half_rn(o2), h3 = __float2half_rn(o3);
    __half2* hp = (__half2*)(outh + base);
    hp[0] = __halves2half2(h0, h1); hp[1] = __halves2half2(h2, h3);
    __half2* lp = (__half2*)(outl + base);
    lp[0] = __halves2half2(__float2half_rn(o0 - __half2float(h0)),
                           __float2half_rn(o1 - __half2float(h1)));
    lp[1] = __halves2half2(__float2half_rn(o2 - __half2float(h2)),
                           __float2half_rn(o3 - __half2float(h3)));
}

// ---- transpose (b,s,512) -> (b,512,s) ----
__global__ void transpose_kernel(const float* __restrict__ D, float* __restrict__ P)
{
    __shared__ float t[32][33];
    int b = blockIdx.z, c0 = blockIdx.x * 32, s0 = blockIdx.y * 32;
    int x = threadIdx.x, y = threadIdx.y;
    const float* Db = D + (size_t)b * SEQN * (NH * NL);
    float* Pb = P + (size_t)b * (NH * NL) * SEQN;
#pragma unroll
    for (int i = 0; i < 32; i += 8)
        t[y + i][x] = Db[(size_t)(s0 + y + i) * (NH * NL) + c0 + x];
    __syncthreads();
#pragma unroll
    for (int i = 0; i < 32; i += 8)
        Pb[(size_t)(c0 + y + i) * SEQN + s0 + x] = t[x][y + i];
}

// ---- row softmax over 4096; emits fp16 hi/lo probs ----
__global__ __launch_bounds__(256) void softmax_rows_kernel(
    const float* __restrict__ P, __half* __restrict__ Ph, __half* __restrict__ Pl)
{
    __shared__ float sh[8];
    size_t base = (size_t)blockIdx.x * SEQN;
    int tid = threadIdx.x, lane = tid & 31, wid = tid >> 5;
    float v[16], m = -1e30f;
#pragma unroll
    for (int i = 0; i < 16; i++) { v[i] = P[base + tid + i * 256]; m = fmaxf(m, v[i]); }
#pragma unroll
    for (int o = 16; o; o >>= 1) m = fmaxf(m, __shfl_xor_sync(~0u, m, o));
    if (lane == 0) sh[wid] = m;
    __syncthreads();
    if (tid == 0) { float t = sh[0]; for (int i = 1; i < 8; i++) t = fmaxf(t, sh[i]); sh[0] = t; }
    __syncthreads();
    float M = sh[0];
    __syncthreads();
    float s = 0.f;
#pragma unroll
    for (int i = 0; i < 16; i++) { v[i] = __expf(v[i] - M); s += v[i]; }
#pragma unroll
    for (int o = 16; o; o >>= 1) s += __shfl_xor_sync(~0u, s, o);
    if (lane == 0) sh[wid] = s;
    __syncthreads();
    if (tid == 0) { float t = 0; for (int i = 0; i < 8; i++) t += sh[i]; sh[0] = t; }
    __syncthreads();
    float inv = 1.f / sh[0];
#pragma unroll
    for (int i = 0; i < 16; i++) {
        float p = v[i] * inv;
        __half h = __float2half_rn(p);
        Ph[base + tid + i * 256] = h;
        Pl[base + tid + i * 256] = __float2half_rn(p - __half2float(h));
    }
}

// ---- reduce partials + LN for Kc/Vc; fp16 hi/lo outputs ----
__global__ __launch_bounds__(256) void compress_ln_kernel(
    const float* __restrict__ partK, const float* __restrict__ partV,
    const float* __restrict__ gamma, const float* __restrict__ beta,
    __half* __restrict__ oKh, __half* __restrict__ oKl,
    __half* __restrict__ oVh, __half* __restrict__ oVl)
{
    __shared__ float shs[8], shq[8];
    int bl = blockIdx.x, b = bl >> 5, l = bl & 31;
    const float* part = blockIdx.y ? partV : partK;
    __half* outh = blockIdx.y ? oVh : oKh;
    __half* outl = blockIdx.y ? oVl : oKl;
    int tid = threadIdx.x, c = tid * 4;
    size_t base = ((size_t)(b * NH + (c >> 6)) * NL + l) * DHD + (c & 63);
    float4 acc = make_float4(0, 0, 0, 0);
#pragma unroll
    for (int sp = 0; sp < NSPLIT; sp++) {
        float4 p = *(const float4*)(part + (size_t)sp * CSIZE + base);
        acc.x += p.x; acc.y += p.y; acc.z += p.z; acc.w += p.w;
    }
    float s = acc.x + acc.y + acc.z + acc.w;
    float q = acc.x*acc.x + acc.y*acc.y + acc.z*acc.z + acc.w*acc.w;
    int lane = tid & 31, wid = tid >> 5;
#pragma unroll
    for (int o = 16; o; o >>= 1) {
        s += __shfl_xor_sync(~0u, s, o); q += __shfl_xor_sync(~0u, q, o);
    }
    if (lane == 0) { shs[wid] = s; shq[wid] = q; }
    __syncthreads();
    if (tid == 0) {
        float ts = 0, tq = 0;
        for (int i = 0; i < 8; i++) { ts += shs[i]; tq += shq[i]; }
        shs[0] = ts; shq[0] = tq;
    }
    __syncthreads();
    float mean = shs[0] * (1.f / DIM);
    float rstd = rsqrtf(shq[0] * (1.f / DIM) - mean * mean + 1e-5f);
    float4 g4 = ((const float4*)gamma)[tid], b4 = ((const float4*)beta)[tid];
    float o0 = (acc.x - mean) * rstd * g4.x + b4.x;
    float o1 = (acc.y - mean) * rstd * g4.y + b4.y;
    float o2 = (acc.z - mean) * rstd * g4.z + b4.z;
    float o3 = (acc.w - mean) * rstd * g4.w + b4.w;
    __half h0 = __float2half_rn(o0), h1 = __float2half_rn(o1);
    __half h2 = __float2half_rn(o2), h3 = __float2half_rn(o3);
    __half2* hp = (__half2*)(outh + base);
    hp[0] = __halves2half2(h0, h1); hp[1] = __halves2half2(h2, h3);
    __half2* lp = (__half2*)(outl + base);
    lp[0] = __halves2half2(__float2half_rn(o0 - __half2float(h0)),
                           __float2half_rn(o1 - __half2float(h1)));
    lp[1] = __halves2half2(__float2half_rn(o2 - __half2float(h2)),
                           __float2half_rn(o3 - __half2float(h3)));
}

// ================= HMMA attention ==========================================
#define AROWB 144
#define AS_QH 0
#define AS_QL (64 * AROWB)
#define AS_KH (128 * AROWB)
#define AS_KL (240 * AROWB)
#define AS_VH (352 * AROWB)
#define AS_VL (464 * AROWB)
#define ATTN_SMEM (576 * AROWB)

__global__ __launch_bounds__(128) void attn_hmma(
    const __half* __restrict__ Qh, const __half* __restrict__ Ql,
    const __half* __restrict__ Kh, const __half* __restrict__ Kl,
    const __half* __restrict__ Vh, const __half* __restrict__ Vl,
    const __half* __restrict__ Kch, const __half* __restrict__ Kcl,
    const __half* __restrict__ Vch, const __half* __restrict__ Vcl,
    __half* __restrict__ Ch)
{
    extern __shared__ __align__(16) char smem[];
    const uint32_t sb = smem_u32(smem);
    const int h = blockIdx.y, bb = blockIdx.z;
    const int bh = bb * NH + h;
    const int qbase = blockIdx.x * 64;
    const int tid = threadIdx.x, lane = tid & 31, warp = tid >> 5;

    for (int idx = tid; idx < 112 * 8; idx += 128) {
        const int row = idx >> 3, seg = idx & 7;
        const uint32_t dst = row * AROWB + seg * 16;
        uint4 kh4 = {0,0,0,0}, kl4 = {0,0,0,0}, vh4 = {0,0,0,0}, vl4 = {0,0,0,0};
        if (row < 32) {
            size_t src = ((size_t)bh * NL + row) * DHD + seg * 8;
            kh4 = *(const uint4*)(Kch + src); kl4 = *(const uint4*)(Kcl + src);
            vh4 = *(const uint4*)(Vch + src); vl4 = *(const uint4*)(Vcl + src);
        } else {
            const int seq = qbase - EE + (row - 32);
            if (seq >= 0 && seq < SEQN) {
                size_t src = ((size_t)bh * SEQN + seq) * DHD + seg * 8;
                kh4 = *(const uint4*)(Kh + src); kl4 = *(const uint4*)(Kl + src);
                vh4 = *(const uint4*)(Vh + src); vl4 = *(const uint4*)(Vl + src);
            }
        }
        *(uint4*)(smem + AS_KH + dst) = kh4;
        *(uint4*)(smem + AS_KL + dst) = kl4;
        *(uint4*)(smem + AS_VH + dst) = vh4;
        *(uint4*)(smem + AS_VL + dst) = vl4;
    }
    for (int idx = tid; idx < 64 * 8; idx += 128) {
        const int row = idx >> 3, seg = idx & 7;
        const uint32_t dst = row * AROWB + seg * 16;
        size_t src = ((size_t)bh * SEQN + qbase + row) * DHD + seg * 8;
        *(uint4*)(smem + AS_QH + dst) = *(const uint4*)(Qh + src);
        *(uint4*)(smem + AS_QL + dst) = *(const uint4*)(Ql + src);
    }
    __syncthreads();

    const int r0 = warp * 16;
    float sacc[14][4];
#pragma unroll
    for (int j = 0; j < 14; j++)
#pragma unroll
        for (int e = 0; e < 4; e++) sacc[j][e] = 0.f;

    const uint32_t aOff = (uint32_t)(r0 + (lane & 15)) * AROWB + (lane >> 4) * 16;
    const uint32_t bOffS = (uint32_t)(((lane >> 4) & 1) * 8 + (lane & 7)) * AROWB
                           + ((lane >> 3) & 1) * 16;
#pragma unroll
    for (int ks = 0; ks < 4; ks++) {
        uint32_t ah[4], al[4];
        LDSM4(ah, sb + AS_QH + aOff + ks * 32);
        LDSM4(al, sb + AS_QL + aOff + ks * 32);
#pragma unroll
        for (int i = 0; i < 7; i++) {
            const uint32_t bo = bOffS + (uint32_t)(i * 16) * AROWB + ks * 32;
            uint32_t bh4[4], bl4[4];
            LDSM4(bh4, sb + AS_KH + bo);
            LDSM4(bl4, sb + AS_KL + bo);
            MMA16816(sacc[2*i+0], ah, bh4[0], bh4[1]);
            MMA16816(sacc[2*i+0], al, bh4[0], bh4[1]);
            MMA16816(sacc[2*i+0], ah, bl4[0], bl4[1]);
            MMA16816(sacc[2*i+1], ah, bh4[2], bh4[3]);
            MMA16816(sacc[2*i+1], al, bh4[2], bh4[3]);
            MMA16816(sacc[2*i+1], ah, bl4[2], bl4[3]);
        }
    }

    const int ra = r0 + (lane >> 2), rb = ra + 8;
    const int ga = ra >> 3, gb = rb >> 3;
    float mxa = -1e30f, mxb = -1e30f;
    bool vld[14][4];
#pragma unroll
    for (int j = 0; j < 14; j++) {
#pragma unroll
        for (int e = 0; e < 2; e++) {
            const int col = j * 8 + (lane & 3) * 2 + e;
            bool va, vb;
            if (col < 32) { va = true; vb = true; }
            else {
                const int w = col - 32;
                const int seq = qbase - EE + w;
                const bool sv = (seq >= 0) && (seq < SEQN);
                va = sv && (w >= ga * 8) && (w < ga * 8 + BAND);
                vb = sv && (w >= gb * 8) && (w < gb * 8 + BAND);
            }
            vld[j][e] = va; vld[j][2 + e] = vb;
            if (va) mxa = fmaxf(mxa, sacc[j][e]);
            if (vb) mxb = fmaxf(mxb, sacc[j][2 + e]);
        }
    }
#pragma unroll
    for (int o = 1; o <= 2; o <<= 1) {
        mxa = fmaxf(mxa, __shfl_xor_sync(~0u, mxa, o));
        mxb = fmaxf(mxb, __shfl_xor_sync(~0u, mxb, o));
    }
    float sma = 0.f, smb = 0.f;
#pragma unroll
    for (int j = 0; j < 14; j++) {
#pragma unroll
        for (int e = 0; e < 2; e++) {
            float pa = vld[j][e]     ? __expf(sacc[j][e]     - mxa) : 0.f;
            float pb = vld[j][2 + e] ? __expf(sacc[j][2 + e] - mxb) : 0.f;
            sacc[j][e] = pa; sacc[j][2 + e] = pb;
            sma += pa; smb += pb;
        }
    }
#pragma unroll
    for (int o = 1; o <= 2; o <<= 1) {
        sma += __shfl_xor_sync(~0u, sma, o);
        smb += __shfl_xor_sync(~0u, smb, o);
    }
    const float iva = 1.f / sma, ivb = 1.f / smb;
#pragma unroll
    for (int j = 0; j < 14; j++) {
        sacc[j][0] *= iva; sacc[j][1] *= iva;
        sacc[j][2] *= ivb; sacc[j][3] *= ivb;
    }

    float pacc[8][4];
#pragma unroll
    for (int i = 0; i < 8; i++)
#pragma unroll
        for (int e = 0; e < 4; e++) pacc[i][e] = 0.f;

    const uint32_t bRowV = (uint32_t)((lane & 7) + ((lane >> 3) & 1) * 8);
    const uint32_t bColV = ((lane >> 4) & 1) * 16;
#pragma unroll
    for (int ks = 0; ks < 7; ks++) {
        const int j0 = 2 * ks, j1 = 2 * ks + 1;
        uint32_t Pf[4], Pr[4];
        {
            float a0 = sacc[j0][0], a1 = sacc[j0][1];
            float b0 = sacc[j0][2], b1 = sacc[j0][3];
            float c0 = sacc[j1][0], c1 = sacc[j1][1];
            float d0 = sacc[j1][2], d1 = sacc[j1][3];
            Pf[0] = pack_h2(a0, a1); Pf[1] = pack_h2(b0, b1);
            Pf[2] = pack_h2(c0, c1); Pf[3] = pack_h2(d0, d1);
            Pr[0] = pack_h2(a0 - __half2float(__float2half_rn(a0)),
                            a1 - __half2float(__float2half_rn(a1)));
            Pr[1] = pack_h2(b0 - __half2float(__float2half_rn(b0)),
                            b1 - __half2float(__float2half_rn(b1)));
            Pr[2] = pack_h2(c0 - __half2float(__float2half_rn(c0)),
                            c1 - __half2float(__float2half_rn(c1)));
            Pr[3] = pack_h2(d0 - __half2float(__float2half_rn(d0)),
                            d1 - __half2float(__float2half_rn(d1)));
        }
        const uint32_t vbase = (uint32_t)(ks * 16 + bRowV) * AROWB + bColV;
#pragma unroll
        for (int m = 0; m < 4; m++) {
            uint32_t bvh[4], bvl[4];
            LDSM4T(bvh, sb + AS_VH + vbase + m * 32);
            LDSM4T(bvl, sb + AS_VL + vbase + m * 32);
            MMA16816(pacc[2*m+0], Pf, bvh[0], bvh[1]);
            MMA16816(pacc[2*m+0], Pr, bvh[0], bvh[1]);
            MMA16816(pacc[2*m+0], Pf, bvl[0], bvl[1]);
            MMA16816(pacc[2*m+1], Pf, bvh[2], bvh[3]);
            MMA16816(pacc[2*m+1], Pr, bvh[2], bvh[3]);
            MMA16816(pacc[2*m+1], Pf, bvl[2], bvl[3]);
        }
    }

    const size_t rowA = ((size_t)(bb * SEQN) + qbase + ra) * DIM + h * DHD;
    const size_t rowB = ((size_t)(bb * SEQN) + qbase + rb) * DIM + h * DHD;
#pragma unroll
    for (int nt = 0; nt < 8; nt++) {
        const int d = nt * 8 + (lane & 3) * 2;
        *(__half2*)(Ch + rowA + d) = __halves2half2(
            __float2half_rn(pacc[nt][0]), __float2half_rn(pacc[nt][1]));
        *(__half2*)(Ch + rowB + d) = __halves2half2(
            __float2half_rn(pacc[nt][2]), __float2half_rn(pacc[nt][3]));
    }
}

// ===========================================================================
extern "C" void kernel_launch(void* const* d_in, const int* in_sizes, int n_in,
                              void* d_out, int out_size)
{
    (void)in_sizes; (void)n_in; (void)out_size;
    const float* query = (const float*)d_in[0];
    const float* Wq = (const float*)d_in[1];  const float* bq = (const float*)d_in[2];
    const float* Wk = (const float*)d_in[3];  const float* bk = (const float*)d_in[4];
    const float* Wv = (const float*)d_in[5];  const float* bv = (const float*)d_in[6];
    const float* Wo = (const float*)d_in[7];  const float* bo = (const float*)d_in[8];
    const float* gl = (const float*)d_in[9];  const float* bl = (const float*)d_in[10];
    const float* gs = (const float*)d_in[11]; const float* bs = (const float*)d_in[12];
    const float* Wd = (const float*)d_in[13]; const float* bd = (const float*)d_in[14];
    float* out = (float*)d_out;

    float *pTmp,*pTv,*pD,*pP,*pKcP,*pVcP;
    __half *pXh,*pCh,*pWth,*pQh,*pQl;
    __half *pKhF,*pKlF,*pVhF,*pVlF,*pPh,*pPl,*pKch,*pKcl,*pVch,*pVcl;
    cudaGetSymbolAddress((void**)&pTmp, g_tmp);
    cudaGetSymbolAddress((void**)&pTv, g_tv);
    cudaGetSymbolAddress((void**)&pD, g_D);
    cudaGetSymbolAddress((void**)&pP, g_P);
    cudaGetSymbolAddress((void**)&pKcP, g_KcP);
    cudaGetSymbolAddress((void**)&pVcP, g_VcP);
    cudaGetSymbolAddress((void**)&pXh, g_Xh);
    cudaGetSymbolAddress((void**)&pCh, g_Ch);
    cudaGetSymbolAddress((void**)&pWth, g_Wth);
    cudaGetSymbolAddress((void**)&pQh, g_Qh);
    cudaGetSymbolAddress((void**)&pQl, g_Ql);
    cudaGetSymbolAddress((void**)&pKhF, g_KhF);
    cudaGetSymbolAddress((void**)&pKlF, g_KlF);
    cudaGetSymbolAddress((void**)&pVhF, g_VhF);
    cudaGetSymbolAddress((void**)&pVlF, g_VlF);
    cudaGetSymbolAddress((void**)&pPh, g_Ph);
    cudaGetSymbolAddress((void**)&pPl, g_Pl);
    cudaGetSymbolAddress((void**)&pKch, g_Kch);
    cudaGetSymbolAddress((void**)&pKcl, g_Kcl);
    cudaGetSymbolAddress((void**)&pVch, g_Vch);
    cudaGetSymbolAddress((void**)&pVcl, g_Vcl);

    cudaFuncSetAttribute(hgemm_qkvd, cudaFuncAttributeMaxDynamicSharedMemorySize, GEMM_SMEM1);
    cudaFuncSetAttribute(hgemm_o, cudaFuncAttributeMaxDynamicSharedMemorySize, GEMM_SMEM1);
    cudaFuncSetAttribute(compress_hmma, cudaFuncAttributeMaxDynamicSharedMemorySize, COMP_SMEM);
    cudaFuncSetAttribute(attn_hmma, cudaFuncAttributeMaxDynamicSharedMemorySize, ATTN_SMEM);

    split_perm_kernel<<<MROWS * DIM / 4 / 256, 256>>>(query, pXh);
    wsplit_all_kernel<<<dim3(DIM / 32, DIM / 32, 5), dim3(32, 8)>>>(
        Wq, Wk, Wv, Wd, Wo, pWth);

    hgemm_qkvd<<<dim3((3 * DIM + NH * NL) / 128, MROWS / 128), 256, GEMM_SMEM1>>>(
        pXh, pWth, bq, bk, bv, bd, pQh, pQl, pTmp, pTv, pD);

    ln_split2_kernel<<<dim3(MROWS, 2), 256>>>(pTmp, pTv, gl, bl, pKhF, pKlF, pVhF, pVlF);

    transpose_kernel<<<dim3((NH * NL) / 32, SEQN / 32, BATCH), dim3(32, 8)>>>(pD, pP);
    softmax_rows_kernel<<<BATCH * NH * NL, 256>>>(pP, pPh, pPl);

    compress_hmma<<<dim3(BATCH * NH, NSPLIT), 256, COMP_SMEM>>>(
        pPh, pPl, pKhF, pVhF, pKcP, pVcP);
    compress_ln_kernel<<<dim3(BATCH * NL, 2), 256>>>(
        pKcP, pVcP, gs, bs, pKch, pKcl, pVch, pVcl);

    attn_hmma<<<dim3(SEQN / 64, NH, BATCH), 128, ATTN_SMEM>>>(
        pQh, pQl, pKhF, pKlF, pVhF, pVlF, pKch, pKcl, pVch, pVcl, pCh);

    hgemm_o<<<dim3(DIM / 128, MROWS / 128), 256, GEMM_SMEM1>>>(
        pCh, pWth + WOFF_O, bo, out);
}